// round 4
// baseline (speedup 1.0000x reference)
#include <cuda_runtime.h>
#include <stdint.h>

// ---------------- problem constants ----------------
constexpr int N  = 50000;
constexpr int E  = 800000;
constexpr int NG = 128;
constexpr int D  = 128;
constexpr int M  = 2;
constexpr int NT = 10;

typedef unsigned long long ull;

// ---------------- device scratch ----------------
__device__ float g_tx[N * D];
__device__ float g_z1[N * D];
__device__ float g_h1[N * D];
__device__ float g_z2[N * D];
__device__ float g_h2[N * D];
__device__ float g_hn[N * D];
__device__ float g_dz[M * N * D];
__device__ float g_dh1[M * N * D];
__device__ float g_dh2[M * N * D];
__device__ float g_dhn[M * N * D];
__device__ int   g_deg[N];
__device__ int   g_rowoff[N + 1];
__device__ int   g_cursor[N];
__device__ int   g_csrsrc[E];
__device__ int   g_gstart[NG + 1];
__device__ float g_pred[N];
__device__ float g_gmax[NG];
__device__ float g_gsum[NG];
__device__ int   g_anchor[M * NG];
__device__ float g_hg[M * NG * D];
__device__ unsigned char g_fA[M * N];
__device__ unsigned char g_f1[M * N];
__device__ unsigned char g_f2[M * N];
__device__ int   g_list1[M * N];
__device__ int   g_list2[M * N];
__device__ int   g_hitE[M * E];
__device__ int   g_cnt[8];  // [m]=cnt1, [2+m]=hit1, [4+m]=cnt2, [6+m]=hit2

// ---------------- f32x2 helpers ----------------
__device__ __forceinline__ ull ffma2(ull a, ull b, ull c) {
  ull d;
  asm("fma.rn.f32x2 %0, %1, %2, %3;" : "=l"(d) : "l"(a), "l"(b), "l"(c));
  return d;
}
__device__ __forceinline__ ull pack2dup(float x) {
  ull r;
  asm("mov.b64 %0, {%1, %1};" : "=l"(r) : "f"(x));
  return r;
}
__device__ __forceinline__ void unpack2(ull v, float& lo, float& hi) {
  asm("mov.b64 {%0, %1}, %2;" : "=f"(lo), "=f"(hi) : "l"(v));
}

// ---------------- threefry2x32 (exact JAX) ----------------
__device__ __forceinline__ uint2 threefry2x32(unsigned k0, unsigned k1,
                                              unsigned x0, unsigned x1) {
  unsigned k2 = k0 ^ k1 ^ 0x1BD11BDAu;
  x0 += k0; x1 += k1;
#define TF_ROT(x, d) (((x) << (d)) | ((x) >> (32 - (d))))
#define TF_RND(r) { x0 += x1; x1 = TF_ROT(x1, r); x1 ^= x0; }
  TF_RND(13) TF_RND(15) TF_RND(26) TF_RND(6)
  x0 += k1; x1 += k2 + 1u;
  TF_RND(17) TF_RND(29) TF_RND(16) TF_RND(24)
  x0 += k2; x1 += k0 + 2u;
  TF_RND(13) TF_RND(15) TF_RND(26) TF_RND(6)
  x0 += k0; x1 += k1 + 3u;
  TF_RND(17) TF_RND(29) TF_RND(16) TF_RND(24)
  x0 += k1; x1 += k2 + 4u;
  TF_RND(13) TF_RND(15) TF_RND(26) TF_RND(6)
  x0 += k2; x1 += k0 + 5u;
#undef TF_RND
#undef TF_ROT
  return make_uint2(x0, x1);
}

// ---------------- base kernels ----------------
__global__ void k_embed(const int* __restrict__ x_idx,
                        const int* __restrict__ batch,
                        const float* __restrict__ x_table) {
  int n = blockIdx.x;
  int d = threadIdx.x;
  g_tx[n * D + d] = x_table[x_idx[n] * D + d];
  if (d == 0) {
    g_deg[n] = 0;
    int b = batch[n];
    if (n == 0) {
      for (int g = 0; g <= b; ++g) g_gstart[g] = 0;
    } else {
      int pb = batch[n - 1];
      for (int g = pb + 1; g <= b; ++g) g_gstart[g] = n;
    }
    if (n == N - 1) {
      for (int g = b + 1; g <= NG; ++g) g_gstart[g] = N;
    }
  }
}

__global__ void k_hist(const int* __restrict__ edge_dst) {
  int e = blockIdx.x * blockDim.x + threadIdx.x;
  if (e < E) atomicAdd(&g_deg[edge_dst[e]], 1);
}

__global__ void k_scan() {
  __shared__ int sums[1024];
  int tid = threadIdx.x;
  const int CH = (N + 1023) / 1024;
  int beg = tid * CH;
  int end = min(beg + CH, N);
  int s = 0;
  for (int i = beg; i < end; ++i) s += g_deg[i];
  sums[tid] = s;
  __syncthreads();
  for (int off = 1; off < 1024; off <<= 1) {
    int v = (tid >= off) ? sums[tid - off] : 0;
    __syncthreads();
    sums[tid] += v;
    __syncthreads();
  }
  int pre = (tid == 0) ? 0 : sums[tid - 1];
  for (int i = beg; i < end; ++i) {
    g_rowoff[i] = pre;
    g_cursor[i] = pre;
    pre += g_deg[i];
  }
  if (tid == 1023) g_rowoff[N] = sums[1023];
}

__global__ void k_scatter(const int* __restrict__ edge_src,
                          const int* __restrict__ edge_dst) {
  int e = blockIdx.x * blockDim.x + threadIdx.x;
  if (e < E) {
    int d = edge_dst[e];
    int pos = atomicAdd(&g_cursor[d], 1);
    g_csrsrc[pos] = edge_src[e];
  }
}

// z[n,:] = h[n,:] + sum_{e: dst==n} h[src,:]   (one warp per node)
__global__ void __launch_bounds__(256) k_agg(const float* __restrict__ hin,
                                             float* __restrict__ zout) {
  int w = (blockIdx.x * blockDim.x + threadIdx.x) >> 5;
  int lane = threadIdx.x & 31;
  if (w >= N) return;
  int beg = g_rowoff[w], end = g_rowoff[w + 1];
  float4 acc = *reinterpret_cast<const float4*>(hin + (size_t)w * D + lane * 4);
  int k = beg;
  for (; k + 1 < end; k += 2) {
    int s0 = g_csrsrc[k];
    int s1 = g_csrsrc[k + 1];
    float4 v0 = *reinterpret_cast<const float4*>(hin + (size_t)s0 * D + lane * 4);
    float4 v1 = *reinterpret_cast<const float4*>(hin + (size_t)s1 * D + lane * 4);
    acc.x += v0.x + v1.x; acc.y += v0.y + v1.y;
    acc.z += v0.z + v1.z; acc.w += v0.w + v1.w;
  }
  if (k < end) {
    int s0 = g_csrsrc[k];
    float4 v0 = *reinterpret_cast<const float4*>(hin + (size_t)s0 * D + lane * 4);
    acc.x += v0.x; acc.y += v0.y; acc.z += v0.z; acc.w += v0.w;
  }
  *reinterpret_cast<float4*>(zout + (size_t)w * D + lane * 4) = acc;
}

// Unified 128x128-tile GEMM, 8x8 per thread, FFMA2, double-buffered.
// Dense mode  (listb==null): rows t0+zr, Out[row]=relu(Z[row]@W+b)
// List mode   (listb!=null): rows from list[m]; Z-input gets +Dz[m][row];
//                            Out[m][row] = relu(..) - Sub[row]
__global__ void __launch_bounds__(256, 2) k_mm(
    int Rdense,
    const int* __restrict__ listb, const int* __restrict__ cntp, int cntoff,
    const float* __restrict__ Zb, const float* __restrict__ Dzb,
    const float* __restrict__ W, const float* __restrict__ bias,
    const float* __restrict__ Sub, float* __restrict__ Outb) {
  const int m = blockIdx.y;
  const int cnt = listb ? cntp[cntoff + m] : Rdense;
  const int t0 = blockIdx.x * 128;
  if (t0 >= cnt) return;
  const int* list = listb ? (listb + m * N) : nullptr;
  const float* Dz = Dzb ? (Dzb + (size_t)m * N * D) : nullptr;
  float* Out = Outb + (listb ? (size_t)m * N * D : (size_t)0);

  __shared__ int lrow[128];
  __shared__ float Zs[2][16][136];
  __shared__ float Ws[2][16][132];

  const int tid = threadIdx.x;
  if (list) {
    if (tid < 128) lrow[tid] = (t0 + tid < cnt) ? list[t0 + tid] : -1;
    __syncthreads();
  }
  const int zr = tid >> 1;         // 0..127
  const int zk = (tid & 1) * 8;    // 0 or 8
  const int wk = tid >> 4;         // 0..15
  const int wj = (tid & 15) * 8;   // 0..120
  const int tr = tid >> 4;         // 0..15 -> rows tr*8..+7
  const int tc = tid & 15;         // 0..15 -> cols tc*8..+7
  const int zrow = list ? lrow[zr] : ((t0 + zr < cnt) ? (t0 + zr) : -1);

  ull acc[8][4];
#pragma unroll
  for (int i = 0; i < 8; ++i)
#pragma unroll
    for (int p = 0; p < 4; ++p) acc[i][p] = 0ull;

  // stage chunk 0
  {
    float4 a0 = make_float4(0.f, 0.f, 0.f, 0.f), a1 = a0;
    if (zrow >= 0) {
      a0 = *reinterpret_cast<const float4*>(Zb + (size_t)zrow * 128 + zk);
      a1 = *reinterpret_cast<const float4*>(Zb + (size_t)zrow * 128 + zk + 4);
      if (Dz) {
        float4 d0 = *reinterpret_cast<const float4*>(Dz + (size_t)zrow * 128 + zk);
        float4 d1 = *reinterpret_cast<const float4*>(Dz + (size_t)zrow * 128 + zk + 4);
        a0.x += d0.x; a0.y += d0.y; a0.z += d0.z; a0.w += d0.w;
        a1.x += d1.x; a1.y += d1.y; a1.z += d1.z; a1.w += d1.w;
      }
    }
    Zs[0][zk + 0][zr] = a0.x; Zs[0][zk + 1][zr] = a0.y;
    Zs[0][zk + 2][zr] = a0.z; Zs[0][zk + 3][zr] = a0.w;
    Zs[0][zk + 4][zr] = a1.x; Zs[0][zk + 5][zr] = a1.y;
    Zs[0][zk + 6][zr] = a1.z; Zs[0][zk + 7][zr] = a1.w;
    float4 w0 = *reinterpret_cast<const float4*>(W + (size_t)wk * 128 + wj);
    float4 w1 = *reinterpret_cast<const float4*>(W + (size_t)wk * 128 + wj + 4);
    *reinterpret_cast<float4*>(&Ws[0][wk][wj]) = w0;
    *reinterpret_cast<float4*>(&Ws[0][wk][wj + 4]) = w1;
  }
  __syncthreads();

  int buf = 0;
#pragma unroll 1
  for (int c = 0; c < 8; ++c) {
    float4 na0, na1, nw0, nw1;
    if (c < 7) {
      int k0 = (c + 1) * 16;
      na0 = make_float4(0.f, 0.f, 0.f, 0.f); na1 = na0;
      if (zrow >= 0) {
        na0 = *reinterpret_cast<const float4*>(Zb + (size_t)zrow * 128 + k0 + zk);
        na1 = *reinterpret_cast<const float4*>(Zb + (size_t)zrow * 128 + k0 + zk + 4);
        if (Dz) {
          float4 d0 = *reinterpret_cast<const float4*>(Dz + (size_t)zrow * 128 + k0 + zk);
          float4 d1 = *reinterpret_cast<const float4*>(Dz + (size_t)zrow * 128 + k0 + zk + 4);
          na0.x += d0.x; na0.y += d0.y; na0.z += d0.z; na0.w += d0.w;
          na1.x += d1.x; na1.y += d1.y; na1.z += d1.z; na1.w += d1.w;
        }
      }
      nw0 = *reinterpret_cast<const float4*>(W + (size_t)(k0 + wk) * 128 + wj);
      nw1 = *reinterpret_cast<const float4*>(W + (size_t)(k0 + wk) * 128 + wj + 4);
    }
#pragma unroll
    for (int kk = 0; kk < 16; ++kk) {
      float4 za = *reinterpret_cast<const float4*>(&Zs[buf][kk][tr * 8]);
      float4 zb2 = *reinterpret_cast<const float4*>(&Zs[buf][kk][tr * 8 + 4]);
      ull z0 = pack2dup(za.x), z1 = pack2dup(za.y);
      ull z2 = pack2dup(za.z), z3 = pack2dup(za.w);
      ull z4 = pack2dup(zb2.x), z5 = pack2dup(zb2.y);
      ull z6 = pack2dup(zb2.z), z7 = pack2dup(zb2.w);
      const ull* wp = reinterpret_cast<const ull*>(&Ws[buf][kk][tc * 8]);
      ull w0 = wp[0], w1 = wp[1], w2 = wp[2], w3 = wp[3];
      acc[0][0] = ffma2(z0, w0, acc[0][0]); acc[0][1] = ffma2(z0, w1, acc[0][1]);
      acc[0][2] = ffma2(z0, w2, acc[0][2]); acc[0][3] = ffma2(z0, w3, acc[0][3]);
      acc[1][0] = ffma2(z1, w0, acc[1][0]); acc[1][1] = ffma2(z1, w1, acc[1][1]);
      acc[1][2] = ffma2(z1, w2, acc[1][2]); acc[1][3] = ffma2(z1, w3, acc[1][3]);
      acc[2][0] = ffma2(z2, w0, acc[2][0]); acc[2][1] = ffma2(z2, w1, acc[2][1]);
      acc[2][2] = ffma2(z2, w2, acc[2][2]); acc[2][3] = ffma2(z2, w3, acc[2][3]);
      acc[3][0] = ffma2(z3, w0, acc[3][0]); acc[3][1] = ffma2(z3, w1, acc[3][1]);
      acc[3][2] = ffma2(z3, w2, acc[3][2]); acc[3][3] = ffma2(z3, w3, acc[3][3]);
      acc[4][0] = ffma2(z4, w0, acc[4][0]); acc[4][1] = ffma2(z4, w1, acc[4][1]);
      acc[4][2] = ffma2(z4, w2, acc[4][2]); acc[4][3] = ffma2(z4, w3, acc[4][3]);
      acc[5][0] = ffma2(z5, w0, acc[5][0]); acc[5][1] = ffma2(z5, w1, acc[5][1]);
      acc[5][2] = ffma2(z5, w2, acc[5][2]); acc[5][3] = ffma2(z5, w3, acc[5][3]);
      acc[6][0] = ffma2(z6, w0, acc[6][0]); acc[6][1] = ffma2(z6, w1, acc[6][1]);
      acc[6][2] = ffma2(z6, w2, acc[6][2]); acc[6][3] = ffma2(z6, w3, acc[6][3]);
      acc[7][0] = ffma2(z7, w0, acc[7][0]); acc[7][1] = ffma2(z7, w1, acc[7][1]);
      acc[7][2] = ffma2(z7, w2, acc[7][2]); acc[7][3] = ffma2(z7, w3, acc[7][3]);
    }
    if (c < 7) {
      int nb = buf ^ 1;
      Zs[nb][zk + 0][zr] = na0.x; Zs[nb][zk + 1][zr] = na0.y;
      Zs[nb][zk + 2][zr] = na0.z; Zs[nb][zk + 3][zr] = na0.w;
      Zs[nb][zk + 4][zr] = na1.x; Zs[nb][zk + 5][zr] = na1.y;
      Zs[nb][zk + 6][zr] = na1.z; Zs[nb][zk + 7][zr] = na1.w;
      *reinterpret_cast<float4*>(&Ws[nb][wk][wj]) = nw0;
      *reinterpret_cast<float4*>(&Ws[nb][wk][wj + 4]) = nw1;
      __syncthreads();
      buf = nb;
    }
  }

  float4 b0 = *reinterpret_cast<const float4*>(bias + tc * 8);
  float4 b1 = *reinterpret_cast<const float4*>(bias + tc * 8 + 4);
  float bb[8] = {b0.x, b0.y, b0.z, b0.w, b1.x, b1.y, b1.z, b1.w};
#pragma unroll
  for (int i = 0; i < 8; ++i) {
    int row = list ? lrow[tr * 8 + i]
                   : ((t0 + tr * 8 + i < cnt) ? (t0 + tr * 8 + i) : -1);
    if (row >= 0) {
      float o[8];
#pragma unroll
      for (int p = 0; p < 4; ++p) {
        float lo, hi;
        unpack2(acc[i][p], lo, hi);
        o[2 * p] = fmaxf(lo + bb[2 * p], 0.f);
        o[2 * p + 1] = fmaxf(hi + bb[2 * p + 1], 0.f);
      }
      if (Sub) {
        float4 s0 = *reinterpret_cast<const float4*>(Sub + (size_t)row * 128 + tc * 8);
        float4 s1 = *reinterpret_cast<const float4*>(Sub + (size_t)row * 128 + tc * 8 + 4);
        o[0] -= s0.x; o[1] -= s0.y; o[2] -= s0.z; o[3] -= s0.w;
        o[4] -= s1.x; o[5] -= s1.y; o[6] -= s1.z; o[7] -= s1.w;
      }
      *reinterpret_cast<float4*>(Out + (size_t)row * 128 + tc * 8) =
          make_float4(o[0], o[1], o[2], o[3]);
      *reinterpret_cast<float4*>(Out + (size_t)row * 128 + tc * 8 + 4) =
          make_float4(o[4], o[5], o[6], o[7]);
    }
  }
}

// ---------------- sampling path (unchanged, validated) ----------------
__global__ void k_pred(const float* __restrict__ h, const float* __restrict__ Wd,
                       const float* __restrict__ bd) {
  int w = (blockIdx.x * blockDim.x + threadIdx.x) >> 5;
  int lane = threadIdx.x & 31;
  if (w >= N) return;
  float4 hv = *reinterpret_cast<const float4*>(h + (size_t)w * D + lane * 4);
  float4 wv = *reinterpret_cast<const float4*>(Wd + lane * 4);
  float s = hv.x * wv.x + hv.y * wv.y + hv.z * wv.z + hv.w * wv.w;
#pragma unroll
  for (int off = 16; off; off >>= 1) s += __shfl_xor_sync(0xffffffffu, s, off);
  if (lane == 0) g_pred[w] = s + bd[0];
}

__global__ void k_gstats() {
  int g = blockIdx.x;
  int tid = threadIdx.x;
  int beg = g_gstart[g], end = g_gstart[g + 1];
  __shared__ float red[256];
  float mx = -3.4e38f;
  for (int n = beg + tid; n < end; n += 256) mx = fmaxf(mx, g_pred[n]);
  red[tid] = mx;
  __syncthreads();
  for (int off = 128; off; off >>= 1) {
    if (tid < off) red[tid] = fmaxf(red[tid], red[tid + off]);
    __syncthreads();
  }
  float mxv = red[0];
  __syncthreads();
  float s = 0.f;
  for (int n = beg + tid; n < end; n += 256) s += expf(g_pred[n] - mxv);
  red[tid] = s;
  __syncthreads();
  for (int off = 128; off; off >>= 1) {
    if (tid < off) red[tid] += red[tid + off];
    __syncthreads();
  }
  if (tid == 0) {
    bool ok = beg < end;
    g_gmax[g] = ok ? mxv : 0.f;
    g_gsum[g] = ok ? red[0] : 1.f;
  }
}

__global__ void k_sample() {
  int b = blockIdx.x;
  int m = b >> 7;
  int g = b & 127;
  int tid = threadIdx.x;
  int beg = g_gstart[g], end = g_gstart[g + 1];
  if (beg >= end) {
    if (tid == 0) g_anchor[b] = -1;
    return;
  }
  uint2 dk = threefry2x32(0u, 1u, 0u, 1u);
  float mxv = g_gmax[g];
  float sv = g_gsum[g];
  float best = -3.4e38f;
  int bid = 0x7fffffff;
  for (int n = beg + tid; n < end; n += 128) {
    float prob = expf(g_pred[n] - mxv) / sv;
    float lp = logf(prob + 1e-15f);
    uint2 r = threefry2x32(dk.x, dk.y, (unsigned)n, (unsigned)(N + n));
    unsigned bits = (m == 0) ? r.x : r.y;
    float u = __uint_as_float((bits >> 9) | 0x3f800000u) - 1.0f;
    float gum = -logf(-logf(u + 1e-12f) + 1e-12f);
    float sc = lp + gum;
    if (sc > best || (sc == best && n < bid)) { best = sc; bid = n; }
  }
  __shared__ float rs[128];
  __shared__ int ri[128];
  rs[tid] = best; ri[tid] = bid;
  __syncthreads();
  for (int off = 64; off; off >>= 1) {
    if (tid < off) {
      if (rs[tid + off] > rs[tid] ||
          (rs[tid + off] == rs[tid] && ri[tid + off] < ri[tid])) {
        rs[tid] = rs[tid + off];
        ri[tid] = ri[tid + off];
      }
    }
    __syncthreads();
  }
  if (tid == 0) g_anchor[b] = ri[0];
}

// ---------------- pass-2 sparse machinery ----------------
__global__ void k_mclear() {
  int n = blockIdx.x * blockDim.x + threadIdx.x;
  if (n < N) {
    g_fA[n] = 0; g_fA[N + n] = 0;
    g_f1[n] = 0; g_f1[N + n] = 0;
    g_f2[n] = 0; g_f2[N + n] = 0;
  }
  if (n < 8) g_cnt[n] = 0;
}

__global__ void k_mark_anchor() {
  int t = blockIdx.x * blockDim.x + threadIdx.x;
  if (t < M * NG) {
    int a = g_anchor[t];
    int m = t >> 7;
    if (a >= 0) { g_fA[m * N + a] = 1; g_f1[m * N + a] = 1; }
  }
}

__global__ void k_mark_edges1(const int* __restrict__ es, const int* __restrict__ ed) {
  int e = blockIdx.x * blockDim.x + threadIdx.x;
  if (e >= E) return;
  int s = es[e], dd = ed[e];
#pragma unroll
  for (int m = 0; m < M; ++m) {
    if (g_fA[m * N + s]) {
      g_f1[m * N + dd] = 1;
      int p = atomicAdd(&g_cnt[2 + m], 1);
      g_hitE[m * E + p] = e;
    }
  }
}

__global__ void k_compact1() {
  int n = blockIdx.x * blockDim.x + threadIdx.x;
  if (n >= N) return;
#pragma unroll
  for (int m = 0; m < M; ++m) {
    if (g_f1[m * N + n]) {
      int p = atomicAdd(&g_cnt[m], 1);
      g_list1[m * N + p] = n;
    }
  }
}

__global__ void k_mark_edges2(const int* __restrict__ es, const int* __restrict__ ed) {
  int e = blockIdx.x * blockDim.x + threadIdx.x;
  if (e >= E) return;
  int s = es[e], dd = ed[e];
#pragma unroll
  for (int m = 0; m < M; ++m) {
    if (g_f1[m * N + s]) {
      g_f2[m * N + dd] = 1;
      int p = atomicAdd(&g_cnt[6 + m], 1);
      g_hitE[m * E + p] = e;
    }
  }
}

__global__ void k_compact2() {
  int n = blockIdx.x * blockDim.x + threadIdx.x;
  if (n >= N) return;
#pragma unroll
  for (int m = 0; m < M; ++m) {
    if (g_f1[m * N + n] || g_f2[m * N + n]) {
      int p = atomicAdd(&g_cnt[4 + m], 1);
      g_list2[m * N + p] = n;
    }
  }
}

__global__ void k_zero_rows(int which) {
  int m = blockIdx.y;
  const int* list = (which ? g_list2 : g_list1) + m * N;
  int cnt = g_cnt[(which ? 4 : 0) + m];
  int w = blockIdx.x * 8 + (threadIdx.x >> 5);
  int lane = threadIdx.x & 31;
  float* dz = g_dz + (size_t)m * N * D;
  for (int i = w; i < cnt; i += 256 * 8) {
    int row = list[i];
    *reinterpret_cast<float4*>(dz + (size_t)row * D + lane * 4) =
        make_float4(0.f, 0.f, 0.f, 0.f);
  }
}

__global__ void k_self1(const float* __restrict__ at) {
  int m = blockIdx.y;
  int g = blockIdx.x;
  int a = g_anchor[m * NG + g];
  if (a < 0) return;
  int lane = threadIdx.x;
  float4 t = *reinterpret_cast<const float4*>(g_tx + (size_t)a * D + lane * 4);
  float4 f = *reinterpret_cast<const float4*>(at + D + lane * 4);
  *reinterpret_cast<float4*>(g_dz + ((size_t)m * N + a) * D + lane * 4) =
      make_float4(t.x * f.x, t.y * f.y, t.z * f.z, t.w * f.w);
}

__global__ void k_edge_add1(const int* __restrict__ es, const int* __restrict__ ed,
                            const float* __restrict__ at) {
  int m = blockIdx.y;
  int cnt = g_cnt[2 + m];
  int w = blockIdx.x * 8 + (threadIdx.x >> 5);
  int lane = threadIdx.x & 31;
  float4 f = *reinterpret_cast<const float4*>(at + D + lane * 4);
  float* dz = g_dz + (size_t)m * N * D;
  for (int i = w; i < cnt; i += 256 * 8) {
    int e = g_hitE[m * E + i];
    int s = es[e], dd = ed[e];
    float4 t = *reinterpret_cast<const float4*>(g_tx + (size_t)s * D + lane * 4);
    float* p = dz + (size_t)dd * D + lane * 4;
    atomicAdd(p + 0, t.x * f.x);
    atomicAdd(p + 1, t.y * f.y);
    atomicAdd(p + 2, t.z * f.z);
    atomicAdd(p + 3, t.w * f.w);
  }
}

__global__ void k_self2() {
  int m = blockIdx.y;
  int cnt = g_cnt[m];
  int w = blockIdx.x * 8 + (threadIdx.x >> 5);
  int lane = threadIdx.x & 31;
  const float* dh1 = g_dh1 + (size_t)m * N * D;
  float* dz = g_dz + (size_t)m * N * D;
  for (int i = w; i < cnt; i += 256 * 8) {
    int row = g_list1[m * N + i];
    float4 v = *reinterpret_cast<const float4*>(dh1 + (size_t)row * D + lane * 4);
    *reinterpret_cast<float4*>(dz + (size_t)row * D + lane * 4) = v;
  }
}

__global__ void k_edge_add2(const int* __restrict__ es, const int* __restrict__ ed) {
  int m = blockIdx.y;
  int cnt = g_cnt[6 + m];
  int w = blockIdx.x * 8 + (threadIdx.x >> 5);
  int lane = threadIdx.x & 31;
  const float* dh1 = g_dh1 + (size_t)m * N * D;
  float* dz = g_dz + (size_t)m * N * D;
  for (int i = w; i < cnt; i += 256 * 8) {
    int e = g_hitE[m * E + i];
    int s = es[e], dd = ed[e];
    float4 v = *reinterpret_cast<const float4*>(dh1 + (size_t)s * D + lane * 4);
    float* p = dz + (size_t)dd * D + lane * 4;
    atomicAdd(p + 0, v.x);
    atomicAdd(p + 1, v.y);
    atomicAdd(p + 2, v.z);
    atomicAdd(p + 3, v.w);
  }
}

// base mean pool over all nodes -> write both m copies of g_hg
__global__ void k_poolb() {
  int g = blockIdx.x;
  int tid = threadIdx.x;
  int d = tid & 127;
  int half = tid >> 7;
  int beg = g_gstart[g], end = g_gstart[g + 1];
  float acc = 0.f;
  for (int n = beg + half; n < end; n += 2) acc += g_hn[(size_t)n * D + d];
  __shared__ float s[128];
  if (half == 1) s[d] = acc;
  __syncthreads();
  if (half == 0) {
    float tot = acc + s[d];
    int c = end - beg;
    float v = tot / (float)max(c, 1);
    g_hg[(0 * NG + g) * D + d] = v;
    g_hg[(1 * NG + g) * D + d] = v;
  }
}

__global__ void k_pool_delta(const int* __restrict__ batch) {
  int m = blockIdx.y;
  int cnt = g_cnt[4 + m];
  int d = threadIdx.x;
  const float* dhn = g_dhn + (size_t)m * N * D;
  for (int i = blockIdx.x; i < cnt; i += gridDim.x) {
    int n = g_list2[m * N + i];
    int g = batch[n];
    int c = g_gstart[g + 1] - g_gstart[g];
    float inv = 1.0f / (float)max(c, 1);
    atomicAdd(&g_hg[(m * NG + g) * D + d], dhn[(size_t)n * D + d] * inv);
  }
}

__global__ void k_out(const float* __restrict__ Wp, const float* __restrict__ bp,
                      float* __restrict__ out) {
  int g = blockIdx.x;
  int t = threadIdx.x;
  if (t >= NT) return;
  float acc = 0.f;
  for (int m = 0; m < M; ++m) {
    const float* hg = &g_hg[(m * NG + g) * D];
    float s = 0.f;
#pragma unroll 16
    for (int k = 0; k < D; ++k) s += hg[k] * Wp[k * NT + t];
    acc += s;
  }
  out[g * NT + t] = acc * (1.0f / M) + bp[t];
}

// ---------------- launch ----------------
extern "C" void kernel_launch(void* const* d_in, const int* in_sizes, int n_in,
                              void* d_out, int out_size) {
  const int*   x_idx    = (const int*)d_in[0];
  const int*   edge_src = (const int*)d_in[1];
  const int*   edge_dst = (const int*)d_in[2];
  const int*   batch    = (const int*)d_in[3];
  const float* x_table  = (const float*)d_in[4];
  const float* anchor_t = (const float*)d_in[5];
  const float* Wg       = (const float*)d_in[6];
  const float* bg       = (const float*)d_in[7];
  const float* Wn       = (const float*)d_in[8];
  const float* bn       = (const float*)d_in[9];
  const float* Wd       = (const float*)d_in[10];
  const float* bd       = (const float*)d_in[11];
  const float* Wp       = (const float*)d_in[12];
  const float* bp       = (const float*)d_in[13];
  float* out = (float*)d_out;

  float *txp, *z1, *h1, *z2, *h2, *hn, *dz, *dh1, *dh2, *dhn;
  int *list1, *list2, *cnt;
  cudaGetSymbolAddress((void**)&txp, g_tx);
  cudaGetSymbolAddress((void**)&z1, g_z1);
  cudaGetSymbolAddress((void**)&h1, g_h1);
  cudaGetSymbolAddress((void**)&z2, g_z2);
  cudaGetSymbolAddress((void**)&h2, g_h2);
  cudaGetSymbolAddress((void**)&hn, g_hn);
  cudaGetSymbolAddress((void**)&dz, g_dz);
  cudaGetSymbolAddress((void**)&dh1, g_dh1);
  cudaGetSymbolAddress((void**)&dh2, g_dh2);
  cudaGetSymbolAddress((void**)&dhn, g_dhn);
  cudaGetSymbolAddress((void**)&list1, g_list1);
  cudaGetSymbolAddress((void**)&list2, g_list2);
  cudaGetSymbolAddress((void**)&cnt, g_cnt);

  const int AGG_GRID = (N * 32 + 255) / 256;
  const int MMG = (N + 127) / 128;       // 391
  const dim3 MM1(MMG, 1);
  const dim3 MM2(MMG, 2);
  const dim3 SP(256, 2);

  // ---- prep ----
  k_embed<<<N, D>>>(x_idx, batch, x_table);
  k_hist<<<(E + 255) / 256, 256>>>(edge_dst);
  k_scan<<<1, 1024>>>();
  k_scatter<<<(E + 255) / 256, 256>>>(edge_src, edge_dst);

  // ---- pass 1 (base, m-independent) ----
  k_agg<<<AGG_GRID, 256>>>(txp, z1);
  k_mm<<<MM1, 256>>>(N, nullptr, nullptr, 0, z1, nullptr, Wg, bg, nullptr, h1);
  k_agg<<<AGG_GRID, 256>>>(h1, z2);
  k_mm<<<MM1, 256>>>(N, nullptr, nullptr, 0, z2, nullptr, Wg + D * D, bg + D, nullptr, h2);

  // ---- sampling ----
  k_pred<<<AGG_GRID, 256>>>(h2, Wd, bd);
  k_gstats<<<NG, 256>>>();
  k_sample<<<M * NG, 128>>>();

  // ---- base node MLP + base pool ----
  k_mm<<<MM1, 256>>>(N, nullptr, nullptr, 0, h2, nullptr, Wn, bn, nullptr, hn);
  k_poolb<<<NG, 256>>>();

  // ---- pass 2: sparse deltas, both m ----
  k_mclear<<<(N + 255) / 256, 256>>>();
  k_mark_anchor<<<1, M * NG>>>();
  k_mark_edges1<<<(E + 255) / 256, 256>>>(edge_src, edge_dst);
  k_compact1<<<(N + 255) / 256, 256>>>();
  k_zero_rows<<<SP, 256>>>(0);
  k_self1<<<dim3(NG, 2), 32>>>(anchor_t);
  k_edge_add1<<<SP, 256>>>(edge_src, edge_dst, anchor_t);
  k_mm<<<MM2, 256>>>(0, list1, cnt, 0, z1, dz, Wg, bg, h1, dh1);
  k_mark_edges2<<<(E + 255) / 256, 256>>>(edge_src, edge_dst);
  k_compact2<<<(N + 255) / 256, 256>>>();
  k_zero_rows<<<SP, 256>>>(1);
  k_self2<<<SP, 256>>>();
  k_edge_add2<<<SP, 256>>>(edge_src, edge_dst);
  k_mm<<<MM2, 256>>>(0, list2, cnt, 4, z2, dz, Wg + D * D, bg + D, h2, dh2);
  k_mm<<<MM2, 256>>>(0, list2, cnt, 4, h2, dh2, Wn, bn, hn, dhn);
  k_pool_delta<<<dim3(256, 2), 128>>>(batch);

  // ---- head ----
  k_out<<<NG, 32>>>(Wp, bp, out);
}

// round 5
// speedup vs baseline: 1.4378x; 1.4378x over previous
#include <cuda_runtime.h>
#include <stdint.h>

// ---------------- problem constants ----------------
constexpr int N  = 50000;
constexpr int E  = 800000;
constexpr int NG = 128;
constexpr int D  = 128;
constexpr int M  = 2;
constexpr int NT = 10;

typedef unsigned long long ull;

// ---------------- device scratch ----------------
__device__ float g_tx[N * D];
__device__ float g_z1[N * D];
__device__ float g_h1[N * D];
__device__ float g_z2[N * D];
__device__ float g_h2[N * D];
__device__ float g_hn[N * D];
__device__ float g_dz[M * N * D];
__device__ float g_dh1[M * N * D];
__device__ float g_dh2[M * N * D];
__device__ float g_dhn[M * N * D];
__device__ int   g_deg[N];
__device__ int   g_rowoff[N + 1];
__device__ int   g_cursor[N];
__device__ int   g_csrsrc[E];
__device__ int   g_gstart[NG + 1];
__device__ float g_pred[N];
__device__ float g_gmax[NG];
__device__ float g_gsum[NG];
__device__ int   g_anchor[M * NG];
__device__ float g_hg[M * NG * D];
__device__ unsigned char g_fA[M * N];
__device__ unsigned char g_f1[M * N];
__device__ unsigned char g_f2[M * N];
__device__ int   g_list1[M * N];
__device__ int   g_list2[M * N];
__device__ int   g_hitE[M * E];
__device__ int   g_cnt[8];  // [m]=cnt1, [2+m]=hit1, [4+m]=cnt2, [6+m]=hit2

// ---------------- f32x2 helpers ----------------
__device__ __forceinline__ ull ffma2(ull a, ull b, ull c) {
  ull d;
  asm("fma.rn.f32x2 %0, %1, %2, %3;" : "=l"(d) : "l"(a), "l"(b), "l"(c));
  return d;
}
__device__ __forceinline__ ull pack2dup(float x) {
  ull r;
  asm("mov.b64 %0, {%1, %1};" : "=l"(r) : "f"(x));
  return r;
}
__device__ __forceinline__ void unpack2(ull v, float& lo, float& hi) {
  asm("mov.b64 {%0, %1}, %2;" : "=f"(lo), "=f"(hi) : "l"(v));
}
__device__ __forceinline__ void cp16(void* smem, const void* gmem) {
  unsigned s = (unsigned)__cvta_generic_to_shared(smem);
  asm volatile("cp.async.cg.shared.global [%0], [%1], 16;" :: "r"(s), "l"(gmem));
}
__device__ __forceinline__ void cp_commit_wait() {
  asm volatile("cp.async.commit_group;");
  asm volatile("cp.async.wait_group 0;");
}

// ---------------- threefry2x32 (exact JAX) ----------------
__device__ __forceinline__ uint2 threefry2x32(unsigned k0, unsigned k1,
                                              unsigned x0, unsigned x1) {
  unsigned k2 = k0 ^ k1 ^ 0x1BD11BDAu;
  x0 += k0; x1 += k1;
#define TF_ROT(x, d) (((x) << (d)) | ((x) >> (32 - (d))))
#define TF_RND(r) { x0 += x1; x1 = TF_ROT(x1, r); x1 ^= x0; }
  TF_RND(13) TF_RND(15) TF_RND(26) TF_RND(6)
  x0 += k1; x1 += k2 + 1u;
  TF_RND(17) TF_RND(29) TF_RND(16) TF_RND(24)
  x0 += k2; x1 += k0 + 2u;
  TF_RND(13) TF_RND(15) TF_RND(26) TF_RND(6)
  x0 += k0; x1 += k1 + 3u;
  TF_RND(17) TF_RND(29) TF_RND(16) TF_RND(24)
  x0 += k1; x1 += k2 + 4u;
  TF_RND(13) TF_RND(15) TF_RND(26) TF_RND(6)
  x0 += k2; x1 += k0 + 5u;
#undef TF_RND
#undef TF_ROT
  return make_uint2(x0, x1);
}

// ---------------- base kernels ----------------
__global__ void k_embed(const int* __restrict__ x_idx,
                        const int* __restrict__ batch,
                        const float* __restrict__ x_table) {
  int n = blockIdx.x;
  int d = threadIdx.x;
  g_tx[n * D + d] = x_table[x_idx[n] * D + d];
  if (d == 0) {
    g_deg[n] = 0;
    int b = batch[n];
    if (n == 0) {
      for (int g = 0; g <= b; ++g) g_gstart[g] = 0;
    } else {
      int pb = batch[n - 1];
      for (int g = pb + 1; g <= b; ++g) g_gstart[g] = n;
    }
    if (n == N - 1) {
      for (int g = b + 1; g <= NG; ++g) g_gstart[g] = N;
    }
  }
}

__global__ void k_hist(const int* __restrict__ edge_dst) {
  int e = blockIdx.x * blockDim.x + threadIdx.x;
  if (e < E) atomicAdd(&g_deg[edge_dst[e]], 1);
}

__global__ void k_scan() {
  __shared__ int sums[1024];
  int tid = threadIdx.x;
  const int CH = (N + 1023) / 1024;
  int beg = tid * CH;
  int end = min(beg + CH, N);
  int s = 0;
  for (int i = beg; i < end; ++i) s += g_deg[i];
  sums[tid] = s;
  __syncthreads();
  for (int off = 1; off < 1024; off <<= 1) {
    int v = (tid >= off) ? sums[tid - off] : 0;
    __syncthreads();
    sums[tid] += v;
    __syncthreads();
  }
  int pre = (tid == 0) ? 0 : sums[tid - 1];
  for (int i = beg; i < end; ++i) {
    g_rowoff[i] = pre;
    g_cursor[i] = pre;
    pre += g_deg[i];
  }
  if (tid == 1023) g_rowoff[N] = sums[1023];
}

__global__ void k_scatter(const int* __restrict__ edge_src,
                          const int* __restrict__ edge_dst) {
  int e = blockIdx.x * blockDim.x + threadIdx.x;
  if (e < E) {
    int d = edge_dst[e];
    int pos = atomicAdd(&g_cursor[d], 1);
    g_csrsrc[pos] = edge_src[e];
  }
}

// z[n,:] = h[n,:] + sum_{e: dst==n} h[src,:]   (one warp per node)
__global__ void __launch_bounds__(256) k_agg(const float* __restrict__ hin,
                                             float* __restrict__ zout) {
  int w = (blockIdx.x * blockDim.x + threadIdx.x) >> 5;
  int lane = threadIdx.x & 31;
  if (w >= N) return;
  int beg = g_rowoff[w], end = g_rowoff[w + 1];
  float4 acc = *reinterpret_cast<const float4*>(hin + (size_t)w * D + lane * 4);
  int k = beg;
  for (; k + 1 < end; k += 2) {
    int s0 = g_csrsrc[k];
    int s1 = g_csrsrc[k + 1];
    float4 v0 = *reinterpret_cast<const float4*>(hin + (size_t)s0 * D + lane * 4);
    float4 v1 = *reinterpret_cast<const float4*>(hin + (size_t)s1 * D + lane * 4);
    acc.x += v0.x + v1.x; acc.y += v0.y + v1.y;
    acc.z += v0.z + v1.z; acc.w += v0.w + v1.w;
  }
  if (k < end) {
    int s0 = g_csrsrc[k];
    float4 v0 = *reinterpret_cast<const float4*>(hin + (size_t)s0 * D + lane * 4);
    acc.x += v0.x; acc.y += v0.y; acc.z += v0.z; acc.w += v0.w;
  }
  *reinterpret_cast<float4*>(zout + (size_t)w * D + lane * 4) = acc;
}

// Unified 128x128-tile GEMM, 8x8 per thread, FFMA2, double-buffered,
// W prefetched via cp.async, Z register-staged (transpose). NO reg cap.
__global__ void __launch_bounds__(256) k_mm(
    int Rdense,
    const int* __restrict__ listb, const int* __restrict__ cntp, int cntoff,
    const float* __restrict__ Zb, const float* __restrict__ Dzb,
    const float* __restrict__ W, const float* __restrict__ bias,
    const float* __restrict__ Sub, float* __restrict__ Outb) {
  const int m = blockIdx.y;
  const int cnt = listb ? cntp[cntoff + m] : Rdense;
  const int t0 = blockIdx.x * 128;
  if (t0 >= cnt) return;
  const int* list = listb ? (listb + m * N) : nullptr;
  const float* Dz = Dzb ? (Dzb + (size_t)m * N * D) : nullptr;
  float* Out = Outb + (listb ? (size_t)m * N * D : (size_t)0);

  __shared__ int lrow[128];
  __shared__ float Zs[2][16][136];
  __shared__ float Ws[2][16][132];

  const int tid = threadIdx.x;
  if (list) {
    if (tid < 128) lrow[tid] = (t0 + tid < cnt) ? list[t0 + tid] : -1;
    __syncthreads();
  }
  const int zr = tid >> 1;         // 0..127
  const int zk = (tid & 1) * 8;    // 0 or 8
  const int wk = tid >> 4;         // 0..15
  const int wj = (tid & 15) * 8;   // 0..120
  const int tr = tid >> 4;         // rows tr*8..+7
  const int tc = tid & 15;         // cols tc*8..+7
  const int zrow = list ? lrow[zr] : ((t0 + zr < cnt) ? (t0 + zr) : -1);

  ull acc[8][4];
#pragma unroll
  for (int i = 0; i < 8; ++i)
#pragma unroll
    for (int p = 0; p < 4; ++p) acc[i][p] = 0ull;

  // stage chunk 0: W via cp.async, Z via register transpose
  {
    cp16(&Ws[0][wk][wj], W + (size_t)wk * 128 + wj);
    cp16(&Ws[0][wk][wj + 4], W + (size_t)wk * 128 + wj + 4);
    float4 a0 = make_float4(0.f, 0.f, 0.f, 0.f), a1 = a0;
    if (zrow >= 0) {
      a0 = *reinterpret_cast<const float4*>(Zb + (size_t)zrow * 128 + zk);
      a1 = *reinterpret_cast<const float4*>(Zb + (size_t)zrow * 128 + zk + 4);
      if (Dz) {
        float4 d0 = *reinterpret_cast<const float4*>(Dz + (size_t)zrow * 128 + zk);
        float4 d1 = *reinterpret_cast<const float4*>(Dz + (size_t)zrow * 128 + zk + 4);
        a0.x += d0.x; a0.y += d0.y; a0.z += d0.z; a0.w += d0.w;
        a1.x += d1.x; a1.y += d1.y; a1.z += d1.z; a1.w += d1.w;
      }
    }
    Zs[0][zk + 0][zr] = a0.x; Zs[0][zk + 1][zr] = a0.y;
    Zs[0][zk + 2][zr] = a0.z; Zs[0][zk + 3][zr] = a0.w;
    Zs[0][zk + 4][zr] = a1.x; Zs[0][zk + 5][zr] = a1.y;
    Zs[0][zk + 6][zr] = a1.z; Zs[0][zk + 7][zr] = a1.w;
    cp_commit_wait();
  }
  __syncthreads();

  int buf = 0;
#pragma unroll 1
  for (int c = 0; c < 8; ++c) {
    const int nb = buf ^ 1;
    float4 na0, na1;
    if (c < 7) {
      int k0 = (c + 1) * 16;
      cp16(&Ws[nb][wk][wj], W + (size_t)(k0 + wk) * 128 + wj);
      cp16(&Ws[nb][wk][wj + 4], W + (size_t)(k0 + wk) * 128 + wj + 4);
      na0 = make_float4(0.f, 0.f, 0.f, 0.f); na1 = na0;
      if (zrow >= 0) {
        na0 = *reinterpret_cast<const float4*>(Zb + (size_t)zrow * 128 + k0 + zk);
        na1 = *reinterpret_cast<const float4*>(Zb + (size_t)zrow * 128 + k0 + zk + 4);
        if (Dz) {
          float4 d0 = *reinterpret_cast<const float4*>(Dz + (size_t)zrow * 128 + k0 + zk);
          float4 d1 = *reinterpret_cast<const float4*>(Dz + (size_t)zrow * 128 + k0 + zk + 4);
          na0.x += d0.x; na0.y += d0.y; na0.z += d0.z; na0.w += d0.w;
          na1.x += d1.x; na1.y += d1.y; na1.z += d1.z; na1.w += d1.w;
        }
      }
    }
#pragma unroll
    for (int kk = 0; kk < 16; ++kk) {
      float4 za = *reinterpret_cast<const float4*>(&Zs[buf][kk][tr * 8]);
      float4 zb2 = *reinterpret_cast<const float4*>(&Zs[buf][kk][tr * 8 + 4]);
      ull z0 = pack2dup(za.x), z1 = pack2dup(za.y);
      ull z2 = pack2dup(za.z), z3 = pack2dup(za.w);
      ull z4 = pack2dup(zb2.x), z5 = pack2dup(zb2.y);
      ull z6 = pack2dup(zb2.z), z7 = pack2dup(zb2.w);
      const ull* wp = reinterpret_cast<const ull*>(&Ws[buf][kk][tc * 8]);
      ull w0 = wp[0], w1 = wp[1], w2 = wp[2], w3 = wp[3];
      acc[0][0] = ffma2(z0, w0, acc[0][0]); acc[0][1] = ffma2(z0, w1, acc[0][1]);
      acc[0][2] = ffma2(z0, w2, acc[0][2]); acc[0][3] = ffma2(z0, w3, acc[0][3]);
      acc[1][0] = ffma2(z1, w0, acc[1][0]); acc[1][1] = ffma2(z1, w1, acc[1][1]);
      acc[1][2] = ffma2(z1, w2, acc[1][2]); acc[1][3] = ffma2(z1, w3, acc[1][3]);
      acc[2][0] = ffma2(z2, w0, acc[2][0]); acc[2][1] = ffma2(z2, w1, acc[2][1]);
      acc[2][2] = ffma2(z2, w2, acc[2][2]); acc[2][3] = ffma2(z2, w3, acc[2][3]);
      acc[3][0] = ffma2(z3, w0, acc[3][0]); acc[3][1] = ffma2(z3, w1, acc[3][1]);
      acc[3][2] = ffma2(z3, w2, acc[3][2]); acc[3][3] = ffma2(z3, w3, acc[3][3]);
      acc[4][0] = ffma2(z4, w0, acc[4][0]); acc[4][1] = ffma2(z4, w1, acc[4][1]);
      acc[4][2] = ffma2(z4, w2, acc[4][2]); acc[4][3] = ffma2(z4, w3, acc[4][3]);
      acc[5][0] = ffma2(z5, w0, acc[5][0]); acc[5][1] = ffma2(z5, w1, acc[5][1]);
      acc[5][2] = ffma2(z5, w2, acc[5][2]); acc[5][3] = ffma2(z5, w3, acc[5][3]);
      acc[6][0] = ffma2(z6, w0, acc[6][0]); acc[6][1] = ffma2(z6, w1, acc[6][1]);
      acc[6][2] = ffma2(z6, w2, acc[6][2]); acc[6][3] = ffma2(z6, w3, acc[6][3]);
      acc[7][0] = ffma2(z7, w0, acc[7][0]); acc[7][1] = ffma2(z7, w1, acc[7][1]);
      acc[7][2] = ffma2(z7, w2, acc[7][2]); acc[7][3] = ffma2(z7, w3, acc[7][3]);
    }
    if (c < 7) {
      Zs[nb][zk + 0][zr] = na0.x; Zs[nb][zk + 1][zr] = na0.y;
      Zs[nb][zk + 2][zr] = na0.z; Zs[nb][zk + 3][zr] = na0.w;
      Zs[nb][zk + 4][zr] = na1.x; Zs[nb][zk + 5][zr] = na1.y;
      Zs[nb][zk + 6][zr] = na1.z; Zs[nb][zk + 7][zr] = na1.w;
      cp_commit_wait();
      __syncthreads();
      buf = nb;
    }
  }

  float4 b0 = *reinterpret_cast<const float4*>(bias + tc * 8);
  float4 b1 = *reinterpret_cast<const float4*>(bias + tc * 8 + 4);
  float bb[8] = {b0.x, b0.y, b0.z, b0.w, b1.x, b1.y, b1.z, b1.w};
#pragma unroll
  for (int i = 0; i < 8; ++i) {
    int row = list ? lrow[tr * 8 + i]
                   : ((t0 + tr * 8 + i < cnt) ? (t0 + tr * 8 + i) : -1);
    if (row >= 0) {
      float o[8];
#pragma unroll
      for (int p = 0; p < 4; ++p) {
        float lo, hi;
        unpack2(acc[i][p], lo, hi);
        o[2 * p] = fmaxf(lo + bb[2 * p], 0.f);
        o[2 * p + 1] = fmaxf(hi + bb[2 * p + 1], 0.f);
      }
      if (Sub) {
        float4 s0 = *reinterpret_cast<const float4*>(Sub + (size_t)row * 128 + tc * 8);
        float4 s1 = *reinterpret_cast<const float4*>(Sub + (size_t)row * 128 + tc * 8 + 4);
        o[0] -= s0.x; o[1] -= s0.y; o[2] -= s0.z; o[3] -= s0.w;
        o[4] -= s1.x; o[5] -= s1.y; o[6] -= s1.z; o[7] -= s1.w;
      }
      *reinterpret_cast<float4*>(Out + (size_t)row * 128 + tc * 8) =
          make_float4(o[0], o[1], o[2], o[3]);
      *reinterpret_cast<float4*>(Out + (size_t)row * 128 + tc * 8 + 4) =
          make_float4(o[4], o[5], o[6], o[7]);
    }
  }
}

// ---------------- sampling path (unchanged, validated) ----------------
__global__ void k_pred(const float* __restrict__ h, const float* __restrict__ Wd,
                       const float* __restrict__ bd) {
  int w = (blockIdx.x * blockDim.x + threadIdx.x) >> 5;
  int lane = threadIdx.x & 31;
  if (w >= N) return;
  float4 hv = *reinterpret_cast<const float4*>(h + (size_t)w * D + lane * 4);
  float4 wv = *reinterpret_cast<const float4*>(Wd + lane * 4);
  float s = hv.x * wv.x + hv.y * wv.y + hv.z * wv.z + hv.w * wv.w;
#pragma unroll
  for (int off = 16; off; off >>= 1) s += __shfl_xor_sync(0xffffffffu, s, off);
  if (lane == 0) g_pred[w] = s + bd[0];
}

__global__ void k_gstats() {
  int g = blockIdx.x;
  int tid = threadIdx.x;
  int beg = g_gstart[g], end = g_gstart[g + 1];
  __shared__ float red[256];
  float mx = -3.4e38f;
  for (int n = beg + tid; n < end; n += 256) mx = fmaxf(mx, g_pred[n]);
  red[tid] = mx;
  __syncthreads();
  for (int off = 128; off; off >>= 1) {
    if (tid < off) red[tid] = fmaxf(red[tid], red[tid + off]);
    __syncthreads();
  }
  float mxv = red[0];
  __syncthreads();
  float s = 0.f;
  for (int n = beg + tid; n < end; n += 256) s += expf(g_pred[n] - mxv);
  red[tid] = s;
  __syncthreads();
  for (int off = 128; off; off >>= 1) {
    if (tid < off) red[tid] += red[tid + off];
    __syncthreads();
  }
  if (tid == 0) {
    bool ok = beg < end;
    g_gmax[g] = ok ? mxv : 0.f;
    g_gsum[g] = ok ? red[0] : 1.f;
  }
}

__global__ void k_sample() {
  int b = blockIdx.x;
  int m = b >> 7;
  int g = b & 127;
  int tid = threadIdx.x;
  int beg = g_gstart[g], end = g_gstart[g + 1];
  if (beg >= end) {
    if (tid == 0) g_anchor[b] = -1;
    return;
  }
  uint2 dk = threefry2x32(0u, 1u, 0u, 1u);
  float mxv = g_gmax[g];
  float sv = g_gsum[g];
  float best = -3.4e38f;
  int bid = 0x7fffffff;
  for (int n = beg + tid; n < end; n += 128) {
    float prob = expf(g_pred[n] - mxv) / sv;
    float lp = logf(prob + 1e-15f);
    uint2 r = threefry2x32(dk.x, dk.y, (unsigned)n, (unsigned)(N + n));
    unsigned bits = (m == 0) ? r.x : r.y;
    float u = __uint_as_float((bits >> 9) | 0x3f800000u) - 1.0f;
    float gum = -logf(-logf(u + 1e-12f) + 1e-12f);
    float sc = lp + gum;
    if (sc > best || (sc == best && n < bid)) { best = sc; bid = n; }
  }
  __shared__ float rs[128];
  __shared__ int ri[128];
  rs[tid] = best; ri[tid] = bid;
  __syncthreads();
  for (int off = 64; off; off >>= 1) {
    if (tid < off) {
      if (rs[tid + off] > rs[tid] ||
          (rs[tid + off] == rs[tid] && ri[tid + off] < ri[tid])) {
        rs[tid] = rs[tid + off];
        ri[tid] = ri[tid + off];
      }
    }
    __syncthreads();
  }
  if (tid == 0) g_anchor[b] = ri[0];
}

// ---------------- pass-2 sparse machinery ----------------
__global__ void k_mclear() {
  int n = blockIdx.x * blockDim.x + threadIdx.x;
  if (n < N) {
    g_fA[n] = 0; g_fA[N + n] = 0;
    g_f1[n] = 0; g_f1[N + n] = 0;
    g_f2[n] = 0; g_f2[N + n] = 0;
  }
  if (n < 8) g_cnt[n] = 0;
}

__global__ void k_mark_anchor() {
  int t = blockIdx.x * blockDim.x + threadIdx.x;
  if (t < M * NG) {
    int a = g_anchor[t];
    int m = t >> 7;
    if (a >= 0) { g_fA[m * N + a] = 1; g_f1[m * N + a] = 1; }
  }
}

__global__ void k_mark_edges1(const int* __restrict__ es, const int* __restrict__ ed) {
  int e = blockIdx.x * blockDim.x + threadIdx.x;
  if (e >= E) return;
  int s = es[e], dd = ed[e];
#pragma unroll
  for (int m = 0; m < M; ++m) {
    if (g_fA[m * N + s]) {
      g_f1[m * N + dd] = 1;
      int p = atomicAdd(&g_cnt[2 + m], 1);
      g_hitE[m * E + p] = e;
    }
  }
}

__global__ void k_compact1() {
  int n = blockIdx.x * blockDim.x + threadIdx.x;
  if (n >= N) return;
#pragma unroll
  for (int m = 0; m < M; ++m) {
    if (g_f1[m * N + n]) {
      int p = atomicAdd(&g_cnt[m], 1);
      g_list1[m * N + p] = n;
    }
  }
}

__global__ void k_mark_edges2(const int* __restrict__ es, const int* __restrict__ ed) {
  int e = blockIdx.x * blockDim.x + threadIdx.x;
  if (e >= E) return;
  int s = es[e], dd = ed[e];
#pragma unroll
  for (int m = 0; m < M; ++m) {
    if (g_f1[m * N + s]) {
      g_f2[m * N + dd] = 1;
      int p = atomicAdd(&g_cnt[6 + m], 1);
      g_hitE[m * E + p] = e;
    }
  }
}

__global__ void k_compact2() {
  int n = blockIdx.x * blockDim.x + threadIdx.x;
  if (n >= N) return;
#pragma unroll
  for (int m = 0; m < M; ++m) {
    if (g_f1[m * N + n] || g_f2[m * N + n]) {
      int p = atomicAdd(&g_cnt[4 + m], 1);
      g_list2[m * N + p] = n;
    }
  }
}

__global__ void k_zero_rows(int which) {
  int m = blockIdx.y;
  const int* list = (which ? g_list2 : g_list1) + m * N;
  int cnt = g_cnt[(which ? 4 : 0) + m];
  int w = blockIdx.x * 8 + (threadIdx.x >> 5);
  int lane = threadIdx.x & 31;
  float* dz = g_dz + (size_t)m * N * D;
  for (int i = w; i < cnt; i += 256 * 8) {
    int row = list[i];
    *reinterpret_cast<float4*>(dz + (size_t)row * D + lane * 4) =
        make_float4(0.f, 0.f, 0.f, 0.f);
  }
}

__global__ void k_self1(const float* __restrict__ at) {
  int m = blockIdx.y;
  int g = blockIdx.x;
  int a = g_anchor[m * NG + g];
  if (a < 0) return;
  int lane = threadIdx.x;
  float4 t = *reinterpret_cast<const float4*>(g_tx + (size_t)a * D + lane * 4);
  float4 f = *reinterpret_cast<const float4*>(at + D + lane * 4);
  *reinterpret_cast<float4*>(g_dz + ((size_t)m * N + a) * D + lane * 4) =
      make_float4(t.x * f.x, t.y * f.y, t.z * f.z, t.w * f.w);
}

__global__ void k_edge_add1(const int* __restrict__ es, const int* __restrict__ ed,
                            const float* __restrict__ at) {
  int m = blockIdx.y;
  int cnt = g_cnt[2 + m];
  int w = blockIdx.x * 8 + (threadIdx.x >> 5);
  int lane = threadIdx.x & 31;
  float4 f = *reinterpret_cast<const float4*>(at + D + lane * 4);
  float* dz = g_dz + (size_t)m * N * D;
  for (int i = w; i < cnt; i += 256 * 8) {
    int e = g_hitE[m * E + i];
    int s = es[e], dd = ed[e];
    float4 t = *reinterpret_cast<const float4*>(g_tx + (size_t)s * D + lane * 4);
    float* p = dz + (size_t)dd * D + lane * 4;
    atomicAdd(p + 0, t.x * f.x);
    atomicAdd(p + 1, t.y * f.y);
    atomicAdd(p + 2, t.z * f.z);
    atomicAdd(p + 3, t.w * f.w);
  }
}

__global__ void k_self2() {
  int m = blockIdx.y;
  int cnt = g_cnt[m];
  int w = blockIdx.x * 8 + (threadIdx.x >> 5);
  int lane = threadIdx.x & 31;
  const float* dh1 = g_dh1 + (size_t)m * N * D;
  float* dz = g_dz + (size_t)m * N * D;
  for (int i = w; i < cnt; i += 256 * 8) {
    int row = g_list1[m * N + i];
    float4 v = *reinterpret_cast<const float4*>(dh1 + (size_t)row * D + lane * 4);
    *reinterpret_cast<float4*>(dz + (size_t)row * D + lane * 4) = v;
  }
}

__global__ void k_edge_add2(const int* __restrict__ es, const int* __restrict__ ed) {
  int m = blockIdx.y;
  int cnt = g_cnt[6 + m];
  int w = blockIdx.x * 8 + (threadIdx.x >> 5);
  int lane = threadIdx.x & 31;
  const float* dh1 = g_dh1 + (size_t)m * N * D;
  float* dz = g_dz + (size_t)m * N * D;
  for (int i = w; i < cnt; i += 256 * 8) {
    int e = g_hitE[m * E + i];
    int s = es[e], dd = ed[e];
    float4 v = *reinterpret_cast<const float4*>(dh1 + (size_t)s * D + lane * 4);
    float* p = dz + (size_t)dd * D + lane * 4;
    atomicAdd(p + 0, v.x);
    atomicAdd(p + 1, v.y);
    atomicAdd(p + 2, v.z);
    atomicAdd(p + 3, v.w);
  }
}

// base mean pool over all nodes -> write both m copies of g_hg
__global__ void k_poolb() {
  int g = blockIdx.x;
  int tid = threadIdx.x;
  int d = tid & 127;
  int half = tid >> 7;
  int beg = g_gstart[g], end = g_gstart[g + 1];
  float acc = 0.f;
  for (int n = beg + half; n < end; n += 2) acc += g_hn[(size_t)n * D + d];
  __shared__ float s[128];
  if (half == 1) s[d] = acc;
  __syncthreads();
  if (half == 0) {
    float tot = acc + s[d];
    int c = end - beg;
    float v = tot / (float)max(c, 1);
    g_hg[(0 * NG + g) * D + d] = v;
    g_hg[(1 * NG + g) * D + d] = v;
  }
}

__global__ void k_pool_delta(const int* __restrict__ batch) {
  int m = blockIdx.y;
  int cnt = g_cnt[4 + m];
  int d = threadIdx.x;
  const float* dhn = g_dhn + (size_t)m * N * D;
  for (int i = blockIdx.x; i < cnt; i += gridDim.x) {
    int n = g_list2[m * N + i];
    int g = batch[n];
    int c = g_gstart[g + 1] - g_gstart[g];
    float inv = 1.0f / (float)max(c, 1);
    atomicAdd(&g_hg[(m * NG + g) * D + d], dhn[(size_t)n * D + d] * inv);
  }
}

__global__ void k_out(const float* __restrict__ Wp, const float* __restrict__ bp,
                      float* __restrict__ out) {
  int g = blockIdx.x;
  int t = threadIdx.x;
  if (t >= NT) return;
  float acc = 0.f;
  for (int m = 0; m < M; ++m) {
    const float* hg = &g_hg[(m * NG + g) * D];
    float s = 0.f;
#pragma unroll 16
    for (int k = 0; k < D; ++k) s += hg[k] * Wp[k * NT + t];
    acc += s;
  }
  out[g * NT + t] = acc * (1.0f / M) + bp[t];
}

// ---------------- launch ----------------
extern "C" void kernel_launch(void* const* d_in, const int* in_sizes, int n_in,
                              void* d_out, int out_size) {
  const int*   x_idx    = (const int*)d_in[0];
  const int*   edge_src = (const int*)d_in[1];
  const int*   edge_dst = (const int*)d_in[2];
  const int*   batch    = (const int*)d_in[3];
  const float* x_table  = (const float*)d_in[4];
  const float* anchor_t = (const float*)d_in[5];
  const float* Wg       = (const float*)d_in[6];
  const float* bg       = (const float*)d_in[7];
  const float* Wn       = (const float*)d_in[8];
  const float* bn       = (const float*)d_in[9];
  const float* Wd       = (const float*)d_in[10];
  const float* bd       = (const float*)d_in[11];
  const float* Wp       = (const float*)d_in[12];
  const float* bp       = (const float*)d_in[13];
  float* out = (float*)d_out;

  float *txp, *z1, *h1, *z2, *h2, *hn, *dz, *dh1, *dh2, *dhn;
  int *list1, *list2, *cnt;
  cudaGetSymbolAddress((void**)&txp, g_tx);
  cudaGetSymbolAddress((void**)&z1, g_z1);
  cudaGetSymbolAddress((void**)&h1, g_h1);
  cudaGetSymbolAddress((void**)&z2, g_z2);
  cudaGetSymbolAddress((void**)&h2, g_h2);
  cudaGetSymbolAddress((void**)&hn, g_hn);
  cudaGetSymbolAddress((void**)&dz, g_dz);
  cudaGetSymbolAddress((void**)&dh1, g_dh1);
  cudaGetSymbolAddress((void**)&dh2, g_dh2);
  cudaGetSymbolAddress((void**)&dhn, g_dhn);
  cudaGetSymbolAddress((void**)&list1, g_list1);
  cudaGetSymbolAddress((void**)&list2, g_list2);
  cudaGetSymbolAddress((void**)&cnt, g_cnt);

  const int AGG_GRID = (N * 32 + 255) / 256;
  const int MMG = (N + 127) / 128;       // 391
  const dim3 MM1(MMG, 1);
  const dim3 MM2(MMG, 2);
  const dim3 SP(256, 2);

  // ---- prep ----
  k_embed<<<N, D>>>(x_idx, batch, x_table);
  k_hist<<<(E + 255) / 256, 256>>>(edge_dst);
  k_scan<<<1, 1024>>>();
  k_scatter<<<(E + 255) / 256, 256>>>(edge_src, edge_dst);

  // ---- pass 1 (base, m-independent) ----
  k_agg<<<AGG_GRID, 256>>>(txp, z1);
  k_mm<<<MM1, 256>>>(N, nullptr, nullptr, 0, z1, nullptr, Wg, bg, nullptr, h1);
  k_agg<<<AGG_GRID, 256>>>(h1, z2);
  k_mm<<<MM1, 256>>>(N, nullptr, nullptr, 0, z2, nullptr, Wg + D * D, bg + D, nullptr, h2);

  // ---- sampling ----
  k_pred<<<AGG_GRID, 256>>>(h2, Wd, bd);
  k_gstats<<<NG, 256>>>();
  k_sample<<<M * NG, 128>>>();

  // ---- base node MLP + base pool ----
  k_mm<<<MM1, 256>>>(N, nullptr, nullptr, 0, h2, nullptr, Wn, bn, nullptr, hn);
  k_poolb<<<NG, 256>>>();

  // ---- pass 2: sparse deltas, both m ----
  k_mclear<<<(N + 255) / 256, 256>>>();
  k_mark_anchor<<<1, M * NG>>>();
  k_mark_edges1<<<(E + 255) / 256, 256>>>(edge_src, edge_dst);
  k_compact1<<<(N + 255) / 256, 256>>>();
  k_zero_rows<<<SP, 256>>>(0);
  k_self1<<<dim3(NG, 2), 32>>>(anchor_t);
  k_edge_add1<<<SP, 256>>>(edge_src, edge_dst, anchor_t);
  k_mm<<<MM2, 256>>>(0, list1, cnt, 0, z1, dz, Wg, bg, h1, dh1);
  k_mark_edges2<<<(E + 255) / 256, 256>>>(edge_src, edge_dst);
  k_compact2<<<(N + 255) / 256, 256>>>();
  k_zero_rows<<<SP, 256>>>(1);
  k_self2<<<SP, 256>>>();
  k_edge_add2<<<SP, 256>>>(edge_src, edge_dst);
  k_mm<<<MM2, 256>>>(0, list2, cnt, 4, z2, dz, Wg + D * D, bg + D, h2, dh2);
  k_mm<<<MM2, 256>>>(0, list2, cnt, 4, h2, dh2, Wn, bn, hn, dhn);
  k_pool_delta<<<dim3(256, 2), 128>>>(batch);

  // ---- head ----
  k_out<<<NG, 32>>>(Wp, bp, out);
}

// round 6
// speedup vs baseline: 1.5079x; 1.0488x over previous
#include <cuda_runtime.h>
#include <stdint.h>

// ---------------- problem constants ----------------
constexpr int N  = 50000;
constexpr int E  = 800000;
constexpr int NG = 128;
constexpr int D  = 128;
constexpr int M  = 2;
constexpr int NT = 10;

typedef unsigned long long ull;

// ---------------- device scratch ----------------
__device__ float g_tx[N * D];
__device__ float g_z1[N * D];
__device__ float g_h1[N * D];
__device__ float g_z2[N * D];
__device__ float g_h2[N * D];
__device__ float g_hn[N * D];
__device__ float g_dz[M * N * D];
__device__ float g_dh1[M * N * D];
__device__ float g_dh2[M * N * D];
__device__ float g_dhn[M * N * D];
__device__ int   g_deg[N];
__device__ int   g_rowoff[N + 1];
__device__ int   g_cursor[N];
__device__ int   g_csrsrc[E];
__device__ int   g_gstart[NG + 1];
__device__ float g_pred[N];
__device__ float g_gmax[NG];
__device__ float g_gsum[NG];
__device__ int   g_anchor[M * NG];
__device__ float g_hg[M * NG * D];
__device__ unsigned char g_fA[M * N];
__device__ unsigned char g_f1[M * N];
__device__ unsigned char g_f2[M * N];
__device__ int   g_list1[M * N];
__device__ int   g_list2[M * N];
__device__ int   g_hitE[M * E];
__device__ int   g_cnt[8];  // [m]=cnt1, [2+m]=hit1, [4+m]=cnt2, [6+m]=hit2

// ---------------- f32x2 helpers ----------------
__device__ __forceinline__ ull ffma2(ull a, ull b, ull c) {
  ull d;
  asm("fma.rn.f32x2 %0, %1, %2, %3;" : "=l"(d) : "l"(a), "l"(b), "l"(c));
  return d;
}
__device__ __forceinline__ ull pack2dup(float x) {
  ull r;
  asm("mov.b64 %0, {%1, %1};" : "=l"(r) : "f"(x));
  return r;
}
__device__ __forceinline__ void unpack2(ull v, float& lo, float& hi) {
  asm("mov.b64 {%0, %1}, %2;" : "=f"(lo), "=f"(hi) : "l"(v));
}
__device__ __forceinline__ void cp16(void* smem, const void* gmem) {
  unsigned s = (unsigned)__cvta_generic_to_shared(smem);
  asm volatile("cp.async.cg.shared.global [%0], [%1], 16;" :: "r"(s), "l"(gmem));
}
__device__ __forceinline__ void cp_commit_wait() {
  asm volatile("cp.async.commit_group;");
  asm volatile("cp.async.wait_group 0;");
}

// ---------------- threefry2x32 (exact JAX) ----------------
__device__ __forceinline__ uint2 threefry2x32(unsigned k0, unsigned k1,
                                              unsigned x0, unsigned x1) {
  unsigned k2 = k0 ^ k1 ^ 0x1BD11BDAu;
  x0 += k0; x1 += k1;
#define TF_ROT(x, d) (((x) << (d)) | ((x) >> (32 - (d))))
#define TF_RND(r) { x0 += x1; x1 = TF_ROT(x1, r); x1 ^= x0; }
  TF_RND(13) TF_RND(15) TF_RND(26) TF_RND(6)
  x0 += k1; x1 += k2 + 1u;
  TF_RND(17) TF_RND(29) TF_RND(16) TF_RND(24)
  x0 += k2; x1 += k0 + 2u;
  TF_RND(13) TF_RND(15) TF_RND(26) TF_RND(6)
  x0 += k0; x1 += k1 + 3u;
  TF_RND(17) TF_RND(29) TF_RND(16) TF_RND(24)
  x0 += k1; x1 += k2 + 4u;
  TF_RND(13) TF_RND(15) TF_RND(26) TF_RND(6)
  x0 += k2; x1 += k0 + 5u;
#undef TF_RND
#undef TF_ROT
  return make_uint2(x0, x1);
}

// ---------------- base kernels ----------------
__global__ void k_zerodeg() {
  int n = blockIdx.x * blockDim.x + threadIdx.x;
  if (n < N) g_deg[n] = 0;
}

__global__ void k_embed(const int* __restrict__ x_idx,
                        const int* __restrict__ batch,
                        const float* __restrict__ x_table) {
  int n = blockIdx.x;
  int d = threadIdx.x;
  g_tx[n * D + d] = x_table[x_idx[n] * D + d];
  if (d == 0) {
    int b = batch[n];
    if (n == 0) {
      for (int g = 0; g <= b; ++g) g_gstart[g] = 0;
    } else {
      int pb = batch[n - 1];
      for (int g = pb + 1; g <= b; ++g) g_gstart[g] = n;
    }
    if (n == N - 1) {
      for (int g = b + 1; g <= NG; ++g) g_gstart[g] = N;
    }
  }
}

__global__ void k_hist(const int* __restrict__ edge_dst) {
  int e = blockIdx.x * blockDim.x + threadIdx.x;
  if (e < E) atomicAdd(&g_deg[edge_dst[e]], 1);
}

__global__ void k_scan() {
  __shared__ int sums[1024];
  int tid = threadIdx.x;
  const int CH = (N + 1023) / 1024;
  int beg = tid * CH;
  int end = min(beg + CH, N);
  int s = 0;
  for (int i = beg; i < end; ++i) s += g_deg[i];
  sums[tid] = s;
  __syncthreads();
  for (int off = 1; off < 1024; off <<= 1) {
    int v = (tid >= off) ? sums[tid - off] : 0;
    __syncthreads();
    sums[tid] += v;
    __syncthreads();
  }
  int pre = (tid == 0) ? 0 : sums[tid - 1];
  for (int i = beg; i < end; ++i) {
    g_rowoff[i] = pre;
    g_cursor[i] = pre;
    pre += g_deg[i];
  }
  if (tid == 1023) g_rowoff[N] = sums[1023];
}

__global__ void k_scatter(const int* __restrict__ edge_src,
                          const int* __restrict__ edge_dst) {
  int e = blockIdx.x * blockDim.x + threadIdx.x;
  if (e < E) {
    int d = edge_dst[e];
    int pos = atomicAdd(&g_cursor[d], 1);
    g_csrsrc[pos] = edge_src[e];
  }
}

// z[n,:] = h[n,:] + sum_{e: dst==n} h[src,:]   (one warp per node)
__global__ void __launch_bounds__(256) k_agg(const float* __restrict__ hin,
                                             float* __restrict__ zout) {
  int w = (blockIdx.x * blockDim.x + threadIdx.x) >> 5;
  int lane = threadIdx.x & 31;
  if (w >= N) return;
  int beg = g_rowoff[w], end = g_rowoff[w + 1];
  float4 acc = *reinterpret_cast<const float4*>(hin + (size_t)w * D + lane * 4);
  int k = beg;
  for (; k + 1 < end; k += 2) {
    int s0 = g_csrsrc[k];
    int s1 = g_csrsrc[k + 1];
    float4 v0 = *reinterpret_cast<const float4*>(hin + (size_t)s0 * D + lane * 4);
    float4 v1 = *reinterpret_cast<const float4*>(hin + (size_t)s1 * D + lane * 4);
    acc.x += v0.x + v1.x; acc.y += v0.y + v1.y;
    acc.z += v0.z + v1.z; acc.w += v0.w + v1.w;
  }
  if (k < end) {
    int s0 = g_csrsrc[k];
    float4 v0 = *reinterpret_cast<const float4*>(hin + (size_t)s0 * D + lane * 4);
    acc.x += v0.x; acc.y += v0.y; acc.z += v0.z; acc.w += v0.w;
  }
  *reinterpret_cast<float4*>(zout + (size_t)w * D + lane * 4) = acc;
}

// Unified 128x128-tile GEMM, 8x8 per thread, FFMA2, double-buffered,
// W via cp.async, Z register-staged. Optional fused pred head (dense mode).
__global__ void __launch_bounds__(256) k_mm(
    int Rdense,
    const int* __restrict__ listb, const int* __restrict__ cntp, int cntoff,
    const float* __restrict__ Zb, const float* __restrict__ Dzb,
    const float* __restrict__ W, const float* __restrict__ bias,
    const float* __restrict__ Sub, float* __restrict__ Outb,
    const float* __restrict__ WdP, const float* __restrict__ bdP,
    float* __restrict__ predOut) {
  const int m = blockIdx.y;
  const int cnt = listb ? cntp[cntoff + m] : Rdense;
  const int t0 = blockIdx.x * 128;
  if (t0 >= cnt) return;
  const int* list = listb ? (listb + m * N) : nullptr;
  const float* Dz = Dzb ? (Dzb + (size_t)m * N * D) : nullptr;
  float* Out = Outb + (listb ? (size_t)m * N * D : (size_t)0);

  __shared__ int lrow[128];
  __shared__ float Zs[2][16][136];
  __shared__ float Ws[2][16][132];

  const int tid = threadIdx.x;
  if (list) {
    if (tid < 128) lrow[tid] = (t0 + tid < cnt) ? list[t0 + tid] : -1;
    __syncthreads();
  }
  const int zr = tid >> 1;         // 0..127
  const int zk = (tid & 1) * 8;    // 0 or 8
  const int wk = tid >> 4;         // 0..15
  const int wj = (tid & 15) * 8;   // 0..120
  const int tr = tid >> 4;         // rows tr*8..+7
  const int tc = tid & 15;         // cols tc*8..+7
  const int zrow = list ? lrow[zr] : ((t0 + zr < cnt) ? (t0 + zr) : -1);

  ull acc[8][4];
#pragma unroll
  for (int i = 0; i < 8; ++i)
#pragma unroll
    for (int p = 0; p < 4; ++p) acc[i][p] = 0ull;

  // stage chunk 0: W via cp.async, Z via register transpose
  {
    cp16(&Ws[0][wk][wj], W + (size_t)wk * 128 + wj);
    cp16(&Ws[0][wk][wj + 4], W + (size_t)wk * 128 + wj + 4);
    float4 a0 = make_float4(0.f, 0.f, 0.f, 0.f), a1 = a0;
    if (zrow >= 0) {
      a0 = *reinterpret_cast<const float4*>(Zb + (size_t)zrow * 128 + zk);
      a1 = *reinterpret_cast<const float4*>(Zb + (size_t)zrow * 128 + zk + 4);
      if (Dz) {
        float4 d0 = *reinterpret_cast<const float4*>(Dz + (size_t)zrow * 128 + zk);
        float4 d1 = *reinterpret_cast<const float4*>(Dz + (size_t)zrow * 128 + zk + 4);
        a0.x += d0.x; a0.y += d0.y; a0.z += d0.z; a0.w += d0.w;
        a1.x += d1.x; a1.y += d1.y; a1.z += d1.z; a1.w += d1.w;
      }
    }
    Zs[0][zk + 0][zr] = a0.x; Zs[0][zk + 1][zr] = a0.y;
    Zs[0][zk + 2][zr] = a0.z; Zs[0][zk + 3][zr] = a0.w;
    Zs[0][zk + 4][zr] = a1.x; Zs[0][zk + 5][zr] = a1.y;
    Zs[0][zk + 6][zr] = a1.z; Zs[0][zk + 7][zr] = a1.w;
    cp_commit_wait();
  }
  __syncthreads();

  int buf = 0;
#pragma unroll 1
  for (int c = 0; c < 8; ++c) {
    const int nb = buf ^ 1;
    float4 na0, na1;
    if (c < 7) {
      int k0 = (c + 1) * 16;
      cp16(&Ws[nb][wk][wj], W + (size_t)(k0 + wk) * 128 + wj);
      cp16(&Ws[nb][wk][wj + 4], W + (size_t)(k0 + wk) * 128 + wj + 4);
      na0 = make_float4(0.f, 0.f, 0.f, 0.f); na1 = na0;
      if (zrow >= 0) {
        na0 = *reinterpret_cast<const float4*>(Zb + (size_t)zrow * 128 + k0 + zk);
        na1 = *reinterpret_cast<const float4*>(Zb + (size_t)zrow * 128 + k0 + zk + 4);
        if (Dz) {
          float4 d0 = *reinterpret_cast<const float4*>(Dz + (size_t)zrow * 128 + k0 + zk);
          float4 d1 = *reinterpret_cast<const float4*>(Dz + (size_t)zrow * 128 + k0 + zk + 4);
          na0.x += d0.x; na0.y += d0.y; na0.z += d0.z; na0.w += d0.w;
          na1.x += d1.x; na1.y += d1.y; na1.z += d1.z; na1.w += d1.w;
        }
      }
    }
#pragma unroll
    for (int kk = 0; kk < 16; ++kk) {
      float4 za = *reinterpret_cast<const float4*>(&Zs[buf][kk][tr * 8]);
      float4 zb2 = *reinterpret_cast<const float4*>(&Zs[buf][kk][tr * 8 + 4]);
      ull z0 = pack2dup(za.x), z1 = pack2dup(za.y);
      ull z2 = pack2dup(za.z), z3 = pack2dup(za.w);
      ull z4 = pack2dup(zb2.x), z5 = pack2dup(zb2.y);
      ull z6 = pack2dup(zb2.z), z7 = pack2dup(zb2.w);
      const ull* wp = reinterpret_cast<const ull*>(&Ws[buf][kk][tc * 8]);
      ull w0 = wp[0], w1 = wp[1], w2 = wp[2], w3 = wp[3];
      acc[0][0] = ffma2(z0, w0, acc[0][0]); acc[0][1] = ffma2(z0, w1, acc[0][1]);
      acc[0][2] = ffma2(z0, w2, acc[0][2]); acc[0][3] = ffma2(z0, w3, acc[0][3]);
      acc[1][0] = ffma2(z1, w0, acc[1][0]); acc[1][1] = ffma2(z1, w1, acc[1][1]);
      acc[1][2] = ffma2(z1, w2, acc[1][2]); acc[1][3] = ffma2(z1, w3, acc[1][3]);
      acc[2][0] = ffma2(z2, w0, acc[2][0]); acc[2][1] = ffma2(z2, w1, acc[2][1]);
      acc[2][2] = ffma2(z2, w2, acc[2][2]); acc[2][3] = ffma2(z2, w3, acc[2][3]);
      acc[3][0] = ffma2(z3, w0, acc[3][0]); acc[3][1] = ffma2(z3, w1, acc[3][1]);
      acc[3][2] = ffma2(z3, w2, acc[3][2]); acc[3][3] = ffma2(z3, w3, acc[3][3]);
      acc[4][0] = ffma2(z4, w0, acc[4][0]); acc[4][1] = ffma2(z4, w1, acc[4][1]);
      acc[4][2] = ffma2(z4, w2, acc[4][2]); acc[4][3] = ffma2(z4, w3, acc[4][3]);
      acc[5][0] = ffma2(z5, w0, acc[5][0]); acc[5][1] = ffma2(z5, w1, acc[5][1]);
      acc[5][2] = ffma2(z5, w2, acc[5][2]); acc[5][3] = ffma2(z5, w3, acc[5][3]);
      acc[6][0] = ffma2(z6, w0, acc[6][0]); acc[6][1] = ffma2(z6, w1, acc[6][1]);
      acc[6][2] = ffma2(z6, w2, acc[6][2]); acc[6][3] = ffma2(z6, w3, acc[6][3]);
      acc[7][0] = ffma2(z7, w0, acc[7][0]); acc[7][1] = ffma2(z7, w1, acc[7][1]);
      acc[7][2] = ffma2(z7, w2, acc[7][2]); acc[7][3] = ffma2(z7, w3, acc[7][3]);
    }
    if (c < 7) {
      Zs[nb][zk + 0][zr] = na0.x; Zs[nb][zk + 1][zr] = na0.y;
      Zs[nb][zk + 2][zr] = na0.z; Zs[nb][zk + 3][zr] = na0.w;
      Zs[nb][zk + 4][zr] = na1.x; Zs[nb][zk + 5][zr] = na1.y;
      Zs[nb][zk + 6][zr] = na1.z; Zs[nb][zk + 7][zr] = na1.w;
      cp_commit_wait();
      __syncthreads();
      buf = nb;
    }
  }

  float4 b0 = *reinterpret_cast<const float4*>(bias + tc * 8);
  float4 b1 = *reinterpret_cast<const float4*>(bias + tc * 8 + 4);
  float bb[8] = {b0.x, b0.y, b0.z, b0.w, b1.x, b1.y, b1.z, b1.w};
  float wd[8] = {0, 0, 0, 0, 0, 0, 0, 0};
  if (predOut) {
    float4 wd0 = *reinterpret_cast<const float4*>(WdP + tc * 8);
    float4 wd1 = *reinterpret_cast<const float4*>(WdP + tc * 8 + 4);
    wd[0] = wd0.x; wd[1] = wd0.y; wd[2] = wd0.z; wd[3] = wd0.w;
    wd[4] = wd1.x; wd[5] = wd1.y; wd[6] = wd1.z; wd[7] = wd1.w;
  }
#pragma unroll
  for (int i = 0; i < 8; ++i) {
    int row = list ? lrow[tr * 8 + i]
                   : ((t0 + tr * 8 + i < cnt) ? (t0 + tr * 8 + i) : -1);
    float o[8];
#pragma unroll
    for (int p = 0; p < 4; ++p) {
      float lo, hi;
      unpack2(acc[i][p], lo, hi);
      o[2 * p] = fmaxf(lo + bb[2 * p], 0.f);
      o[2 * p + 1] = fmaxf(hi + bb[2 * p + 1], 0.f);
    }
    if (predOut) {
      float p = o[0] * wd[0] + o[1] * wd[1] + o[2] * wd[2] + o[3] * wd[3] +
                o[4] * wd[4] + o[5] * wd[5] + o[6] * wd[6] + o[7] * wd[7];
#pragma unroll
      for (int off = 8; off; off >>= 1) p += __shfl_xor_sync(0xffffffffu, p, off);
      if (tc == 0 && row >= 0) predOut[row] = p + bdP[0];
    }
    if (row >= 0) {
      if (Sub) {
        float4 s0 = *reinterpret_cast<const float4*>(Sub + (size_t)row * 128 + tc * 8);
        float4 s1 = *reinterpret_cast<const float4*>(Sub + (size_t)row * 128 + tc * 8 + 4);
        o[0] -= s0.x; o[1] -= s0.y; o[2] -= s0.z; o[3] -= s0.w;
        o[4] -= s1.x; o[5] -= s1.y; o[6] -= s1.z; o[7] -= s1.w;
      }
      *reinterpret_cast<float4*>(Out + (size_t)row * 128 + tc * 8) =
          make_float4(o[0], o[1], o[2], o[3]);
      *reinterpret_cast<float4*>(Out + (size_t)row * 128 + tc * 8 + 4) =
          make_float4(o[4], o[5], o[6], o[7]);
    }
  }
}

// ---------------- sampling path ----------------
__global__ void k_gstats() {
  int g = blockIdx.x;
  int tid = threadIdx.x;
  int beg = g_gstart[g], end = g_gstart[g + 1];
  __shared__ float red[256];
  float mx = -3.4e38f;
  for (int n = beg + tid; n < end; n += 256) mx = fmaxf(mx, g_pred[n]);
  red[tid] = mx;
  __syncthreads();
  for (int off = 128; off; off >>= 1) {
    if (tid < off) red[tid] = fmaxf(red[tid], red[tid + off]);
    __syncthreads();
  }
  float mxv = red[0];
  __syncthreads();
  float s = 0.f;
  for (int n = beg + tid; n < end; n += 256) s += expf(g_pred[n] - mxv);
  red[tid] = s;
  __syncthreads();
  for (int off = 128; off; off >>= 1) {
    if (tid < off) red[tid] += red[tid + off];
    __syncthreads();
  }
  if (tid == 0) {
    bool ok = beg < end;
    g_gmax[g] = ok ? mxv : 0.f;
    g_gsum[g] = ok ? red[0] : 1.f;
  }
}

__global__ void k_sample() {
  int b = blockIdx.x;
  int m = b >> 7;
  int g = b & 127;
  int tid = threadIdx.x;
  int beg = g_gstart[g], end = g_gstart[g + 1];
  if (beg >= end) {
    if (tid == 0) g_anchor[b] = -1;
    return;
  }
  uint2 dk = threefry2x32(0u, 1u, 0u, 1u);
  float mxv = g_gmax[g];
  float sv = g_gsum[g];
  float best = -3.4e38f;
  int bid = 0x7fffffff;
  for (int n = beg + tid; n < end; n += 128) {
    float prob = expf(g_pred[n] - mxv) / sv;
    float lp = logf(prob + 1e-15f);
    uint2 r = threefry2x32(dk.x, dk.y, (unsigned)n, (unsigned)(N + n));
    unsigned bits = (m == 0) ? r.x : r.y;
    float u = __uint_as_float((bits >> 9) | 0x3f800000u) - 1.0f;
    float gum = -logf(-logf(u + 1e-12f) + 1e-12f);
    float sc = lp + gum;
    if (sc > best || (sc == best && n < bid)) { best = sc; bid = n; }
  }
  __shared__ float rs[128];
  __shared__ int ri[128];
  rs[tid] = best; ri[tid] = bid;
  __syncthreads();
  for (int off = 64; off; off >>= 1) {
    if (tid < off) {
      if (rs[tid + off] > rs[tid] ||
          (rs[tid + off] == rs[tid] && ri[tid + off] < ri[tid])) {
        rs[tid] = rs[tid + off];
        ri[tid] = ri[tid + off];
      }
    }
    __syncthreads();
  }
  if (tid == 0) g_anchor[b] = ri[0];
}

// ---------------- pass-2 sparse machinery ----------------
__global__ void k_mclear() {
  int n = blockIdx.x * blockDim.x + threadIdx.x;
  if (n < N) {
    g_fA[n] = 0; g_fA[N + n] = 0;
    g_f1[n] = 0; g_f1[N + n] = 0;
    g_f2[n] = 0; g_f2[N + n] = 0;
  }
  if (n < 8) g_cnt[n] = 0;
}

__global__ void k_mark_anchor() {
  int t = blockIdx.x * blockDim.x + threadIdx.x;
  if (t < M * NG) {
    int a = g_anchor[t];
    int m = t >> 7;
    if (a >= 0) { g_fA[m * N + a] = 1; g_f1[m * N + a] = 1; }
  }
}

__global__ void k_mark_edges1(const int* __restrict__ es, const int* __restrict__ ed) {
  int e = blockIdx.x * blockDim.x + threadIdx.x;
  if (e >= E) return;
  int s = es[e], dd = ed[e];
#pragma unroll
  for (int m = 0; m < M; ++m) {
    if (g_fA[m * N + s]) {
      g_f1[m * N + dd] = 1;
      int p = atomicAdd(&g_cnt[2 + m], 1);
      g_hitE[m * E + p] = e;
    }
  }
}

__global__ void k_compact1() {
  int n = blockIdx.x * blockDim.x + threadIdx.x;
  if (n >= N) return;
#pragma unroll
  for (int m = 0; m < M; ++m) {
    if (g_f1[m * N + n]) {
      int p = atomicAdd(&g_cnt[m], 1);
      g_list1[m * N + p] = n;
    }
  }
}

__global__ void k_mark_edges2(const int* __restrict__ es, const int* __restrict__ ed) {
  int e = blockIdx.x * blockDim.x + threadIdx.x;
  if (e >= E) return;
  int s = es[e], dd = ed[e];
#pragma unroll
  for (int m = 0; m < M; ++m) {
    if (g_f1[m * N + s]) {
      g_f2[m * N + dd] = 1;
      int p = atomicAdd(&g_cnt[6 + m], 1);
      g_hitE[m * E + p] = e;
    }
  }
}

__global__ void k_compact2() {
  int n = blockIdx.x * blockDim.x + threadIdx.x;
  if (n >= N) return;
#pragma unroll
  for (int m = 0; m < M; ++m) {
    if (g_f1[m * N + n] || g_f2[m * N + n]) {
      int p = atomicAdd(&g_cnt[4 + m], 1);
      g_list2[m * N + p] = n;
    }
  }
}

__global__ void k_zero_rows(int which) {
  int m = blockIdx.y;
  const int* list = (which ? g_list2 : g_list1) + m * N;
  int cnt = g_cnt[(which ? 4 : 0) + m];
  int w = blockIdx.x * 8 + (threadIdx.x >> 5);
  int lane = threadIdx.x & 31;
  float* dz = g_dz + (size_t)m * N * D;
  for (int i = w; i < cnt; i += 256 * 8) {
    int row = list[i];
    *reinterpret_cast<float4*>(dz + (size_t)row * D + lane * 4) =
        make_float4(0.f, 0.f, 0.f, 0.f);
  }
}

__global__ void k_self1(const float* __restrict__ at) {
  int m = blockIdx.y;
  int g = blockIdx.x;
  int a = g_anchor[m * NG + g];
  if (a < 0) return;
  int lane = threadIdx.x;
  float4 t = *reinterpret_cast<const float4*>(g_tx + (size_t)a * D + lane * 4);
  float4 f = *reinterpret_cast<const float4*>(at + D + lane * 4);
  *reinterpret_cast<float4*>(g_dz + ((size_t)m * N + a) * D + lane * 4) =
      make_float4(t.x * f.x, t.y * f.y, t.z * f.z, t.w * f.w);
}

__global__ void k_edge_add1(const int* __restrict__ es, const int* __restrict__ ed,
                            const float* __restrict__ at) {
  int m = blockIdx.y;
  int cnt = g_cnt[2 + m];
  int w = blockIdx.x * 8 + (threadIdx.x >> 5);
  int lane = threadIdx.x & 31;
  float4 f = *reinterpret_cast<const float4*>(at + D + lane * 4);
  float* dz = g_dz + (size_t)m * N * D;
  for (int i = w; i < cnt; i += 256 * 8) {
    int e = g_hitE[m * E + i];
    int s = es[e], dd = ed[e];
    float4 t = *reinterpret_cast<const float4*>(g_tx + (size_t)s * D + lane * 4);
    float* p = dz + (size_t)dd * D + lane * 4;
    atomicAdd(p + 0, t.x * f.x);
    atomicAdd(p + 1, t.y * f.y);
    atomicAdd(p + 2, t.z * f.z);
    atomicAdd(p + 3, t.w * f.w);
  }
}

__global__ void k_self2() {
  int m = blockIdx.y;
  int cnt = g_cnt[m];
  int w = blockIdx.x * 8 + (threadIdx.x >> 5);
  int lane = threadIdx.x & 31;
  const float* dh1 = g_dh1 + (size_t)m * N * D;
  float* dz = g_dz + (size_t)m * N * D;
  for (int i = w; i < cnt; i += 256 * 8) {
    int row = g_list1[m * N + i];
    float4 v = *reinterpret_cast<const float4*>(dh1 + (size_t)row * D + lane * 4);
    *reinterpret_cast<float4*>(dz + (size_t)row * D + lane * 4) = v;
  }
}

__global__ void k_edge_add2(const int* __restrict__ es, const int* __restrict__ ed) {
  int m = blockIdx.y;
  int cnt = g_cnt[6 + m];
  int w = blockIdx.x * 8 + (threadIdx.x >> 5);
  int lane = threadIdx.x & 31;
  const float* dh1 = g_dh1 + (size_t)m * N * D;
  float* dz = g_dz + (size_t)m * N * D;
  for (int i = w; i < cnt; i += 256 * 8) {
    int e = g_hitE[m * E + i];
    int s = es[e], dd = ed[e];
    float4 v = *reinterpret_cast<const float4*>(dh1 + (size_t)s * D + lane * 4);
    float* p = dz + (size_t)dd * D + lane * 4;
    atomicAdd(p + 0, v.x);
    atomicAdd(p + 1, v.y);
    atomicAdd(p + 2, v.z);
    atomicAdd(p + 3, v.w);
  }
}

// base mean pool over all nodes -> write both m copies of g_hg
__global__ void k_poolb() {
  int g = blockIdx.x;
  int tid = threadIdx.x;
  int d = tid & 127;
  int half = tid >> 7;
  int beg = g_gstart[g], end = g_gstart[g + 1];
  float acc = 0.f;
  for (int n = beg + half; n < end; n += 2) acc += g_hn[(size_t)n * D + d];
  __shared__ float s[128];
  if (half == 1) s[d] = acc;
  __syncthreads();
  if (half == 0) {
    float tot = acc + s[d];
    int c = end - beg;
    float v = tot / (float)max(c, 1);
    g_hg[(0 * NG + g) * D + d] = v;
    g_hg[(1 * NG + g) * D + d] = v;
  }
}

__global__ void k_pool_delta(const int* __restrict__ batch) {
  int m = blockIdx.y;
  int cnt = g_cnt[4 + m];
  int d = threadIdx.x;
  const float* dhn = g_dhn + (size_t)m * N * D;
  for (int i = blockIdx.x; i < cnt; i += gridDim.x) {
    int n = g_list2[m * N + i];
    int g = batch[n];
    int c = g_gstart[g + 1] - g_gstart[g];
    float inv = 1.0f / (float)max(c, 1);
    atomicAdd(&g_hg[(m * NG + g) * D + d], dhn[(size_t)n * D + d] * inv);
  }
}

__global__ void k_out(const float* __restrict__ Wp, const float* __restrict__ bp,
                      float* __restrict__ out) {
  int g = blockIdx.x;
  int t = threadIdx.x;
  if (t >= NT) return;
  float acc = 0.f;
  for (int m = 0; m < M; ++m) {
    const float* hg = &g_hg[(m * NG + g) * D];
    float s = 0.f;
#pragma unroll 16
    for (int k = 0; k < D; ++k) s += hg[k] * Wp[k * NT + t];
    acc += s;
  }
  out[g * NT + t] = acc * (1.0f / M) + bp[t];
}

// ---------------- launch ----------------
extern "C" void kernel_launch(void* const* d_in, const int* in_sizes, int n_in,
                              void* d_out, int out_size) {
  const int*   x_idx    = (const int*)d_in[0];
  const int*   edge_src = (const int*)d_in[1];
  const int*   edge_dst = (const int*)d_in[2];
  const int*   batch    = (const int*)d_in[3];
  const float* x_table  = (const float*)d_in[4];
  const float* anchor_t = (const float*)d_in[5];
  const float* Wg       = (const float*)d_in[6];
  const float* bg       = (const float*)d_in[7];
  const float* Wn       = (const float*)d_in[8];
  const float* bn       = (const float*)d_in[9];
  const float* Wd       = (const float*)d_in[10];
  const float* bd       = (const float*)d_in[11];
  const float* Wp       = (const float*)d_in[12];
  const float* bp       = (const float*)d_in[13];
  float* out = (float*)d_out;

  float *txp, *z1, *h1, *z2, *h2, *hn, *dz, *dh1, *dh2, *dhn, *predp;
  int *list1, *list2, *cnt;
  cudaGetSymbolAddress((void**)&txp, g_tx);
  cudaGetSymbolAddress((void**)&z1, g_z1);
  cudaGetSymbolAddress((void**)&h1, g_h1);
  cudaGetSymbolAddress((void**)&z2, g_z2);
  cudaGetSymbolAddress((void**)&h2, g_h2);
  cudaGetSymbolAddress((void**)&hn, g_hn);
  cudaGetSymbolAddress((void**)&dz, g_dz);
  cudaGetSymbolAddress((void**)&dh1, g_dh1);
  cudaGetSymbolAddress((void**)&dh2, g_dh2);
  cudaGetSymbolAddress((void**)&dhn, g_dhn);
  cudaGetSymbolAddress((void**)&predp, g_pred);
  cudaGetSymbolAddress((void**)&list1, g_list1);
  cudaGetSymbolAddress((void**)&list2, g_list2);
  cudaGetSymbolAddress((void**)&cnt, g_cnt);

  // lazily-created side stream + events (never destroyed; capture-safe)
  static cudaStream_t s1 = nullptr;
  static cudaEvent_t evFork = nullptr, evA = nullptr, evH2 = nullptr, evPool = nullptr;
  if (!s1) {
    cudaStreamCreateWithFlags(&s1, cudaStreamNonBlocking);
    cudaEventCreateWithFlags(&evFork, cudaEventDisableTiming);
    cudaEventCreateWithFlags(&evA, cudaEventDisableTiming);
    cudaEventCreateWithFlags(&evH2, cudaEventDisableTiming);
    cudaEventCreateWithFlags(&evPool, cudaEventDisableTiming);
  }
  cudaStream_t s0 = 0;

  const int AGG_GRID = (N * 32 + 255) / 256;
  const int MMG = (N + 127) / 128;       // 391
  const dim3 MM1(MMG, 1);
  const dim3 MM2(MMG, 2);
  const dim3 SP(256, 2);

  // ---- fork: embed + flag clear on s1, CSR build on s0 ----
  cudaEventRecord(evFork, s0);
  cudaStreamWaitEvent(s1, evFork, 0);
  k_embed<<<N, D, 0, s1>>>(x_idx, batch, x_table);
  k_mclear<<<(N + 255) / 256, 256, 0, s1>>>();
  cudaEventRecord(evA, s1);

  k_zerodeg<<<(N + 255) / 256, 256, 0, s0>>>();
  k_hist<<<(E + 255) / 256, 256, 0, s0>>>(edge_dst);
  k_scan<<<1, 1024, 0, s0>>>();
  k_scatter<<<(E + 255) / 256, 256, 0, s0>>>(edge_src, edge_dst);
  cudaStreamWaitEvent(s0, evA, 0);

  // ---- pass 1 (base) on s0; h2 GEMM fuses the pred head ----
  k_agg<<<AGG_GRID, 256, 0, s0>>>(txp, z1);
  k_mm<<<MM1, 256, 0, s0>>>(N, nullptr, nullptr, 0, z1, nullptr, Wg, bg, nullptr, h1,
                            nullptr, nullptr, nullptr);
  k_agg<<<AGG_GRID, 256, 0, s0>>>(h1, z2);
  k_mm<<<MM1, 256, 0, s0>>>(N, nullptr, nullptr, 0, z2, nullptr, Wg + D * D, bg + D,
                            nullptr, h2, Wd, bd, predp);
  cudaEventRecord(evH2, s0);

  // ---- s1: base node MLP + base pool (overlaps sampling + layer-1 deltas) ----
  cudaStreamWaitEvent(s1, evH2, 0);
  k_mm<<<MM1, 256, 0, s1>>>(N, nullptr, nullptr, 0, h2, nullptr, Wn, bn, nullptr, hn,
                            nullptr, nullptr, nullptr);
  k_poolb<<<NG, 256, 0, s1>>>();
  cudaEventRecord(evPool, s1);

  // ---- s0: sampling + sparse deltas ----
  k_gstats<<<NG, 256, 0, s0>>>();
  k_sample<<<M * NG, 128, 0, s0>>>();
  k_mark_anchor<<<1, M * NG, 0, s0>>>();
  k_mark_edges1<<<(E + 255) / 256, 256, 0, s0>>>(edge_src, edge_dst);
  k_compact1<<<(N + 255) / 256, 256, 0, s0>>>();
  k_zero_rows<<<SP, 256, 0, s0>>>(0);
  k_self1<<<dim3(NG, 2), 32, 0, s0>>>(anchor_t);
  k_edge_add1<<<SP, 256, 0, s0>>>(edge_src, edge_dst, anchor_t);
  k_mm<<<MM2, 256, 0, s0>>>(0, list1, cnt, 0, z1, dz, Wg, bg, h1, dh1,
                            nullptr, nullptr, nullptr);
  k_mark_edges2<<<(E + 255) / 256, 256, 0, s0>>>(edge_src, edge_dst);
  k_compact2<<<(N + 255) / 256, 256, 0, s0>>>();
  k_zero_rows<<<SP, 256, 0, s0>>>(1);
  k_self2<<<SP, 256, 0, s0>>>();
  k_edge_add2<<<SP, 256, 0, s0>>>(edge_src, edge_dst);
  k_mm<<<MM2, 256, 0, s0>>>(0, list2, cnt, 4, z2, dz, Wg + D * D, bg + D, h2, dh2,
                            nullptr, nullptr, nullptr);
  cudaStreamWaitEvent(s0, evPool, 0);
  k_mm<<<MM2, 256, 0, s0>>>(0, list2, cnt, 4, h2, dh2, Wn, bn, hn, dhn,
                            nullptr, nullptr, nullptr);
  k_pool_delta<<<dim3(256, 2), 128, 0, s0>>>(batch);

  // ---- head ----
  k_out<<<NG, 32, 0, s0>>>(Wp, bp, out);
}

// round 8
// speedup vs baseline: 1.5371x; 1.0193x over previous
#include <cuda_runtime.h>
#include <stdint.h>

// ---------------- problem constants ----------------
constexpr int N  = 50000;
constexpr int E  = 800000;
constexpr int NG = 128;
constexpr int D  = 128;
constexpr int M  = 2;
constexpr int NT = 10;

typedef unsigned long long ull;

// ---------------- device scratch ----------------
__device__ float g_tx[N * D];
__device__ float g_z1[N * D];
__device__ float g_h1[N * D];
__device__ float g_z2[N * D];
__device__ float g_h2[N * D];
__device__ float g_hn[N * D];
__device__ float g_dz[M * N * D];
__device__ float g_dh1[M * N * D];
__device__ float g_dh2[M * N * D];
__device__ float g_dhn[M * N * D];
__device__ int   g_deg[N];
__device__ int   g_rowoff[N + 1];
__device__ int   g_cursor[N];
__device__ int   g_csrsrc[E];
__device__ int   g_gstart[NG + 1];
__device__ float g_pred[N];
__device__ float g_gmax[NG];
__device__ float g_gsum[NG];
__device__ int   g_anchor[M * NG];
__device__ float g_hg[M * NG * D];
__device__ unsigned char g_fA[M * N];
__device__ unsigned char g_f1[M * N];
__device__ unsigned char g_f2[M * N];
__device__ int   g_list1[M * N];
__device__ int   g_list2[M * N];
__device__ int   g_cnt[8];  // [m]=cnt1, [4+m]=cnt2

// ---------------- f32x2 helpers ----------------
__device__ __forceinline__ ull ffma2(ull a, ull b, ull c) {
  ull d;
  asm("fma.rn.f32x2 %0, %1, %2, %3;" : "=l"(d) : "l"(a), "l"(b), "l"(c));
  return d;
}
__device__ __forceinline__ ull pack2dup(float x) {
  ull r;
  asm("mov.b64 %0, {%1, %1};" : "=l"(r) : "f"(x));
  return r;
}
__device__ __forceinline__ void unpack2(ull v, float& lo, float& hi) {
  asm("mov.b64 {%0, %1}, %2;" : "=f"(lo), "=f"(hi) : "l"(v));
}
__device__ __forceinline__ void cp16(void* smem, const void* gmem) {
  unsigned s = (unsigned)__cvta_generic_to_shared(smem);
  asm volatile("cp.async.cg.shared.global [%0], [%1], 16;" :: "r"(s), "l"(gmem));
}
__device__ __forceinline__ void cp_commit_wait() {
  asm volatile("cp.async.commit_group;");
  asm volatile("cp.async.wait_group 0;");
}

// ---------------- threefry2x32 (exact JAX) ----------------
__device__ __forceinline__ uint2 threefry2x32(unsigned k0, unsigned k1,
                                              unsigned x0, unsigned x1) {
  unsigned k2 = k0 ^ k1 ^ 0x1BD11BDAu;
  x0 += k0; x1 += k1;
#define TF_ROT(x, d) (((x) << (d)) | ((x) >> (32 - (d))))
#define TF_RND(r) { x0 += x1; x1 = TF_ROT(x1, r); x1 ^= x0; }
  TF_RND(13) TF_RND(15) TF_RND(26) TF_RND(6)
  x0 += k1; x1 += k2 + 1u;
  TF_RND(17) TF_RND(29) TF_RND(16) TF_RND(24)
  x0 += k2; x1 += k0 + 2u;
  TF_RND(13) TF_RND(15) TF_RND(26) TF_RND(6)
  x0 += k0; x1 += k1 + 3u;
  TF_RND(17) TF_RND(29) TF_RND(16) TF_RND(24)
  x0 += k1; x1 += k2 + 4u;
  TF_RND(13) TF_RND(15) TF_RND(26) TF_RND(6)
  x0 += k2; x1 += k0 + 5u;
#undef TF_RND
#undef TF_ROT
  return make_uint2(x0, x1);
}

// ---------------- base kernels ----------------
__global__ void k_zerodeg() {
  int n = blockIdx.x * blockDim.x + threadIdx.x;
  if (n < N) g_deg[n] = 0;
}

// clear flags + counters (runs on side stream)
__global__ void k_mclear() {
  int n = blockIdx.x * blockDim.x + threadIdx.x;
  if (n < N) {
    g_fA[n] = 0; g_fA[N + n] = 0;
    g_f1[n] = 0; g_f1[N + n] = 0;
    g_f2[n] = 0; g_f2[N + n] = 0;
  }
  if (n < 8) g_cnt[n] = 0;
}

__global__ void k_embed(const int* __restrict__ x_idx,
                        const int* __restrict__ batch,
                        const float* __restrict__ x_table) {
  int n = blockIdx.x;
  int d = threadIdx.x;
  g_tx[n * D + d] = x_table[x_idx[n] * D + d];
  if (d == 0) {
    int b = batch[n];
    if (n == 0) {
      for (int g = 0; g <= b; ++g) g_gstart[g] = 0;
    } else {
      int pb = batch[n - 1];
      for (int g = pb + 1; g <= b; ++g) g_gstart[g] = n;
    }
    if (n == N - 1) {
      for (int g = b + 1; g <= NG; ++g) g_gstart[g] = N;
    }
  }
}

__global__ void k_hist(const int* __restrict__ edge_dst) {
  int e = blockIdx.x * blockDim.x + threadIdx.x;
  if (e < E) atomicAdd(&g_deg[edge_dst[e]], 1);
}

__global__ void k_scan() {
  __shared__ int sums[1024];
  int tid = threadIdx.x;
  const int CH = (N + 1023) / 1024;
  int beg = tid * CH;
  int end = min(beg + CH, N);
  int s = 0;
  for (int i = beg; i < end; ++i) s += g_deg[i];
  sums[tid] = s;
  __syncthreads();
  for (int off = 1; off < 1024; off <<= 1) {
    int v = (tid >= off) ? sums[tid - off] : 0;
    __syncthreads();
    sums[tid] += v;
    __syncthreads();
  }
  int pre = (tid == 0) ? 0 : sums[tid - 1];
  for (int i = beg; i < end; ++i) {
    g_rowoff[i] = pre;
    g_cursor[i] = pre;
    pre += g_deg[i];
  }
  if (tid == 1023) g_rowoff[N] = sums[1023];
}

__global__ void k_scatter(const int* __restrict__ edge_src,
                          const int* __restrict__ edge_dst) {
  int e = blockIdx.x * blockDim.x + threadIdx.x;
  if (e < E) {
    int d = edge_dst[e];
    int pos = atomicAdd(&g_cursor[d], 1);
    g_csrsrc[pos] = edge_src[e];
  }
}

// z[n,:] = h[n,:] + sum_{e: dst==n} h[src,:]   (one warp per node)
__global__ void __launch_bounds__(256) k_agg(const float* __restrict__ hin,
                                             float* __restrict__ zout) {
  int w = (blockIdx.x * blockDim.x + threadIdx.x) >> 5;
  int lane = threadIdx.x & 31;
  if (w >= N) return;
  int beg = g_rowoff[w], end = g_rowoff[w + 1];
  float4 acc = *reinterpret_cast<const float4*>(hin + (size_t)w * D + lane * 4);
  int k = beg;
  for (; k + 1 < end; k += 2) {
    int s0 = g_csrsrc[k];
    int s1 = g_csrsrc[k + 1];
    float4 v0 = *reinterpret_cast<const float4*>(hin + (size_t)s0 * D + lane * 4);
    float4 v1 = *reinterpret_cast<const float4*>(hin + (size_t)s1 * D + lane * 4);
    acc.x += v0.x + v1.x; acc.y += v0.y + v1.y;
    acc.z += v0.z + v1.z; acc.w += v0.w + v1.w;
  }
  if (k < end) {
    int s0 = g_csrsrc[k];
    float4 v0 = *reinterpret_cast<const float4*>(hin + (size_t)s0 * D + lane * 4);
    acc.x += v0.x; acc.y += v0.y; acc.z += v0.z; acc.w += v0.w;
  }
  *reinterpret_cast<float4*>(zout + (size_t)w * D + lane * 4) = acc;
}

// Unified 128x128-tile GEMM, 8x8 per thread, FFMA2, double-buffered,
// W via cp.async, Z register-staged. Optional fused pred head (dense mode).
__global__ void __launch_bounds__(256) k_mm(
    int Rdense,
    const int* __restrict__ listb, const int* __restrict__ cntp, int cntoff,
    const float* __restrict__ Zb, const float* __restrict__ Dzb,
    const float* __restrict__ W, const float* __restrict__ bias,
    const float* __restrict__ Sub, float* __restrict__ Outb,
    const float* __restrict__ WdP, const float* __restrict__ bdP,
    float* __restrict__ predOut) {
  const int m = blockIdx.y;
  const int cnt = listb ? cntp[cntoff + m] : Rdense;
  const int t0 = blockIdx.x * 128;
  if (t0 >= cnt) return;
  const int* list = listb ? (listb + m * N) : nullptr;
  const float* Dz = Dzb ? (Dzb + (size_t)m * N * D) : nullptr;
  float* Out = Outb + (listb ? (size_t)m * N * D : (size_t)0);

  __shared__ int lrow[128];
  __shared__ float Zs[2][16][136];
  __shared__ float Ws[2][16][132];

  const int tid = threadIdx.x;
  if (list) {
    if (tid < 128) lrow[tid] = (t0 + tid < cnt) ? list[t0 + tid] : -1;
    __syncthreads();
  }
  const int zr = tid >> 1;         // 0..127
  const int zk = (tid & 1) * 8;    // 0 or 8
  const int wk = tid >> 4;         // 0..15
  const int wj = (tid & 15) * 8;   // 0..120
  const int tr = tid >> 4;         // rows tr*8..+7
  const int tc = tid & 15;         // cols tc*8..+7
  const int zrow = list ? lrow[zr] : ((t0 + zr < cnt) ? (t0 + zr) : -1);

  ull acc[8][4];
#pragma unroll
  for (int i = 0; i < 8; ++i)
#pragma unroll
    for (int p = 0; p < 4; ++p) acc[i][p] = 0ull;

  // stage chunk 0: W via cp.async, Z via register transpose
  {
    cp16(&Ws[0][wk][wj], W + (size_t)wk * 128 + wj);
    cp16(&Ws[0][wk][wj + 4], W + (size_t)wk * 128 + wj + 4);
    float4 a0 = make_float4(0.f, 0.f, 0.f, 0.f), a1 = a0;
    if (zrow >= 0) {
      a0 = *reinterpret_cast<const float4*>(Zb + (size_t)zrow * 128 + zk);
      a1 = *reinterpret_cast<const float4*>(Zb + (size_t)zrow * 128 + zk + 4);
      if (Dz) {
        float4 d0 = *reinterpret_cast<const float4*>(Dz + (size_t)zrow * 128 + zk);
        float4 d1 = *reinterpret_cast<const float4*>(Dz + (size_t)zrow * 128 + zk + 4);
        a0.x += d0.x; a0.y += d0.y; a0.z += d0.z; a0.w += d0.w;
        a1.x += d1.x; a1.y += d1.y; a1.z += d1.z; a1.w += d1.w;
      }
    }
    Zs[0][zk + 0][zr] = a0.x; Zs[0][zk + 1][zr] = a0.y;
    Zs[0][zk + 2][zr] = a0.z; Zs[0][zk + 3][zr] = a0.w;
    Zs[0][zk + 4][zr] = a1.x; Zs[0][zk + 5][zr] = a1.y;
    Zs[0][zk + 6][zr] = a1.z; Zs[0][zk + 7][zr] = a1.w;
    cp_commit_wait();
  }
  __syncthreads();

  int buf = 0;
#pragma unroll 1
  for (int c = 0; c < 8; ++c) {
    const int nb = buf ^ 1;
    float4 na0, na1;
    if (c < 7) {
      int k0 = (c + 1) * 16;
      cp16(&Ws[nb][wk][wj], W + (size_t)(k0 + wk) * 128 + wj);
      cp16(&Ws[nb][wk][wj + 4], W + (size_t)(k0 + wk) * 128 + wj + 4);
      na0 = make_float4(0.f, 0.f, 0.f, 0.f); na1 = na0;
      if (zrow >= 0) {
        na0 = *reinterpret_cast<const float4*>(Zb + (size_t)zrow * 128 + k0 + zk);
        na1 = *reinterpret_cast<const float4*>(Zb + (size_t)zrow * 128 + k0 + zk + 4);
        if (Dz) {
          float4 d0 = *reinterpret_cast<const float4*>(Dz + (size_t)zrow * 128 + k0 + zk);
          float4 d1 = *reinterpret_cast<const float4*>(Dz + (size_t)zrow * 128 + k0 + zk + 4);
          na0.x += d0.x; na0.y += d0.y; na0.z += d0.z; na0.w += d0.w;
          na1.x += d1.x; na1.y += d1.y; na1.z += d1.z; na1.w += d1.w;
        }
      }
    }
#pragma unroll
    for (int kk = 0; kk < 16; ++kk) {
      float4 za = *reinterpret_cast<const float4*>(&Zs[buf][kk][tr * 8]);
      float4 zb2 = *reinterpret_cast<const float4*>(&Zs[buf][kk][tr * 8 + 4]);
      ull z0 = pack2dup(za.x), z1 = pack2dup(za.y);
      ull z2 = pack2dup(za.z), z3 = pack2dup(za.w);
      ull z4 = pack2dup(zb2.x), z5 = pack2dup(zb2.y);
      ull z6 = pack2dup(zb2.z), z7 = pack2dup(zb2.w);
      const ull* wp = reinterpret_cast<const ull*>(&Ws[buf][kk][tc * 8]);
      ull w0 = wp[0], w1 = wp[1], w2 = wp[2], w3 = wp[3];
      acc[0][0] = ffma2(z0, w0, acc[0][0]); acc[0][1] = ffma2(z0, w1, acc[0][1]);
      acc[0][2] = ffma2(z0, w2, acc[0][2]); acc[0][3] = ffma2(z0, w3, acc[0][3]);
      acc[1][0] = ffma2(z1, w0, acc[1][0]); acc[1][1] = ffma2(z1, w1, acc[1][1]);
      acc[1][2] = ffma2(z1, w2, acc[1][2]); acc[1][3] = ffma2(z1, w3, acc[1][3]);
      acc[2][0] = ffma2(z2, w0, acc[2][0]); acc[2][1] = ffma2(z2, w1, acc[2][1]);
      acc[2][2] = ffma2(z2, w2, acc[2][2]); acc[2][3] = ffma2(z2, w3, acc[2][3]);
      acc[3][0] = ffma2(z3, w0, acc[3][0]); acc[3][1] = ffma2(z3, w1, acc[3][1]);
      acc[3][2] = ffma2(z3, w2, acc[3][2]); acc[3][3] = ffma2(z3, w3, acc[3][3]);
      acc[4][0] = ffma2(z4, w0, acc[4][0]); acc[4][1] = ffma2(z4, w1, acc[4][1]);
      acc[4][2] = ffma2(z4, w2, acc[4][2]); acc[4][3] = ffma2(z4, w3, acc[4][3]);
      acc[5][0] = ffma2(z5, w0, acc[5][0]); acc[5][1] = ffma2(z5, w1, acc[5][1]);
      acc[5][2] = ffma2(z5, w2, acc[5][2]); acc[5][3] = ffma2(z5, w3, acc[5][3]);
      acc[6][0] = ffma2(z6, w0, acc[6][0]); acc[6][1] = ffma2(z6, w1, acc[6][1]);
      acc[6][2] = ffma2(z6, w2, acc[6][2]); acc[6][3] = ffma2(z6, w3, acc[6][3]);
      acc[7][0] = ffma2(z7, w0, acc[7][0]); acc[7][1] = ffma2(z7, w1, acc[7][1]);
      acc[7][2] = ffma2(z7, w2, acc[7][2]); acc[7][3] = ffma2(z7, w3, acc[7][3]);
    }
    if (c < 7) {
      Zs[nb][zk + 0][zr] = na0.x; Zs[nb][zk + 1][zr] = na0.y;
      Zs[nb][zk + 2][zr] = na0.z; Zs[nb][zk + 3][zr] = na0.w;
      Zs[nb][zk + 4][zr] = na1.x; Zs[nb][zk + 5][zr] = na1.y;
      Zs[nb][zk + 6][zr] = na1.z; Zs[nb][zk + 7][zr] = na1.w;
      cp_commit_wait();
      __syncthreads();
      buf = nb;
    }
  }

  float4 b0 = *reinterpret_cast<const float4*>(bias + tc * 8);
  float4 b1 = *reinterpret_cast<const float4*>(bias + tc * 8 + 4);
  float bb[8] = {b0.x, b0.y, b0.z, b0.w, b1.x, b1.y, b1.z, b1.w};
  float wd[8] = {0, 0, 0, 0, 0, 0, 0, 0};
  if (predOut) {
    float4 wd0 = *reinterpret_cast<const float4*>(WdP + tc * 8);
    float4 wd1 = *reinterpret_cast<const float4*>(WdP + tc * 8 + 4);
    wd[0] = wd0.x; wd[1] = wd0.y; wd[2] = wd0.z; wd[3] = wd0.w;
    wd[4] = wd1.x; wd[5] = wd1.y; wd[6] = wd1.z; wd[7] = wd1.w;
  }
#pragma unroll
  for (int i = 0; i < 8; ++i) {
    int row = list ? lrow[tr * 8 + i]
                   : ((t0 + tr * 8 + i < cnt) ? (t0 + tr * 8 + i) : -1);
    float o[8];
#pragma unroll
    for (int p = 0; p < 4; ++p) {
      float lo, hi;
      unpack2(acc[i][p], lo, hi);
      o[2 * p] = fmaxf(lo + bb[2 * p], 0.f);
      o[2 * p + 1] = fmaxf(hi + bb[2 * p + 1], 0.f);
    }
    if (predOut) {
      float p = o[0] * wd[0] + o[1] * wd[1] + o[2] * wd[2] + o[3] * wd[3] +
                o[4] * wd[4] + o[5] * wd[5] + o[6] * wd[6] + o[7] * wd[7];
#pragma unroll
      for (int off = 8; off; off >>= 1) p += __shfl_xor_sync(0xffffffffu, p, off);
      if (tc == 0 && row >= 0) predOut[row] = p + bdP[0];
    }
    if (row >= 0) {
      if (Sub) {
        float4 s0 = *reinterpret_cast<const float4*>(Sub + (size_t)row * 128 + tc * 8);
        float4 s1 = *reinterpret_cast<const float4*>(Sub + (size_t)row * 128 + tc * 8 + 4);
        o[0] -= s0.x; o[1] -= s0.y; o[2] -= s0.z; o[3] -= s0.w;
        o[4] -= s1.x; o[5] -= s1.y; o[6] -= s1.z; o[7] -= s1.w;
      }
      *reinterpret_cast<float4*>(Out + (size_t)row * 128 + tc * 8) =
          make_float4(o[0], o[1], o[2], o[3]);
      *reinterpret_cast<float4*>(Out + (size_t)row * 128 + tc * 8 + 4) =
          make_float4(o[4], o[5], o[6], o[7]);
    }
  }
}

// ---------------- sampling path ----------------
__global__ void k_gstats() {
  int g = blockIdx.x;
  int tid = threadIdx.x;
  int beg = g_gstart[g], end = g_gstart[g + 1];
  __shared__ float red[256];
  float mx = -3.4e38f;
  for (int n = beg + tid; n < end; n += 256) mx = fmaxf(mx, g_pred[n]);
  red[tid] = mx;
  __syncthreads();
  for (int off = 128; off; off >>= 1) {
    if (tid < off) red[tid] = fmaxf(red[tid], red[tid + off]);
    __syncthreads();
  }
  float mxv = red[0];
  __syncthreads();
  float s = 0.f;
  for (int n = beg + tid; n < end; n += 256) s += expf(g_pred[n] - mxv);
  red[tid] = s;
  __syncthreads();
  for (int off = 128; off; off >>= 1) {
    if (tid < off) red[tid] += red[tid + off];
    __syncthreads();
  }
  if (tid == 0) {
    bool ok = beg < end;
    g_gmax[g] = ok ? mxv : 0.f;
    g_gsum[g] = ok ? red[0] : 1.f;
  }
}

// Gumbel-max sampling + anchor flag marking fused
__global__ void k_sample() {
  int b = blockIdx.x;
  int m = b >> 7;
  int g = b & 127;
  int tid = threadIdx.x;
  int beg = g_gstart[g], end = g_gstart[g + 1];
  if (beg >= end) {
    if (tid == 0) g_anchor[b] = -1;
    return;
  }
  uint2 dk = threefry2x32(0u, 1u, 0u, 1u);
  float mxv = g_gmax[g];
  float sv = g_gsum[g];
  float best = -3.4e38f;
  int bid = 0x7fffffff;
  for (int n = beg + tid; n < end; n += 128) {
    float prob = expf(g_pred[n] - mxv) / sv;
    float lp = logf(prob + 1e-15f);
    uint2 r = threefry2x32(dk.x, dk.y, (unsigned)n, (unsigned)(N + n));
    unsigned bits = (m == 0) ? r.x : r.y;
    float u = __uint_as_float((bits >> 9) | 0x3f800000u) - 1.0f;
    float gum = -logf(-logf(u + 1e-12f) + 1e-12f);
    float sc = lp + gum;
    if (sc > best || (sc == best && n < bid)) { best = sc; bid = n; }
  }
  __shared__ float rs[128];
  __shared__ int ri[128];
  rs[tid] = best; ri[tid] = bid;
  __syncthreads();
  for (int off = 64; off; off >>= 1) {
    if (tid < off) {
      if (rs[tid + off] > rs[tid] ||
          (rs[tid + off] == rs[tid] && ri[tid + off] < ri[tid])) {
        rs[tid] = rs[tid + off];
        ri[tid] = ri[tid + off];
      }
    }
    __syncthreads();
  }
  if (tid == 0) {
    int a = ri[0];
    g_anchor[b] = a;
    g_fA[m * N + a] = 1;
    g_f1[m * N + a] = 1;
  }
}

// ---------------- pass-2 sparse machinery ----------------
// flag-only edge marks (no atomic appends)
__global__ void k_mark_edges1(const int* __restrict__ es, const int* __restrict__ ed) {
  int e = blockIdx.x * blockDim.x + threadIdx.x;
  if (e >= E) return;
  int s = es[e], dd = ed[e];
#pragma unroll
  for (int m = 0; m < M; ++m)
    if (g_fA[m * N + s]) g_f1[m * N + dd] = 1;
}

__global__ void k_compact1() {
  int n = blockIdx.x * blockDim.x + threadIdx.x;
  if (n >= N) return;
#pragma unroll
  for (int m = 0; m < M; ++m) {
    if (g_f1[m * N + n]) {
      int p = atomicAdd(&g_cnt[m], 1);
      g_list1[m * N + p] = n;
    }
  }
}

__global__ void k_mark_edges2(const int* __restrict__ es, const int* __restrict__ ed) {
  int e = blockIdx.x * blockDim.x + threadIdx.x;
  if (e >= E) return;
  int s = es[e], dd = ed[e];
#pragma unroll
  for (int m = 0; m < M; ++m)
    if (g_f1[m * N + s]) g_f2[m * N + dd] = 1;
}

__global__ void k_compact2() {
  int n = blockIdx.x * blockDim.x + threadIdx.x;
  if (n >= N) return;
#pragma unroll
  for (int m = 0; m < M; ++m) {
    if (g_f1[m * N + n] || g_f2[m * N + n]) {
      int p = atomicAdd(&g_cnt[4 + m], 1);
      g_list2[m * N + p] = n;
    }
  }
}

// layer-1 delta agg, CSR-based, atomic-free: one warp per listed node
// dz[n] = (fA[n] ? tx[n]*f : 0) + sum_{incoming src, fA[src]} tx[src]*f
__global__ void __launch_bounds__(256) k_dz1(const float* __restrict__ at) {
  int m = blockIdx.y;
  int cnt = g_cnt[m];
  int w = (blockIdx.x * 256 + threadIdx.x) >> 5;
  int lane = threadIdx.x & 31;
  int nw = gridDim.x * 8;
  float4 f = *reinterpret_cast<const float4*>(at + D + lane * 4);
  const unsigned char* fA = g_fA + m * N;
  float* dz = g_dz + (size_t)m * N * D;
  for (int i = w; i < cnt; i += nw) {
    int n = g_list1[m * N + i];
    float4 acc = make_float4(0.f, 0.f, 0.f, 0.f);
    if (fA[n]) {
      float4 t = *reinterpret_cast<const float4*>(g_tx + (size_t)n * D + lane * 4);
      acc.x = t.x * f.x; acc.y = t.y * f.y; acc.z = t.z * f.z; acc.w = t.w * f.w;
    }
    int beg = g_rowoff[n], end = g_rowoff[n + 1];
    for (int k = beg; k < end; ++k) {
      int s = g_csrsrc[k];
      if (fA[s]) {
        float4 t = *reinterpret_cast<const float4*>(g_tx + (size_t)s * D + lane * 4);
        acc.x += t.x * f.x; acc.y += t.y * f.y;
        acc.z += t.z * f.z; acc.w += t.w * f.w;
      }
    }
    *reinterpret_cast<float4*>(dz + (size_t)n * D + lane * 4) = acc;
  }
}

// layer-2 delta agg, CSR-based, atomic-free
// dz[n] = (f1[n] ? dh1[n] : 0) + sum_{incoming src, f1[src]} dh1[src]
__global__ void __launch_bounds__(256) k_dz2() {
  int m = blockIdx.y;
  int cnt = g_cnt[4 + m];
  int w = (blockIdx.x * 256 + threadIdx.x) >> 5;
  int lane = threadIdx.x & 31;
  int nw = gridDim.x * 8;
  const unsigned char* f1 = g_f1 + m * N;
  const float* dh1 = g_dh1 + (size_t)m * N * D;
  float* dz = g_dz + (size_t)m * N * D;
  for (int i = w; i < cnt; i += nw) {
    int n = g_list2[m * N + i];
    float4 acc = make_float4(0.f, 0.f, 0.f, 0.f);
    if (f1[n]) acc = *reinterpret_cast<const float4*>(dh1 + (size_t)n * D + lane * 4);
    int beg = g_rowoff[n], end = g_rowoff[n + 1];
    for (int k = beg; k < end; ++k) {
      int s = g_csrsrc[k];
      if (f1[s]) {
        float4 v = *reinterpret_cast<const float4*>(dh1 + (size_t)s * D + lane * 4);
        acc.x += v.x; acc.y += v.y; acc.z += v.z; acc.w += v.w;
      }
    }
    *reinterpret_cast<float4*>(dz + (size_t)n * D + lane * 4) = acc;
  }
}

// base mean pool over all nodes -> write both m copies of g_hg
__global__ void k_poolb() {
  int g = blockIdx.x;
  int tid = threadIdx.x;
  int d = tid & 127;
  int half = tid >> 7;
  int beg = g_gstart[g], end = g_gstart[g + 1];
  float acc = 0.f;
  for (int n = beg + half; n < end; n += 2) acc += g_hn[(size_t)n * D + d];
  __shared__ float s[128];
  if (half == 1) s[d] = acc;
  __syncthreads();
  if (half == 0) {
    float tot = acc + s[d];
    int c = end - beg;
    float v = tot / (float)max(c, 1);
    g_hg[(0 * NG + g) * D + d] = v;
    g_hg[(1 * NG + g) * D + d] = v;
  }
}

__global__ void k_pool_delta(const int* __restrict__ batch) {
  int m = blockIdx.y;
  int cnt = g_cnt[4 + m];
  int d = threadIdx.x;
  const float* dhn = g_dhn + (size_t)m * N * D;
  for (int i = blockIdx.x; i < cnt; i += gridDim.x) {
    int n = g_list2[m * N + i];
    int g = batch[n];
    int c = g_gstart[g + 1] - g_gstart[g];
    float inv = 1.0f / (float)max(c, 1);
    atomicAdd(&g_hg[(m * NG + g) * D + d], dhn[(size_t)n * D + d] * inv);
  }
}

__global__ void k_out(const float* __restrict__ Wp, const float* __restrict__ bp,
                      float* __restrict__ out) {
  int g = blockIdx.x;
  int t = threadIdx.x;
  if (t >= NT) return;
  float acc = 0.f;
  for (int m = 0; m < M; ++m) {
    const float* hg = &g_hg[(m * NG + g) * D];
    float s = 0.f;
#pragma unroll 16
    for (int k = 0; k < D; ++k) s += hg[k] * Wp[k * NT + t];
    acc += s;
  }
  out[g * NT + t] = acc * (1.0f / M) + bp[t];
}

// ---------------- launch ----------------
extern "C" void kernel_launch(void* const* d_in, const int* in_sizes, int n_in,
                              void* d_out, int out_size) {
  const int*   x_idx    = (const int*)d_in[0];
  const int*   edge_src = (const int*)d_in[1];
  const int*   edge_dst = (const int*)d_in[2];
  const int*   batch    = (const int*)d_in[3];
  const float* x_table  = (const float*)d_in[4];
  const float* anchor_t = (const float*)d_in[5];
  const float* Wg       = (const float*)d_in[6];
  const float* bg       = (const float*)d_in[7];
  const float* Wn       = (const float*)d_in[8];
  const float* bn       = (const float*)d_in[9];
  const float* Wd       = (const float*)d_in[10];
  const float* bd       = (const float*)d_in[11];
  const float* Wp       = (const float*)d_in[12];
  const float* bp       = (const float*)d_in[13];
  float* out = (float*)d_out;

  float *txp, *z1, *h1, *z2, *h2, *hn, *dz, *dh1, *dh2, *dhn, *predp;
  int *list1, *list2, *cnt;
  cudaGetSymbolAddress((void**)&txp, g_tx);
  cudaGetSymbolAddress((void**)&z1, g_z1);
  cudaGetSymbolAddress((void**)&h1, g_h1);
  cudaGetSymbolAddress((void**)&z2, g_z2);
  cudaGetSymbolAddress((void**)&h2, g_h2);
  cudaGetSymbolAddress((void**)&hn, g_hn);
  cudaGetSymbolAddress((void**)&dz, g_dz);
  cudaGetSymbolAddress((void**)&dh1, g_dh1);
  cudaGetSymbolAddress((void**)&dh2, g_dh2);
  cudaGetSymbolAddress((void**)&dhn, g_dhn);
  cudaGetSymbolAddress((void**)&predp, g_pred);
  cudaGetSymbolAddress((void**)&list1, g_list1);
  cudaGetSymbolAddress((void**)&list2, g_list2);
  cudaGetSymbolAddress((void**)&cnt, g_cnt);

  // lazily-created side stream + events (never destroyed; capture-safe)
  static cudaStream_t s1 = nullptr;
  static cudaEvent_t evFork = nullptr, evA = nullptr, evH2 = nullptr;
  static cudaEvent_t evPool = nullptr, evC1 = nullptr, evC2 = nullptr;
  if (!s1) {
    cudaStreamCreateWithFlags(&s1, cudaStreamNonBlocking);
    cudaEventCreateWithFlags(&evFork, cudaEventDisableTiming);
    cudaEventCreateWithFlags(&evA, cudaEventDisableTiming);
    cudaEventCreateWithFlags(&evH2, cudaEventDisableTiming);
    cudaEventCreateWithFlags(&evPool, cudaEventDisableTiming);
    cudaEventCreateWithFlags(&evC1, cudaEventDisableTiming);
    cudaEventCreateWithFlags(&evC2, cudaEventDisableTiming);
  }
  cudaStream_t s0 = 0;

  const int AGG_GRID = (N * 32 + 255) / 256;
  const int MMG = (N + 127) / 128;       // 391
  const dim3 MM1(MMG, 1);
  const dim3 MM2(MMG, 2);

  // ---- fork: embed + flag clear on s1, CSR build on s0 ----
  cudaEventRecord(evFork, s0);
  cudaStreamWaitEvent(s1, evFork, 0);
  k_embed<<<N, D, 0, s1>>>(x_idx, batch, x_table);
  k_mclear<<<(N + 255) / 256, 256, 0, s1>>>();
  cudaEventRecord(evA, s1);

  k_zerodeg<<<(N + 255) / 256, 256, 0, s0>>>();
  k_hist<<<(E + 255) / 256, 256, 0, s0>>>(edge_dst);
  k_scan<<<1, 1024, 0, s0>>>();
  k_scatter<<<(E + 255) / 256, 256, 0, s0>>>(edge_src, edge_dst);
  cudaStreamWaitEvent(s0, evA, 0);

  // ---- pass 1 (base) on s0; h2 GEMM fuses the pred head ----
  k_agg<<<AGG_GRID, 256, 0, s0>>>(txp, z1);
  k_mm<<<MM1, 256, 0, s0>>>(N, nullptr, nullptr, 0, z1, nullptr, Wg, bg, nullptr, h1,
                            nullptr, nullptr, nullptr);
  k_agg<<<AGG_GRID, 256, 0, s0>>>(h1, z2);
  k_mm<<<MM1, 256, 0, s0>>>(N, nullptr, nullptr, 0, z2, nullptr, Wg + D * D, bg + D,
                            nullptr, h2, Wd, bd, predp);
  cudaEventRecord(evH2, s0);

  // ---- s1: base node MLP + base pool (overlaps sampling + layer-1 deltas) ----
  cudaStreamWaitEvent(s1, evH2, 0);
  k_mm<<<MM1, 256, 0, s1>>>(N, nullptr, nullptr, 0, h2, nullptr, Wn, bn, nullptr, hn,
                            nullptr, nullptr, nullptr);
  k_poolb<<<NG, 256, 0, s1>>>();
  cudaEventRecord(evPool, s1);

  // ---- s0: sampling + layer-1 deltas ----
  k_gstats<<<NG, 256, 0, s0>>>();
  k_sample<<<M * NG, 128, 0, s0>>>();
  k_mark_edges1<<<(E + 255) / 256, 256, 0, s0>>>(edge_src, edge_dst);
  k_compact1<<<(N + 255) / 256, 256, 0, s0>>>();
  cudaEventRecord(evC1, s0);
  k_dz1<<<dim3(64, 2), 256, 0, s0>>>(anchor_t);
  k_mm<<<MM2, 256, 0, s0>>>(0, list1, cnt, 0, z1, dz, Wg, bg, h1, dh1,
                            nullptr, nullptr, nullptr);

  // ---- s1 (concurrent): layer-2 frontier discovery ----
  cudaStreamWaitEvent(s1, evC1, 0);
  k_mark_edges2<<<(E + 255) / 256, 256, 0, s1>>>(edge_src, edge_dst);
  k_compact2<<<(N + 255) / 256, 256, 0, s1>>>();
  cudaEventRecord(evC2, s1);

  // ---- s0: layer-2 + node-MLP deltas, pool, head ----
  cudaStreamWaitEvent(s0, evC2, 0);
  k_dz2<<<dim3(256, 2), 256, 0, s0>>>();
  k_mm<<<MM2, 256, 0, s0>>>(0, list2, cnt, 4, z2, dz, Wg + D * D, bg + D, h2, dh2,
                            nullptr, nullptr, nullptr);
  cudaStreamWaitEvent(s0, evPool, 0);
  k_mm<<<MM2, 256, 0, s0>>>(0, list2, cnt, 4, h2, dh2, Wn, bn, hn, dhn,
                            nullptr, nullptr, nullptr);
  k_pool_delta<<<dim3(256, 2), 128, 0, s0>>>(batch);
  k_out<<<NG, 32, 0, s0>>>(Wp, bp, out);
}

// round 10
// speedup vs baseline: 1.6546x; 1.0765x over previous
#include <cuda_runtime.h>
#include <stdint.h>

// ---------------- problem constants ----------------
constexpr int N  = 50000;
constexpr int E  = 800000;
constexpr int NG = 128;
constexpr int D  = 128;
constexpr int M  = 2;
constexpr int NT = 10;

typedef unsigned long long ull;

// ---------------- device scratch ----------------
__device__ float g_tx[N * D];
__device__ float g_y1[N * D];
__device__ float g_zp1[N * D];
__device__ float g_h1[N * D];
__device__ float g_y2[N * D];
__device__ float g_zp2[N * D];
__device__ float g_h2[N * D];
__device__ float g_hn[N * D];
__device__ float g_dA[M * N * D];    // dy1 then dy2
__device__ float g_dh1[M * N * D];
__device__ float g_dh2[M * N * D];
__device__ float g_dhn[M * N * D];
__device__ float g_wmod[D * D];      // diag(at1) * W0
__device__ int   g_deg[N];
__device__ int   g_rowoff[N + 1];
__device__ int   g_cursor[N];
__device__ int   g_csrsrc[E];
__device__ int   g_gstart[NG + 1];
__device__ float g_pred[N];
__device__ float g_gmax[NG];
__device__ float g_gsum[NG];
__device__ int   g_anchor[M * NG];
__device__ float g_hg[M * NG * D];
__device__ unsigned char g_fA[M * N];
__device__ unsigned char g_f1[M * N];
__device__ unsigned char g_f2[M * N];
__device__ int   g_list1[M * N];
__device__ int   g_list2[M * N];
__device__ int   g_cnt[8];  // [m]=cnt1, [4+m]=cnt2

// ---------------- f32x2 helpers ----------------
__device__ __forceinline__ ull ffma2(ull a, ull b, ull c) {
  ull d;
  asm("fma.rn.f32x2 %0, %1, %2, %3;" : "=l"(d) : "l"(a), "l"(b), "l"(c));
  return d;
}
__device__ __forceinline__ ull pack2dup(float x) {
  ull r;
  asm("mov.b64 %0, {%1, %1};" : "=l"(r) : "f"(x));
  return r;
}
__device__ __forceinline__ void unpack2(ull v, float& lo, float& hi) {
  asm("mov.b64 {%0, %1}, %2;" : "=f"(lo), "=f"(hi) : "l"(v));
}
__device__ __forceinline__ void cp16(void* smem, const void* gmem) {
  unsigned s = (unsigned)__cvta_generic_to_shared(smem);
  asm volatile("cp.async.cg.shared.global [%0], [%1], 16;" :: "r"(s), "l"(gmem));
}
__device__ __forceinline__ void cp_commit_wait() {
  asm volatile("cp.async.commit_group;");
  asm volatile("cp.async.wait_group 0;");
}

// ---------------- threefry2x32 (exact JAX) ----------------
__device__ __forceinline__ uint2 threefry2x32(unsigned k0, unsigned k1,
                                              unsigned x0, unsigned x1) {
  unsigned k2 = k0 ^ k1 ^ 0x1BD11BDAu;
  x0 += k0; x1 += k1;
#define TF_ROT(x, d) (((x) << (d)) | ((x) >> (32 - (d))))
#define TF_RND(r) { x0 += x1; x1 = TF_ROT(x1, r); x1 ^= x0; }
  TF_RND(13) TF_RND(15) TF_RND(26) TF_RND(6)
  x0 += k1; x1 += k2 + 1u;
  TF_RND(17) TF_RND(29) TF_RND(16) TF_RND(24)
  x0 += k2; x1 += k0 + 2u;
  TF_RND(13) TF_RND(15) TF_RND(26) TF_RND(6)
  x0 += k0; x1 += k1 + 3u;
  TF_RND(17) TF_RND(29) TF_RND(16) TF_RND(24)
  x0 += k1; x1 += k2 + 4u;
  TF_RND(13) TF_RND(15) TF_RND(26) TF_RND(6)
  x0 += k2; x1 += k0 + 5u;
#undef TF_RND
#undef TF_ROT
  return make_uint2(x0, x1);
}

// ---------------- base kernels ----------------
__global__ void k_zerodeg() {
  int n = blockIdx.x * blockDim.x + threadIdx.x;
  if (n < N) g_deg[n] = 0;
}

__global__ void k_mclear() {
  int n = blockIdx.x * blockDim.x + threadIdx.x;
  if (n < N) {
    g_fA[n] = 0; g_fA[N + n] = 0;
    g_f1[n] = 0; g_f1[N + n] = 0;
    g_f2[n] = 0; g_f2[N + n] = 0;
  }
  if (n < 8) g_cnt[n] = 0;
}

__global__ void k_embed(const int* __restrict__ x_idx,
                        const int* __restrict__ batch,
                        const float* __restrict__ x_table) {
  int n = blockIdx.x;
  int d = threadIdx.x;
  g_tx[n * D + d] = x_table[x_idx[n] * D + d];
  if (d == 0) {
    int b = batch[n];
    if (n == 0) {
      for (int g = 0; g <= b; ++g) g_gstart[g] = 0;
    } else {
      int pb = batch[n - 1];
      for (int g = pb + 1; g <= b; ++g) g_gstart[g] = n;
    }
    if (n == N - 1) {
      for (int g = b + 1; g <= NG; ++g) g_gstart[g] = N;
    }
  }
}

// Wmod[d,j] = at1[d] * W0[d,j]
__global__ void k_wmod(const float* __restrict__ at, const float* __restrict__ W0) {
  int d = blockIdx.x;
  int j = threadIdx.x;
  g_wmod[d * D + j] = at[D + d] * W0[d * D + j];
}

__global__ void k_hist(const int* __restrict__ edge_dst) {
  int e = blockIdx.x * blockDim.x + threadIdx.x;
  if (e < E) atomicAdd(&g_deg[edge_dst[e]], 1);
}

__global__ void k_scan() {
  __shared__ int sums[1024];
  int tid = threadIdx.x;
  const int CH = (N + 1023) / 1024;
  int beg = tid * CH;
  int end = min(beg + CH, N);
  int s = 0;
  for (int i = beg; i < end; ++i) s += g_deg[i];
  sums[tid] = s;
  __syncthreads();
  for (int off = 1; off < 1024; off <<= 1) {
    int v = (tid >= off) ? sums[tid - off] : 0;
    __syncthreads();
    sums[tid] += v;
    __syncthreads();
  }
  int pre = (tid == 0) ? 0 : sums[tid - 1];
  for (int i = beg; i < end; ++i) {
    g_rowoff[i] = pre;
    g_cursor[i] = pre;
    pre += g_deg[i];
  }
  if (tid == 1023) g_rowoff[N] = sums[1023];
}

__global__ void k_scatter(const int* __restrict__ edge_src,
                          const int* __restrict__ edge_dst) {
  int e = blockIdx.x * blockDim.x + threadIdx.x;
  if (e < E) {
    int d = edge_dst[e];
    int pos = atomicAdd(&g_cursor[d], 1);
    g_csrsrc[pos] = edge_src[e];
  }
}

// fused aggregate + bias + relu (+ optional pred head):
// zpre[n] = y[n] + sum_{src->n} y[src] + bias ; h[n] = relu(zpre[n])
// pred[n] = h[n,:].Wd + bd   (if pred != null)
__global__ void __launch_bounds__(256) k_aggf(const float* __restrict__ y,
                                              float* __restrict__ zpre,
                                              float* __restrict__ h,
                                              const float* __restrict__ bias,
                                              const float* __restrict__ Wd,
                                              const float* __restrict__ bd,
                                              float* __restrict__ pred) {
  int w = (blockIdx.x * blockDim.x + threadIdx.x) >> 5;
  int lane = threadIdx.x & 31;
  if (w >= N) return;
  int beg = g_rowoff[w], end = g_rowoff[w + 1];
  float4 acc = *reinterpret_cast<const float4*>(y + (size_t)w * D + lane * 4);
  int k = beg;
  for (; k + 1 < end; k += 2) {
    int s0 = g_csrsrc[k];
    int s1 = g_csrsrc[k + 1];
    float4 v0 = *reinterpret_cast<const float4*>(y + (size_t)s0 * D + lane * 4);
    float4 v1 = *reinterpret_cast<const float4*>(y + (size_t)s1 * D + lane * 4);
    acc.x += v0.x + v1.x; acc.y += v0.y + v1.y;
    acc.z += v0.z + v1.z; acc.w += v0.w + v1.w;
  }
  if (k < end) {
    int s0 = g_csrsrc[k];
    float4 v0 = *reinterpret_cast<const float4*>(y + (size_t)s0 * D + lane * 4);
    acc.x += v0.x; acc.y += v0.y; acc.z += v0.z; acc.w += v0.w;
  }
  float4 bv = *reinterpret_cast<const float4*>(bias + lane * 4);
  acc.x += bv.x; acc.y += bv.y; acc.z += bv.z; acc.w += bv.w;
  *reinterpret_cast<float4*>(zpre + (size_t)w * D + lane * 4) = acc;
  float4 hv = make_float4(fmaxf(acc.x, 0.f), fmaxf(acc.y, 0.f),
                          fmaxf(acc.z, 0.f), fmaxf(acc.w, 0.f));
  *reinterpret_cast<float4*>(h + (size_t)w * D + lane * 4) = hv;
  if (pred) {
    float4 wv = *reinterpret_cast<const float4*>(Wd + lane * 4);
    float p = hv.x * wv.x + hv.y * wv.y + hv.z * wv.z + hv.w * wv.w;
#pragma unroll
    for (int off = 16; off; off >>= 1) p += __shfl_xor_sync(0xffffffffu, p, off);
    if (lane == 0) pred[w] = p + bd[0];
  }
}

// Unified 128x128-tile GEMM, 8x8/thread, FFMA2, double-buffered, cp.async W.
// Dense (listb==null): rows [0,Rdense), Out dense.
// List  (listb!=null): rows list[m][i], i<cnt (cnt = cntp?cntp[cntoff+m]:Rdense),
//                      Out offset m*N*D. Z = (Zb? Zb[row] : 0) + (Dzb? Dzb[m][row] : 0).
// bias!=null => +bias and ReLU. Sub!=null => subtract Sub[row] after activation.
__global__ void __launch_bounds__(256) k_mm(
    int Rdense,
    const int* __restrict__ listb, int listStride,
    const int* __restrict__ cntp, int cntoff,
    const float* __restrict__ Zb, const float* __restrict__ Dzb,
    const float* __restrict__ W, const float* __restrict__ bias,
    const float* __restrict__ Sub, float* __restrict__ Outb) {
  const int m = blockIdx.y;
  const int cnt = cntp ? cntp[cntoff + m] : Rdense;
  const int t0 = blockIdx.x * 128;
  if (t0 >= cnt) return;
  const int* list = listb ? (listb + m * listStride) : nullptr;
  const float* Dz = Dzb ? (Dzb + (size_t)m * N * D) : nullptr;
  float* Out = Outb + (listb ? (size_t)m * N * D : (size_t)0);

  __shared__ int lrow[128];
  __shared__ float Zs[2][16][136];
  __shared__ float Ws[2][16][132];

  const int tid = threadIdx.x;
  if (list) {
    if (tid < 128) lrow[tid] = (t0 + tid < cnt) ? list[t0 + tid] : -1;
    __syncthreads();
  }
  const int zr = tid >> 1;
  const int zk = (tid & 1) * 8;
  const int wk = tid >> 4;
  const int wj = (tid & 15) * 8;
  const int tr = tid >> 4;
  const int tc = tid & 15;
  const int zrow = list ? lrow[zr] : ((t0 + zr < cnt) ? (t0 + zr) : -1);

  ull acc[8][4];
#pragma unroll
  for (int i = 0; i < 8; ++i)
#pragma unroll
    for (int p = 0; p < 4; ++p) acc[i][p] = 0ull;

  {
    cp16(&Ws[0][wk][wj], W + (size_t)wk * 128 + wj);
    cp16(&Ws[0][wk][wj + 4], W + (size_t)wk * 128 + wj + 4);
    float4 a0 = make_float4(0.f, 0.f, 0.f, 0.f), a1 = a0;
    if (zrow >= 0) {
      if (Zb) {
        a0 = *reinterpret_cast<const float4*>(Zb + (size_t)zrow * 128 + zk);
        a1 = *reinterpret_cast<const float4*>(Zb + (size_t)zrow * 128 + zk + 4);
      }
      if (Dz) {
        float4 d0 = *reinterpret_cast<const float4*>(Dz + (size_t)zrow * 128 + zk);
        float4 d1 = *reinterpret_cast<const float4*>(Dz + (size_t)zrow * 128 + zk + 4);
        a0.x += d0.x; a0.y += d0.y; a0.z += d0.z; a0.w += d0.w;
        a1.x += d1.x; a1.y += d1.y; a1.z += d1.z; a1.w += d1.w;
      }
    }
    Zs[0][zk + 0][zr] = a0.x; Zs[0][zk + 1][zr] = a0.y;
    Zs[0][zk + 2][zr] = a0.z; Zs[0][zk + 3][zr] = a0.w;
    Zs[0][zk + 4][zr] = a1.x; Zs[0][zk + 5][zr] = a1.y;
    Zs[0][zk + 6][zr] = a1.z; Zs[0][zk + 7][zr] = a1.w;
    cp_commit_wait();
  }
  __syncthreads();

  int buf = 0;
#pragma unroll 1
  for (int c = 0; c < 8; ++c) {
    const int nb = buf ^ 1;
    float4 na0, na1;
    if (c < 7) {
      int k0 = (c + 1) * 16;
      cp16(&Ws[nb][wk][wj], W + (size_t)(k0 + wk) * 128 + wj);
      cp16(&Ws[nb][wk][wj + 4], W + (size_t)(k0 + wk) * 128 + wj + 4);
      na0 = make_float4(0.f, 0.f, 0.f, 0.f); na1 = na0;
      if (zrow >= 0) {
        if (Zb) {
          na0 = *reinterpret_cast<const float4*>(Zb + (size_t)zrow * 128 + k0 + zk);
          na1 = *reinterpret_cast<const float4*>(Zb + (size_t)zrow * 128 + k0 + zk + 4);
        }
        if (Dz) {
          float4 d0 = *reinterpret_cast<const float4*>(Dz + (size_t)zrow * 128 + k0 + zk);
          float4 d1 = *reinterpret_cast<const float4*>(Dz + (size_t)zrow * 128 + k0 + zk + 4);
          na0.x += d0.x; na0.y += d0.y; na0.z += d0.z; na0.w += d0.w;
          na1.x += d1.x; na1.y += d1.y; na1.z += d1.z; na1.w += d1.w;
        }
      }
    }
#pragma unroll
    for (int kk = 0; kk < 16; ++kk) {
      float4 za = *reinterpret_cast<const float4*>(&Zs[buf][kk][tr * 8]);
      float4 zb2 = *reinterpret_cast<const float4*>(&Zs[buf][kk][tr * 8 + 4]);
      ull z0 = pack2dup(za.x), z1 = pack2dup(za.y);
      ull z2 = pack2dup(za.z), z3 = pack2dup(za.w);
      ull z4 = pack2dup(zb2.x), z5 = pack2dup(zb2.y);
      ull z6 = pack2dup(zb2.z), z7 = pack2dup(zb2.w);
      const ull* wp = reinterpret_cast<const ull*>(&Ws[buf][kk][tc * 8]);
      ull w0 = wp[0], w1 = wp[1], w2 = wp[2], w3 = wp[3];
      acc[0][0] = ffma2(z0, w0, acc[0][0]); acc[0][1] = ffma2(z0, w1, acc[0][1]);
      acc[0][2] = ffma2(z0, w2, acc[0][2]); acc[0][3] = ffma2(z0, w3, acc[0][3]);
      acc[1][0] = ffma2(z1, w0, acc[1][0]); acc[1][1] = ffma2(z1, w1, acc[1][1]);
      acc[1][2] = ffma2(z1, w2, acc[1][2]); acc[1][3] = ffma2(z1, w3, acc[1][3]);
      acc[2][0] = ffma2(z2, w0, acc[2][0]); acc[2][1] = ffma2(z2, w1, acc[2][1]);
      acc[2][2] = ffma2(z2, w2, acc[2][2]); acc[2][3] = ffma2(z2, w3, acc[2][3]);
      acc[3][0] = ffma2(z3, w0, acc[3][0]); acc[3][1] = ffma2(z3, w1, acc[3][1]);
      acc[3][2] = ffma2(z3, w2, acc[3][2]); acc[3][3] = ffma2(z3, w3, acc[3][3]);
      acc[4][0] = ffma2(z4, w0, acc[4][0]); acc[4][1] = ffma2(z4, w1, acc[4][1]);
      acc[4][2] = ffma2(z4, w2, acc[4][2]); acc[4][3] = ffma2(z4, w3, acc[4][3]);
      acc[5][0] = ffma2(z5, w0, acc[5][0]); acc[5][1] = ffma2(z5, w1, acc[5][1]);
      acc[5][2] = ffma2(z5, w2, acc[5][2]); acc[5][3] = ffma2(z5, w3, acc[5][3]);
      acc[6][0] = ffma2(z6, w0, acc[6][0]); acc[6][1] = ffma2(z6, w1, acc[6][1]);
      acc[6][2] = ffma2(z6, w2, acc[6][2]); acc[6][3] = ffma2(z6, w3, acc[6][3]);
      acc[7][0] = ffma2(z7, w0, acc[7][0]); acc[7][1] = ffma2(z7, w1, acc[7][1]);
      acc[7][2] = ffma2(z7, w2, acc[7][2]); acc[7][3] = ffma2(z7, w3, acc[7][3]);
    }
    if (c < 7) {
      Zs[nb][zk + 0][zr] = na0.x; Zs[nb][zk + 1][zr] = na0.y;
      Zs[nb][zk + 2][zr] = na0.z; Zs[nb][zk + 3][zr] = na0.w;
      Zs[nb][zk + 4][zr] = na1.x; Zs[nb][zk + 5][zr] = na1.y;
      Zs[nb][zk + 6][zr] = na1.z; Zs[nb][zk + 7][zr] = na1.w;
      cp_commit_wait();
      __syncthreads();
      buf = nb;
    }
  }

  float bb[8] = {0, 0, 0, 0, 0, 0, 0, 0};
  if (bias) {
    float4 b0 = *reinterpret_cast<const float4*>(bias + tc * 8);
    float4 b1 = *reinterpret_cast<const float4*>(bias + tc * 8 + 4);
    bb[0] = b0.x; bb[1] = b0.y; bb[2] = b0.z; bb[3] = b0.w;
    bb[4] = b1.x; bb[5] = b1.y; bb[6] = b1.z; bb[7] = b1.w;
  }
#pragma unroll
  for (int i = 0; i < 8; ++i) {
    int row = list ? lrow[tr * 8 + i]
                   : ((t0 + tr * 8 + i < cnt) ? (t0 + tr * 8 + i) : -1);
    if (row >= 0) {
      float o[8];
#pragma unroll
      for (int p = 0; p < 4; ++p) {
        float lo, hi;
        unpack2(acc[i][p], lo, hi);
        o[2 * p] = lo + bb[2 * p];
        o[2 * p + 1] = hi + bb[2 * p + 1];
      }
      if (bias) {
#pragma unroll
        for (int j = 0; j < 8; ++j) o[j] = fmaxf(o[j], 0.f);
      }
      if (Sub) {
        float4 s0 = *reinterpret_cast<const float4*>(Sub + (size_t)row * 128 + tc * 8);
        float4 s1 = *reinterpret_cast<const float4*>(Sub + (size_t)row * 128 + tc * 8 + 4);
        o[0] -= s0.x; o[1] -= s0.y; o[2] -= s0.z; o[3] -= s0.w;
        o[4] -= s1.x; o[5] -= s1.y; o[6] -= s1.z; o[7] -= s1.w;
      }
      *reinterpret_cast<float4*>(Out + (size_t)row * 128 + tc * 8) =
          make_float4(o[0], o[1], o[2], o[3]);
      *reinterpret_cast<float4*>(Out + (size_t)row * 128 + tc * 8 + 4) =
          make_float4(o[4], o[5], o[6], o[7]);
    }
  }
}

// ---------------- sampling path ----------------
__global__ void k_gstats() {
  int g = blockIdx.x;
  int tid = threadIdx.x;
  int beg = g_gstart[g], end = g_gstart[g + 1];
  __shared__ float red[256];
  float mx = -3.4e38f;
  for (int n = beg + tid; n < end; n += 256) mx = fmaxf(mx, g_pred[n]);
  red[tid] = mx;
  __syncthreads();
  for (int off = 128; off; off >>= 1) {
    if (tid < off) red[tid] = fmaxf(red[tid], red[tid + off]);
    __syncthreads();
  }
  float mxv = red[0];
  __syncthreads();
  float s = 0.f;
  for (int n = beg + tid; n < end; n += 256) s += expf(g_pred[n] - mxv);
  red[tid] = s;
  __syncthreads();
  for (int off = 128; off; off >>= 1) {
    if (tid < off) red[tid] += red[tid + off];
    __syncthreads();
  }
  if (tid == 0) {
    bool ok = beg < end;
    g_gmax[g] = ok ? mxv : 0.f;
    g_gsum[g] = ok ? red[0] : 1.f;
  }
}

__global__ void k_sample() {
  int b = blockIdx.x;
  int m = b >> 7;
  int g = b & 127;
  int tid = threadIdx.x;
  int beg = g_gstart[g], end = g_gstart[g + 1];
  if (beg >= end) {
    if (tid == 0) g_anchor[b] = -1;
    return;
  }
  uint2 dk = threefry2x32(0u, 1u, 0u, 1u);
  float mxv = g_gmax[g];
  float sv = g_gsum[g];
  float best = -3.4e38f;
  int bid = 0x7fffffff;
  for (int n = beg + tid; n < end; n += 128) {
    float prob = expf(g_pred[n] - mxv) / sv;
    float lp = logf(prob + 1e-15f);
    uint2 r = threefry2x32(dk.x, dk.y, (unsigned)n, (unsigned)(N + n));
    unsigned bits = (m == 0) ? r.x : r.y;
    float u = __uint_as_float((bits >> 9) | 0x3f800000u) - 1.0f;
    float gum = -logf(-logf(u + 1e-12f) + 1e-12f);
    float sc = lp + gum;
    if (sc > best || (sc == best && n < bid)) { best = sc; bid = n; }
  }
  __shared__ float rs[128];
  __shared__ int ri[128];
  rs[tid] = best; ri[tid] = bid;
  __syncthreads();
  for (int off = 64; off; off >>= 1) {
    if (tid < off) {
      if (rs[tid + off] > rs[tid] ||
          (rs[tid + off] == rs[tid] && ri[tid + off] < ri[tid])) {
        rs[tid] = rs[tid + off];
        ri[tid] = ri[tid + off];
      }
    }
    __syncthreads();
  }
  if (tid == 0) {
    int a = ri[0];
    g_anchor[b] = a;
    g_fA[m * N + a] = 1;
    g_f1[m * N + a] = 1;
  }
}

// ---------------- sparse delta machinery ----------------
__global__ void k_mark_edges1(const int* __restrict__ es, const int* __restrict__ ed) {
  int e = blockIdx.x * blockDim.x + threadIdx.x;
  if (e >= E) return;
  int s = es[e], dd = ed[e];
#pragma unroll
  for (int m = 0; m < M; ++m)
    if (g_fA[m * N + s]) g_f1[m * N + dd] = 1;
}

__global__ void k_compact1() {
  int n = blockIdx.x * blockDim.x + threadIdx.x;
  if (n >= N) return;
#pragma unroll
  for (int m = 0; m < M; ++m) {
    if (g_f1[m * N + n]) {
      int p = atomicAdd(&g_cnt[m], 1);
      g_list1[m * N + p] = n;
    }
  }
}

__global__ void k_mark_edges2(const int* __restrict__ es, const int* __restrict__ ed) {
  int e = blockIdx.x * blockDim.x + threadIdx.x;
  if (e >= E) return;
  int s = es[e], dd = ed[e];
#pragma unroll
  for (int m = 0; m < M; ++m)
    if (g_f1[m * N + s]) g_f2[m * N + dd] = 1;
}

__global__ void k_compact2() {
  int n = blockIdx.x * blockDim.x + threadIdx.x;
  if (n >= N) return;
#pragma unroll
  for (int m = 0; m < M; ++m) {
    if (g_f1[m * N + n] || g_f2[m * N + n]) {
      int p = atomicAdd(&g_cnt[4 + m], 1);
      g_list2[m * N + p] = n;
    }
  }
}

// layer-1 delta: for n in list1:
//   dzy = (fA[n]? dA[n]:0) + sum_{src->n, fA[src]} dA[src]
//   dh1[n] = relu(zp1[n] + dzy) - h1[n]
__global__ void __launch_bounds__(256) k_delta1() {
  int m = blockIdx.y;
  int cnt = g_cnt[m];
  int w = (blockIdx.x * 256 + threadIdx.x) >> 5;
  int lane = threadIdx.x & 31;
  int nw = gridDim.x * 8;
  const unsigned char* fA = g_fA + m * N;
  const float* dA = g_dA + (size_t)m * N * D;
  float* dh1 = g_dh1 + (size_t)m * N * D;
  for (int i = w; i < cnt; i += nw) {
    int n = g_list1[m * N + i];
    float4 acc = make_float4(0.f, 0.f, 0.f, 0.f);
    if (fA[n]) acc = *reinterpret_cast<const float4*>(dA + (size_t)n * D + lane * 4);
    int beg = g_rowoff[n], end = g_rowoff[n + 1];
    for (int k = beg; k < end; ++k) {
      int s = g_csrsrc[k];
      if (fA[s]) {
        float4 v = *reinterpret_cast<const float4*>(dA + (size_t)s * D + lane * 4);
        acc.x += v.x; acc.y += v.y; acc.z += v.z; acc.w += v.w;
      }
    }
    float4 zp = *reinterpret_cast<const float4*>(g_zp1 + (size_t)n * D + lane * 4);
    float4 hv = *reinterpret_cast<const float4*>(g_h1 + (size_t)n * D + lane * 4);
    float4 o;
    o.x = fmaxf(zp.x + acc.x, 0.f) - hv.x;
    o.y = fmaxf(zp.y + acc.y, 0.f) - hv.y;
    o.z = fmaxf(zp.z + acc.z, 0.f) - hv.z;
    o.w = fmaxf(zp.w + acc.w, 0.f) - hv.w;
    *reinterpret_cast<float4*>(dh1 + (size_t)n * D + lane * 4) = o;
  }
}

// layer-2 delta: for n in list2:
//   dzy = (f1[n]? dA[n]:0) + sum_{src->n, f1[src]} dA[src]   (dA = dy2)
//   dh2[n] = relu(zp2[n] + dzy) - h2[n]
__global__ void __launch_bounds__(256) k_delta2() {
  int m = blockIdx.y;
  int cnt = g_cnt[4 + m];
  int w = (blockIdx.x * 256 + threadIdx.x) >> 5;
  int lane = threadIdx.x & 31;
  int nw = gridDim.x * 8;
  const unsigned char* f1 = g_f1 + m * N;
  const float* dA = g_dA + (size_t)m * N * D;
  float* dh2 = g_dh2 + (size_t)m * N * D;
  for (int i = w; i < cnt; i += nw) {
    int n = g_list2[m * N + i];
    float4 acc = make_float4(0.f, 0.f, 0.f, 0.f);
    if (f1[n]) acc = *reinterpret_cast<const float4*>(dA + (size_t)n * D + lane * 4);
    int beg = g_rowoff[n], end = g_rowoff[n + 1];
    for (int k = beg; k < end; ++k) {
      int s = g_csrsrc[k];
      if (f1[s]) {
        float4 v = *reinterpret_cast<const float4*>(dA + (size_t)s * D + lane * 4);
        acc.x += v.x; acc.y += v.y; acc.z += v.z; acc.w += v.w;
      }
    }
    float4 zp = *reinterpret_cast<const float4*>(g_zp2 + (size_t)n * D + lane * 4);
    float4 hv = *reinterpret_cast<const float4*>(g_h2 + (size_t)n * D + lane * 4);
    float4 o;
    o.x = fmaxf(zp.x + acc.x, 0.f) - hv.x;
    o.y = fmaxf(zp.y + acc.y, 0.f) - hv.y;
    o.z = fmaxf(zp.z + acc.z, 0.f) - hv.z;
    o.w = fmaxf(zp.w + acc.w, 0.f) - hv.w;
    *reinterpret_cast<float4*>(dh2 + (size_t)n * D + lane * 4) = o;
  }
}

// base mean pool -> both m copies of g_hg
__global__ void k_poolb() {
  int g = blockIdx.x;
  int tid = threadIdx.x;
  int d = tid & 127;
  int half = tid >> 7;
  int beg = g_gstart[g], end = g_gstart[g + 1];
  float acc = 0.f;
  for (int n = beg + half; n < end; n += 2) acc += g_hn[(size_t)n * D + d];
  __shared__ float s[128];
  if (half == 1) s[d] = acc;
  __syncthreads();
  if (half == 0) {
    float tot = acc + s[d];
    int c = end - beg;
    float v = tot / (float)max(c, 1);
    g_hg[(0 * NG + g) * D + d] = v;
    g_hg[(1 * NG + g) * D + d] = v;
  }
}

__global__ void k_pool_delta(const int* __restrict__ batch) {
  int m = blockIdx.y;
  int cnt = g_cnt[4 + m];
  int d = threadIdx.x;
  const float* dhn = g_dhn + (size_t)m * N * D;
  for (int i = blockIdx.x; i < cnt; i += gridDim.x) {
    int n = g_list2[m * N + i];
    int g = batch[n];
    int c = g_gstart[g + 1] - g_gstart[g];
    float inv = 1.0f / (float)max(c, 1);
    atomicAdd(&g_hg[(m * NG + g) * D + d], dhn[(size_t)n * D + d] * inv);
  }
}

__global__ void k_out(const float* __restrict__ Wp, const float* __restrict__ bp,
                      float* __restrict__ out) {
  int g = blockIdx.x;
  int t = threadIdx.x;
  if (t >= NT) return;
  float acc = 0.f;
  for (int m = 0; m < M; ++m) {
    const float* hg = &g_hg[(m * NG + g) * D];
    float s = 0.f;
#pragma unroll 16
    for (int k = 0; k < D; ++k) s += hg[k] * Wp[k * NT + t];
    acc += s;
  }
  out[g * NT + t] = acc * (1.0f / M) + bp[t];
}

// ---------------- launch ----------------
extern "C" void kernel_launch(void* const* d_in, const int* in_sizes, int n_in,
                              void* d_out, int out_size) {
  const int*   x_idx    = (const int*)d_in[0];
  const int*   edge_src = (const int*)d_in[1];
  const int*   edge_dst = (const int*)d_in[2];
  const int*   batch    = (const int*)d_in[3];
  const float* x_table  = (const float*)d_in[4];
  const float* anchor_t = (const float*)d_in[5];
  const float* Wg       = (const float*)d_in[6];
  const float* bg       = (const float*)d_in[7];
  const float* Wn       = (const float*)d_in[8];
  const float* bn       = (const float*)d_in[9];
  const float* Wd       = (const float*)d_in[10];
  const float* bd       = (const float*)d_in[11];
  const float* Wp       = (const float*)d_in[12];
  const float* bp       = (const float*)d_in[13];
  float* out = (float*)d_out;

  float *txp, *y1, *zp1, *h1, *y2, *zp2, *h2, *hn, *dA, *dh1, *dh2, *dhn;
  float *predp, *wmod;
  int *list1, *list2, *cnt, *anch;
  cudaGetSymbolAddress((void**)&txp, g_tx);
  cudaGetSymbolAddress((void**)&y1, g_y1);
  cudaGetSymbolAddress((void**)&zp1, g_zp1);
  cudaGetSymbolAddress((void**)&h1, g_h1);
  cudaGetSymbolAddress((void**)&y2, g_y2);
  cudaGetSymbolAddress((void**)&zp2, g_zp2);
  cudaGetSymbolAddress((void**)&h2, g_h2);
  cudaGetSymbolAddress((void**)&hn, g_hn);
  cudaGetSymbolAddress((void**)&dA, g_dA);
  cudaGetSymbolAddress((void**)&dh1, g_dh1);
  cudaGetSymbolAddress((void**)&dh2, g_dh2);
  cudaGetSymbolAddress((void**)&dhn, g_dhn);
  cudaGetSymbolAddress((void**)&predp, g_pred);
  cudaGetSymbolAddress((void**)&wmod, g_wmod);
  cudaGetSymbolAddress((void**)&list1, g_list1);
  cudaGetSymbolAddress((void**)&list2, g_list2);
  cudaGetSymbolAddress((void**)&cnt, g_cnt);
  cudaGetSymbolAddress((void**)&anch, g_anchor);

  static cudaStream_t s1 = nullptr;
  static cudaEvent_t evFork = nullptr, evY1 = nullptr, evH2 = nullptr;
  static cudaEvent_t evPool = nullptr, evC1 = nullptr, evC2 = nullptr;
  if (!s1) {
    cudaStreamCreateWithFlags(&s1, cudaStreamNonBlocking);
    cudaEventCreateWithFlags(&evFork, cudaEventDisableTiming);
    cudaEventCreateWithFlags(&evY1, cudaEventDisableTiming);
    cudaEventCreateWithFlags(&evH2, cudaEventDisableTiming);
    cudaEventCreateWithFlags(&evPool, cudaEventDisableTiming);
    cudaEventCreateWithFlags(&evC1, cudaEventDisableTiming);
    cudaEventCreateWithFlags(&evC2, cudaEventDisableTiming);
  }
  cudaStream_t s0 = 0;

  const int AGG_GRID = (N * 32 + 255) / 256;
  const int MMG = (N + 127) / 128;       // 391
  const dim3 MM1(MMG, 1);
  const dim3 MM2(MMG, 2);

  // ---- fork: s1 does embed + clears + wmod + y1 GEMM; s0 builds CSR ----
  cudaEventRecord(evFork, s0);
  cudaStreamWaitEvent(s1, evFork, 0);
  k_embed<<<N, D, 0, s1>>>(x_idx, batch, x_table);
  k_mclear<<<(N + 255) / 256, 256, 0, s1>>>();
  k_wmod<<<D, D, 0, s1>>>(anchor_t, Wg);
  k_mm<<<MM1, 256, 0, s1>>>(N, nullptr, 0, nullptr, 0, txp, nullptr, Wg, nullptr,
                            nullptr, y1);
  cudaEventRecord(evY1, s1);

  k_zerodeg<<<(N + 255) / 256, 256, 0, s0>>>();
  k_hist<<<(E + 255) / 256, 256, 0, s0>>>(edge_dst);
  k_scan<<<1, 1024, 0, s0>>>();
  k_scatter<<<(E + 255) / 256, 256, 0, s0>>>(edge_src, edge_dst);
  cudaStreamWaitEvent(s0, evY1, 0);

  // ---- layer 1 + layer 2 (agg-after-GEMM) on s0 ----
  k_aggf<<<AGG_GRID, 256, 0, s0>>>(y1, zp1, h1, bg, nullptr, nullptr, nullptr);
  k_mm<<<MM1, 256, 0, s0>>>(N, nullptr, 0, nullptr, 0, h1, nullptr, Wg + D * D,
                            nullptr, nullptr, y2);
  k_aggf<<<AGG_GRID, 256, 0, s0>>>(y2, zp2, h2, bg + D, Wd, bd, predp);
  cudaEventRecord(evH2, s0);

  // ---- s1: base node MLP + base pool ----
  cudaStreamWaitEvent(s1, evH2, 0);
  k_mm<<<MM1, 256, 0, s1>>>(N, nullptr, 0, nullptr, 0, h2, nullptr, Wn, bn,
                            nullptr, hn);
  k_poolb<<<NG, 256, 0, s1>>>();
  cudaEventRecord(evPool, s1);

  // ---- s0: sampling + layer-1 deltas ----
  k_gstats<<<NG, 256, 0, s0>>>();
  k_sample<<<M * NG, 128, 0, s0>>>();
  k_mark_edges1<<<(E + 255) / 256, 256, 0, s0>>>(edge_src, edge_dst);
  k_compact1<<<(N + 255) / 256, 256, 0, s0>>>();
  cudaEventRecord(evC1, s0);
  // dy1 = tx[anchor rows] @ Wmod   (anchor list, 128 rows per m)
  k_mm<<<dim3(1, 2), 256, 0, s0>>>(NG, anch, NG, nullptr, 0, txp, nullptr, wmod,
                                   nullptr, nullptr, dA);
  k_delta1<<<dim3(64, 2), 256, 0, s0>>>();

  // ---- s1 (concurrent): layer-2 frontier discovery ----
  cudaStreamWaitEvent(s1, evC1, 0);
  k_mark_edges2<<<(E + 255) / 256, 256, 0, s1>>>(edge_src, edge_dst);
  k_compact2<<<(N + 255) / 256, 256, 0, s1>>>();
  cudaEventRecord(evC2, s1);

  // ---- s0: dy2 (list1 GEMM), layer-2 delta, node-MLP delta GEMM ----
  k_mm<<<MM2, 256, 0, s0>>>(0, list1, N, cnt, 0, nullptr, dh1, Wg + D * D,
                            nullptr, nullptr, dA);
  cudaStreamWaitEvent(s0, evC2, 0);
  k_delta2<<<dim3(256, 2), 256, 0, s0>>>();
  cudaStreamWaitEvent(s0, evPool, 0);
  k_mm<<<MM2, 256, 0, s0>>>(0, list2, N, cnt, 4, h2, dh2, Wn, bn, hn, dhn);
  k_pool_delta<<<dim3(256, 2), 128, 0, s0>>>(batch);
  k_out<<<NG, 32, 0, s0>>>(Wp, bp, out);
}

// round 12
// speedup vs baseline: 1.8060x; 1.0915x over previous
#include <cuda_runtime.h>
#include <cuda_bf16.h>
#include <stdint.h>

// ---------------- problem constants ----------------
constexpr int N  = 50000;
constexpr int E  = 800000;
constexpr int NG = 128;
constexpr int D  = 128;
constexpr int M  = 2;
constexpr int NT = 10;

typedef unsigned long long ull;

// ---------------- device scratch ----------------
__device__ float g_tx[N * D];
__device__ float g_y1[N * D];
__device__ float g_zp1[N * D];
__device__ float g_h1[N * D];
__device__ float g_y2[N * D];
__device__ float g_zp2[N * D];
__device__ float g_h2[N * D];
__device__ float g_hn[N * D];
__device__ float g_dA[M * N * D];
__device__ float g_dh1[M * N * D];
__device__ float g_dh2[M * N * D];
__device__ float g_dhn[M * N * D];
__device__ float g_wmod[D * D];
__device__ __nv_bfloat16 g_wb[3 * 3 * D * D];  // [weight][term][n][k]
__device__ int   g_deg[N];
__device__ int   g_rowoff[N + 1];
__device__ int   g_cursor[N];
__device__ int   g_csrsrc[E];
__device__ int   g_gstart[NG + 1];
__device__ float g_pred[N];
__device__ float g_gmax[NG];
__device__ float g_gsum[NG];
__device__ int   g_anchor[M * NG];
__device__ float g_hg[M * NG * D];
__device__ unsigned char g_fA[M * N];
__device__ unsigned char g_f1[M * N];
__device__ unsigned char g_f2[M * N];
__device__ int   g_list1[M * N];
__device__ int   g_list2[M * N];
__device__ int   g_cnt[8];

// ---------------- helpers ----------------
__device__ __forceinline__ ull ffma2(ull a, ull b, ull c) {
  ull d;
  asm("fma.rn.f32x2 %0, %1, %2, %3;" : "=l"(d) : "l"(a), "l"(b), "l"(c));
  return d;
}
__device__ __forceinline__ ull pack2dup(float x) {
  ull r;
  asm("mov.b64 %0, {%1, %1};" : "=l"(r) : "f"(x));
  return r;
}
__device__ __forceinline__ void unpack2(ull v, float& lo, float& hi) {
  asm("mov.b64 {%0, %1}, %2;" : "=f"(lo), "=f"(hi) : "l"(v));
}
__device__ __forceinline__ void cp16(void* smem, const void* gmem) {
  unsigned s = (unsigned)__cvta_generic_to_shared(smem);
  asm volatile("cp.async.cg.shared.global [%0], [%1], 16;" :: "r"(s), "l"(gmem));
}
__device__ __forceinline__ void cp_commit_wait() {
  asm volatile("cp.async.commit_group;");
  asm volatile("cp.async.wait_group 0;");
}

// bf16 mma m16n8k16, fp32 accumulate
__device__ __forceinline__ void mma16816(float* d, const unsigned* a,
                                         unsigned b0, unsigned b1) {
  asm volatile(
      "mma.sync.aligned.m16n8k16.row.col.f32.bf16.bf16.f32 "
      "{%0,%1,%2,%3}, {%4,%5,%6,%7}, {%8,%9}, {%0,%1,%2,%3};"
      : "+f"(d[0]), "+f"(d[1]), "+f"(d[2]), "+f"(d[3])
      : "r"(a[0]), "r"(a[1]), "r"(a[2]), "r"(a[3]), "r"(b0), "r"(b1));
}

// split a pair of fp32 into 3 bf16x2 limb registers (lower 16 bits = v0's limb)
__device__ __forceinline__ void split3pair(float v0, float v1, unsigned& s0,
                                           unsigned& s1, unsigned& s2) {
  __nv_bfloat16 x0 = __float2bfloat16(v0);
  float rx = v0 - __bfloat162float(x0);
  __nv_bfloat16 x1 = __float2bfloat16(rx);
  float rx2 = rx - __bfloat162float(x1);
  __nv_bfloat16 x2 = __float2bfloat16(rx2);
  __nv_bfloat16 y0 = __float2bfloat16(v1);
  float ry = v1 - __bfloat162float(y0);
  __nv_bfloat16 y1 = __float2bfloat16(ry);
  float ry2 = ry - __bfloat162float(y1);
  __nv_bfloat16 y2 = __float2bfloat16(ry2);
  __nv_bfloat162 p0 = __halves2bfloat162(x0, y0);
  __nv_bfloat162 p1 = __halves2bfloat162(x1, y1);
  __nv_bfloat162 p2 = __halves2bfloat162(x2, y2);
  s0 = *reinterpret_cast<unsigned*>(&p0);
  s1 = *reinterpret_cast<unsigned*>(&p1);
  s2 = *reinterpret_cast<unsigned*>(&p2);
}

// ---------------- threefry2x32 (exact JAX) ----------------
__device__ __forceinline__ uint2 threefry2x32(unsigned k0, unsigned k1,
                                              unsigned x0, unsigned x1) {
  unsigned k2 = k0 ^ k1 ^ 0x1BD11BDAu;
  x0 += k0; x1 += k1;
#define TF_ROT(x, d) (((x) << (d)) | ((x) >> (32 - (d))))
#define TF_RND(r) { x0 += x1; x1 = TF_ROT(x1, r); x1 ^= x0; }
  TF_RND(13) TF_RND(15) TF_RND(26) TF_RND(6)
  x0 += k1; x1 += k2 + 1u;
  TF_RND(17) TF_RND(29) TF_RND(16) TF_RND(24)
  x0 += k2; x1 += k0 + 2u;
  TF_RND(13) TF_RND(15) TF_RND(26) TF_RND(6)
  x0 += k0; x1 += k1 + 3u;
  TF_RND(17) TF_RND(29) TF_RND(16) TF_RND(24)
  x0 += k1; x1 += k2 + 4u;
  TF_RND(13) TF_RND(15) TF_RND(26) TF_RND(6)
  x0 += k2; x1 += k0 + 5u;
#undef TF_RND
#undef TF_ROT
  return make_uint2(x0, x1);
}

// ---------------- base kernels ----------------
__global__ void k_zerodeg() {
  int n = blockIdx.x * blockDim.x + threadIdx.x;
  if (n < N) g_deg[n] = 0;
}

__global__ void k_mclear() {
  int n = blockIdx.x * blockDim.x + threadIdx.x;
  if (n < N) {
    g_fA[n] = 0; g_fA[N + n] = 0;
    g_f1[n] = 0; g_f1[N + n] = 0;
    g_f2[n] = 0; g_f2[N + n] = 0;
  }
  if (n < 8) g_cnt[n] = 0;
}

__global__ void k_embed(const int* __restrict__ x_idx,
                        const int* __restrict__ batch,
                        const float* __restrict__ x_table) {
  int n = blockIdx.x;
  int d = threadIdx.x;
  g_tx[n * D + d] = x_table[x_idx[n] * D + d];
  if (d == 0) {
    int b = batch[n];
    if (n == 0) {
      for (int g = 0; g <= b; ++g) g_gstart[g] = 0;
    } else {
      int pb = batch[n - 1];
      for (int g = pb + 1; g <= b; ++g) g_gstart[g] = n;
    }
    if (n == N - 1) {
      for (int g = b + 1; g <= NG; ++g) g_gstart[g] = N;
    }
  }
}

__global__ void k_wmod(const float* __restrict__ at, const float* __restrict__ W0) {
  int d = blockIdx.x;
  int j = threadIdx.x;
  g_wmod[d * D + j] = at[D + d] * W0[d * D + j];
}

// split W[k][n] into 3 bf16 limbs -> g_wb[widx][term][n][k]
__global__ void k_wsplit3(const float* __restrict__ W, int widx) {
  int k = blockIdx.x;
  int n = threadIdx.x;
  float v = W[k * D + n];
  __nv_bfloat16 t0 = __float2bfloat16(v);
  float r = v - __bfloat162float(t0);
  __nv_bfloat16 t1 = __float2bfloat16(r);
  float r2 = r - __bfloat162float(t1);
  __nv_bfloat16 t2 = __float2bfloat16(r2);
  size_t base = (size_t)widx * 3 * D * D;
  g_wb[base + (0 * D + n) * D + k] = t0;
  g_wb[base + (1 * D + n) * D + k] = t1;
  g_wb[base + (2 * D + n) * D + k] = t2;
}

__global__ void k_hist(const int* __restrict__ edge_dst) {
  int e = blockIdx.x * blockDim.x + threadIdx.x;
  if (e < E) atomicAdd(&g_deg[edge_dst[e]], 1);
}

__global__ void k_scan() {
  __shared__ int sums[1024];
  int tid = threadIdx.x;
  const int CH = (N + 1023) / 1024;
  int beg = tid * CH;
  int end = min(beg + CH, N);
  int s = 0;
  for (int i = beg; i < end; ++i) s += g_deg[i];
  sums[tid] = s;
  __syncthreads();
  for (int off = 1; off < 1024; off <<= 1) {
    int v = (tid >= off) ? sums[tid - off] : 0;
    __syncthreads();
    sums[tid] += v;
    __syncthreads();
  }
  int pre = (tid == 0) ? 0 : sums[tid - 1];
  for (int i = beg; i < end; ++i) {
    g_rowoff[i] = pre;
    g_cursor[i] = pre;
    pre += g_deg[i];
  }
  if (tid == 1023) g_rowoff[N] = sums[1023];
}

__global__ void k_scatter(const int* __restrict__ edge_src,
                          const int* __restrict__ edge_dst) {
  int e = blockIdx.x * blockDim.x + threadIdx.x;
  if (e < E) {
    int d = edge_dst[e];
    int pos = atomicAdd(&g_cursor[d], 1);
    g_csrsrc[pos] = edge_src[e];
  }
}

// fused aggregate + bias + relu (+ optional pred head)
__global__ void __launch_bounds__(256) k_aggf(const float* __restrict__ y,
                                              float* __restrict__ zpre,
                                              float* __restrict__ h,
                                              const float* __restrict__ bias,
                                              const float* __restrict__ Wd,
                                              const float* __restrict__ bd,
                                              float* __restrict__ pred) {
  int w = (blockIdx.x * blockDim.x + threadIdx.x) >> 5;
  int lane = threadIdx.x & 31;
  if (w >= N) return;
  int beg = g_rowoff[w], end = g_rowoff[w + 1];
  float4 acc = *reinterpret_cast<const float4*>(y + (size_t)w * D + lane * 4);
  int k = beg;
  for (; k + 1 < end; k += 2) {
    int s0 = g_csrsrc[k];
    int s1 = g_csrsrc[k + 1];
    float4 v0 = *reinterpret_cast<const float4*>(y + (size_t)s0 * D + lane * 4);
    float4 v1 = *reinterpret_cast<const float4*>(y + (size_t)s1 * D + lane * 4);
    acc.x += v0.x + v1.x; acc.y += v0.y + v1.y;
    acc.z += v0.z + v1.z; acc.w += v0.w + v1.w;
  }
  if (k < end) {
    int s0 = g_csrsrc[k];
    float4 v0 = *reinterpret_cast<const float4*>(y + (size_t)s0 * D + lane * 4);
    acc.x += v0.x; acc.y += v0.y; acc.z += v0.z; acc.w += v0.w;
  }
  float4 bv = *reinterpret_cast<const float4*>(bias + lane * 4);
  acc.x += bv.x; acc.y += bv.y; acc.z += bv.z; acc.w += bv.w;
  *reinterpret_cast<float4*>(zpre + (size_t)w * D + lane * 4) = acc;
  float4 hv = make_float4(fmaxf(acc.x, 0.f), fmaxf(acc.y, 0.f),
                          fmaxf(acc.z, 0.f), fmaxf(acc.w, 0.f));
  *reinterpret_cast<float4*>(h + (size_t)w * D + lane * 4) = hv;
  if (pred) {
    float4 wv = *reinterpret_cast<const float4*>(Wd + lane * 4);
    float p = hv.x * wv.x + hv.y * wv.y + hv.z * wv.z + hv.w * wv.w;
#pragma unroll
    for (int off = 16; off; off >>= 1) p += __shfl_xor_sync(0xffffffffu, p, off);
    if (lane == 0) pred[w] = p + bd[0];
  }
}

// ---------------- bf16 tensor-core dense GEMM (6-limb, fp32-accurate) ---------
// Out[r,:] = Z[r,:] @ W[widx] (+bias, relu if bias != null)
// CTA: 128 rows x 128 cols, 8 warps x 16 rows. HMMA m16n8k16.
static constexpr int KP = 136;  // padded k-extent in smem (bank-conflict-free)
static constexpr int WB_SMEM = 3 * D * KP * 2;  // 104448 B

__global__ void __launch_bounds__(256) k_hmm(int R, const float* __restrict__ Z,
                                             int widx,
                                             const float* __restrict__ bias,
                                             float* __restrict__ Out) {
  extern __shared__ __nv_bfloat16 wb_s[];  // [3][D][KP]
  const int tid = threadIdx.x;
  const int lane = tid & 31;
  const int wid = tid >> 5;
  const int t0 = blockIdx.x * 128;

  // stage 3 bf16 weight planes into padded smem
  {
    const __nv_bfloat16* src = g_wb + (size_t)widx * 3 * D * D;
    for (int i = tid; i < 3 * D * (D / 8); i += 256) {
      int t = i / (D * (D / 8));
      int rem = i % (D * (D / 8));
      int n = rem / (D / 8);
      int kk = (rem % (D / 8)) * 8;
      cp16(&wb_s[(t * D + n) * KP + kk], src + (t * D + n) * D + kk);
    }
    cp_commit_wait();
  }
  __syncthreads();

  const int lr0 = lane >> 2;          // 0..7
  const int qc = (lane & 3) * 2;      // 0,2,4,6
  const int gr0 = t0 + wid * 16 + lr0;
  const int gr1 = gr0 + 8;
  const bool ok0 = gr0 < R;
  const bool ok1 = gr1 < R;
  const int nb = lane >> 2;           // B fragment n offset within 8-col tile

  float d[16][4];
#pragma unroll
  for (int i = 0; i < 16; ++i)
#pragma unroll
    for (int j = 0; j < 4; ++j) d[i][j] = 0.f;

#pragma unroll 1
  for (int kc = 0; kc < 8; ++kc) {
    const int k0 = kc * 16 + qc;
    float2 A00 = make_float2(0.f, 0.f), A10 = A00, A01 = A00, A11 = A00;
    if (ok0) {
      A00 = *reinterpret_cast<const float2*>(Z + (size_t)gr0 * D + k0);
      A01 = *reinterpret_cast<const float2*>(Z + (size_t)gr0 * D + k0 + 8);
    }
    if (ok1) {
      A10 = *reinterpret_cast<const float2*>(Z + (size_t)gr1 * D + k0);
      A11 = *reinterpret_cast<const float2*>(Z + (size_t)gr1 * D + k0 + 8);
    }
    unsigned a0[4], a1[4], a2[4];
    split3pair(A00.x, A00.y, a0[0], a1[0], a2[0]);
    split3pair(A10.x, A10.y, a0[1], a1[1], a2[1]);
    split3pair(A01.x, A01.y, a0[2], a1[2], a2[2]);
    split3pair(A11.x, A11.y, a0[3], a1[3], a2[3]);

    const int kb = kc * 16 + qc;
#pragma unroll
    for (int nt = 0; nt < 16; ++nt) {
      const int n = nt * 8 + nb;
      unsigned b00 = *reinterpret_cast<const unsigned*>(&wb_s[(0 * D + n) * KP + kb]);
      unsigned b01 = *reinterpret_cast<const unsigned*>(&wb_s[(0 * D + n) * KP + kb + 8]);
      unsigned b10 = *reinterpret_cast<const unsigned*>(&wb_s[(1 * D + n) * KP + kb]);
      unsigned b11 = *reinterpret_cast<const unsigned*>(&wb_s[(1 * D + n) * KP + kb + 8]);
      unsigned b20 = *reinterpret_cast<const unsigned*>(&wb_s[(2 * D + n) * KP + kb]);
      unsigned b21 = *reinterpret_cast<const unsigned*>(&wb_s[(2 * D + n) * KP + kb + 8]);
      mma16816(d[nt], a0, b00, b01);   // (0,0)
      mma16816(d[nt], a0, b10, b11);   // (0,1)
      mma16816(d[nt], a1, b00, b01);   // (1,0)
      mma16816(d[nt], a1, b10, b11);   // (1,1)
      mma16816(d[nt], a0, b20, b21);   // (0,2)
      mma16816(d[nt], a2, b00, b01);   // (2,0)
    }
  }

  // epilogue
#pragma unroll
  for (int nt = 0; nt < 16; ++nt) {
    int col = nt * 8 + qc;
    float o0 = d[nt][0], o1 = d[nt][1], o2 = d[nt][2], o3 = d[nt][3];
    if (bias) {
      float b0v = bias[col], b1v = bias[col + 1];
      o0 = fmaxf(o0 + b0v, 0.f);
      o1 = fmaxf(o1 + b1v, 0.f);
      o2 = fmaxf(o2 + b0v, 0.f);
      o3 = fmaxf(o3 + b1v, 0.f);
    }
    if (ok0)
      *reinterpret_cast<float2*>(Out + (size_t)gr0 * D + col) = make_float2(o0, o1);
    if (ok1)
      *reinterpret_cast<float2*>(Out + (size_t)gr1 * D + col) = make_float2(o2, o3);
  }
}

// ---------------- FFMA2 GEMM (list modes) ----------------
__global__ void __launch_bounds__(256) k_mm(
    int Rdense,
    const int* __restrict__ listb, int listStride,
    const int* __restrict__ cntp, int cntoff,
    const float* __restrict__ Zb, const float* __restrict__ Dzb,
    const float* __restrict__ W, const float* __restrict__ bias,
    const float* __restrict__ Sub, float* __restrict__ Outb) {
  const int m = blockIdx.y;
  const int cnt = cntp ? cntp[cntoff + m] : Rdense;
  const int t0 = blockIdx.x * 128;
  if (t0 >= cnt) return;
  const int* list = listb ? (listb + m * listStride) : nullptr;
  const float* Dz = Dzb ? (Dzb + (size_t)m * N * D) : nullptr;
  float* Out = Outb + (listb ? (size_t)m * N * D : (size_t)0);

  __shared__ int lrow[128];
  __shared__ float Zs[2][16][136];
  __shared__ float Ws[2][16][132];

  const int tid = threadIdx.x;
  if (list) {
    if (tid < 128) lrow[tid] = (t0 + tid < cnt) ? list[t0 + tid] : -1;
    __syncthreads();
  }
  const int zr = tid >> 1;
  const int zk = (tid & 1) * 8;
  const int wk = tid >> 4;
  const int wj = (tid & 15) * 8;
  const int tr = tid >> 4;
  const int tc = tid & 15;
  const int zrow = list ? lrow[zr] : ((t0 + zr < cnt) ? (t0 + zr) : -1);

  ull acc[8][4];
#pragma unroll
  for (int i = 0; i < 8; ++i)
#pragma unroll
    for (int p = 0; p < 4; ++p) acc[i][p] = 0ull;

  {
    cp16(&Ws[0][wk][wj], W + (size_t)wk * 128 + wj);
    cp16(&Ws[0][wk][wj + 4], W + (size_t)wk * 128 + wj + 4);
    float4 a0 = make_float4(0.f, 0.f, 0.f, 0.f), a1 = a0;
    if (zrow >= 0) {
      if (Zb) {
        a0 = *reinterpret_cast<const float4*>(Zb + (size_t)zrow * 128 + zk);
        a1 = *reinterpret_cast<const float4*>(Zb + (size_t)zrow * 128 + zk + 4);
      }
      if (Dz) {
        float4 d0 = *reinterpret_cast<const float4*>(Dz + (size_t)zrow * 128 + zk);
        float4 d1 = *reinterpret_cast<const float4*>(Dz + (size_t)zrow * 128 + zk + 4);
        a0.x += d0.x; a0.y += d0.y; a0.z += d0.z; a0.w += d0.w;
        a1.x += d1.x; a1.y += d1.y; a1.z += d1.z; a1.w += d1.w;
      }
    }
    Zs[0][zk + 0][zr] = a0.x; Zs[0][zk + 1][zr] = a0.y;
    Zs[0][zk + 2][zr] = a0.z; Zs[0][zk + 3][zr] = a0.w;
    Zs[0][zk + 4][zr] = a1.x; Zs[0][zk + 5][zr] = a1.y;
    Zs[0][zk + 6][zr] = a1.z; Zs[0][zk + 7][zr] = a1.w;
    cp_commit_wait();
  }
  __syncthreads();

  int buf = 0;
#pragma unroll 1
  for (int c = 0; c < 8; ++c) {
    const int nb2 = buf ^ 1;
    float4 na0, na1;
    if (c < 7) {
      int k0 = (c + 1) * 16;
      cp16(&Ws[nb2][wk][wj], W + (size_t)(k0 + wk) * 128 + wj);
      cp16(&Ws[nb2][wk][wj + 4], W + (size_t)(k0 + wk) * 128 + wj + 4);
      na0 = make_float4(0.f, 0.f, 0.f, 0.f); na1 = na0;
      if (zrow >= 0) {
        if (Zb) {
          na0 = *reinterpret_cast<const float4*>(Zb + (size_t)zrow * 128 + k0 + zk);
          na1 = *reinterpret_cast<const float4*>(Zb + (size_t)zrow * 128 + k0 + zk + 4);
        }
        if (Dz) {
          float4 d0 = *reinterpret_cast<const float4*>(Dz + (size_t)zrow * 128 + k0 + zk);
          float4 d1 = *reinterpret_cast<const float4*>(Dz + (size_t)zrow * 128 + k0 + zk + 4);
          na0.x += d0.x; na0.y += d0.y; na0.z += d0.z; na0.w += d0.w;
          na1.x += d1.x; na1.y += d1.y; na1.z += d1.z; na1.w += d1.w;
        }
      }
    }
#pragma unroll
    for (int kk = 0; kk < 16; ++kk) {
      float4 za = *reinterpret_cast<const float4*>(&Zs[buf][kk][tr * 8]);
      float4 zb2 = *reinterpret_cast<const float4*>(&Zs[buf][kk][tr * 8 + 4]);
      ull z0 = pack2dup(za.x), z1 = pack2dup(za.y);
      ull z2 = pack2dup(za.z), z3 = pack2dup(za.w);
      ull z4 = pack2dup(zb2.x), z5 = pack2dup(zb2.y);
      ull z6 = pack2dup(zb2.z), z7 = pack2dup(zb2.w);
      const ull* wp = reinterpret_cast<const ull*>(&Ws[buf][kk][tc * 8]);
      ull w0 = wp[0], w1 = wp[1], w2 = wp[2], w3 = wp[3];
      acc[0][0] = ffma2(z0, w0, acc[0][0]); acc[0][1] = ffma2(z0, w1, acc[0][1]);
      acc[0][2] = ffma2(z0, w2, acc[0][2]); acc[0][3] = ffma2(z0, w3, acc[0][3]);
      acc[1][0] = ffma2(z1, w0, acc[1][0]); acc[1][1] = ffma2(z1, w1, acc[1][1]);
      acc[1][2] = ffma2(z1, w2, acc[1][2]); acc[1][3] = ffma2(z1, w3, acc[1][3]);
      acc[2][0] = ffma2(z2, w0, acc[2][0]); acc[2][1] = ffma2(z2, w1, acc[2][1]);
      acc[2][2] = ffma2(z2, w2, acc[2][2]); acc[2][3] = ffma2(z2, w3, acc[2][3]);
      acc[3][0] = ffma2(z3, w0, acc[3][0]); acc[3][1] = ffma2(z3, w1, acc[3][1]);
      acc[3][2] = ffma2(z3, w2, acc[3][2]); acc[3][3] = ffma2(z3, w3, acc[3][3]);
      acc[4][0] = ffma2(z4, w0, acc[4][0]); acc[4][1] = ffma2(z4, w1, acc[4][1]);
      acc[4][2] = ffma2(z4, w2, acc[4][2]); acc[4][3] = ffma2(z4, w3, acc[4][3]);
      acc[5][0] = ffma2(z5, w0, acc[5][0]); acc[5][1] = ffma2(z5, w1, acc[5][1]);
      acc[5][2] = ffma2(z5, w2, acc[5][2]); acc[5][3] = ffma2(z5, w3, acc[5][3]);
      acc[6][0] = ffma2(z6, w0, acc[6][0]); acc[6][1] = ffma2(z6, w1, acc[6][1]);
      acc[6][2] = ffma2(z6, w2, acc[6][2]); acc[6][3] = ffma2(z6, w3, acc[6][3]);
      acc[7][0] = ffma2(z7, w0, acc[7][0]); acc[7][1] = ffma2(z7, w1, acc[7][1]);
      acc[7][2] = ffma2(z7, w2, acc[7][2]); acc[7][3] = ffma2(z7, w3, acc[7][3]);
    }
    if (c < 7) {
      Zs[nb2][zk + 0][zr] = na0.x; Zs[nb2][zk + 1][zr] = na0.y;
      Zs[nb2][zk + 2][zr] = na0.z; Zs[nb2][zk + 3][zr] = na0.w;
      Zs[nb2][zk + 4][zr] = na1.x; Zs[nb2][zk + 5][zr] = na1.y;
      Zs[nb2][zk + 6][zr] = na1.z; Zs[nb2][zk + 7][zr] = na1.w;
      cp_commit_wait();
      __syncthreads();
      buf = nb2;
    }
  }

  float bb[8] = {0, 0, 0, 0, 0, 0, 0, 0};
  if (bias) {
    float4 b0 = *reinterpret_cast<const float4*>(bias + tc * 8);
    float4 b1 = *reinterpret_cast<const float4*>(bias + tc * 8 + 4);
    bb[0] = b0.x; bb[1] = b0.y; bb[2] = b0.z; bb[3] = b0.w;
    bb[4] = b1.x; bb[5] = b1.y; bb[6] = b1.z; bb[7] = b1.w;
  }
#pragma unroll
  for (int i = 0; i < 8; ++i) {
    int row = list ? lrow[tr * 8 + i]
                   : ((t0 + tr * 8 + i < cnt) ? (t0 + tr * 8 + i) : -1);
    if (row >= 0) {
      float o[8];
#pragma unroll
      for (int p = 0; p < 4; ++p) {
        float lo, hi;
        unpack2(acc[i][p], lo, hi);
        o[2 * p] = lo + bb[2 * p];
        o[2 * p + 1] = hi + bb[2 * p + 1];
      }
      if (bias) {
#pragma unroll
        for (int j = 0; j < 8; ++j) o[j] = fmaxf(o[j], 0.f);
      }
      if (Sub) {
        float4 s0 = *reinterpret_cast<const float4*>(Sub + (size_t)row * 128 + tc * 8);
        float4 s1 = *reinterpret_cast<const float4*>(Sub + (size_t)row * 128 + tc * 8 + 4);
        o[0] -= s0.x; o[1] -= s0.y; o[2] -= s0.z; o[3] -= s0.w;
        o[4] -= s1.x; o[5] -= s1.y; o[6] -= s1.z; o[7] -= s1.w;
      }
      *reinterpret_cast<float4*>(Out + (size_t)row * 128 + tc * 8) =
          make_float4(o[0], o[1], o[2], o[3]);
      *reinterpret_cast<float4*>(Out + (size_t)row * 128 + tc * 8 + 4) =
          make_float4(o[4], o[5], o[6], o[7]);
    }
  }
}

// ---------------- sampling path ----------------
__global__ void k_gstats() {
  int g = blockIdx.x;
  int tid = threadIdx.x;
  int beg = g_gstart[g], end = g_gstart[g + 1];
  __shared__ float red[256];
  float mx = -3.4e38f;
  for (int n = beg + tid; n < end; n += 256) mx = fmaxf(mx, g_pred[n]);
  red[tid] = mx;
  __syncthreads();
  for (int off = 128; off; off >>= 1) {
    if (tid < off) red[tid] = fmaxf(red[tid], red[tid + off]);
    __syncthreads();
  }
  float mxv = red[0];
  __syncthreads();
  float s = 0.f;
  for (int n = beg + tid; n < end; n += 256) s += expf(g_pred[n] - mxv);
  red[tid] = s;
  __syncthreads();
  for (int off = 128; off; off >>= 1) {
    if (tid < off) red[tid] += red[tid + off];
    __syncthreads();
  }
  if (tid == 0) {
    bool ok = beg < end;
    g_gmax[g] = ok ? mxv : 0.f;
    g_gsum[g] = ok ? red[0] : 1.f;
  }
}

__global__ void k_sample() {
  int b = blockIdx.x;
  int m = b >> 7;
  int g = b & 127;
  int tid = threadIdx.x;
  int beg = g_gstart[g], end = g_gstart[g + 1];
  if (beg >= end) {
    if (tid == 0) g_anchor[b] = -1;
    return;
  }
  uint2 dk = threefry2x32(0u, 1u, 0u, 1u);
  float mxv = g_gmax[g];
  float sv = g_gsum[g];
  float best = -3.4e38f;
  int bid = 0x7fffffff;
  for (int n = beg + tid; n < end; n += 128) {
    float prob = expf(g_pred[n] - mxv) / sv;
    float lp = logf(prob + 1e-15f);
    uint2 r = threefry2x32(dk.x, dk.y, (unsigned)n, (unsigned)(N + n));
    unsigned bits = (m == 0) ? r.x : r.y;
    float u = __uint_as_float((bits >> 9) | 0x3f800000u) - 1.0f;
    float gum = -logf(-logf(u + 1e-12f) + 1e-12f);
    float sc = lp + gum;
    if (sc > best || (sc == best && n < bid)) { best = sc; bid = n; }
  }
  __shared__ float rs[128];
  __shared__ int ri[128];
  rs[tid] = best; ri[tid] = bid;
  __syncthreads();
  for (int off = 64; off; off >>= 1) {
    if (tid < off) {
      if (rs[tid + off] > rs[tid] ||
          (rs[tid + off] == rs[tid] && ri[tid + off] < ri[tid])) {
        rs[tid] = rs[tid + off];
        ri[tid] = ri[tid + off];
      }
    }
    __syncthreads();
  }
  if (tid == 0) {
    int a = ri[0];
    g_anchor[b] = a;
    g_fA[m * N + a] = 1;
    g_f1[m * N + a] = 1;
  }
}

// ---------------- sparse delta machinery ----------------
__global__ void k_mark_edges1(const int* __restrict__ es, const int* __restrict__ ed) {
  int e = blockIdx.x * blockDim.x + threadIdx.x;
  if (e >= E) return;
  int s = es[e], dd = ed[e];
#pragma unroll
  for (int m = 0; m < M; ++m)
    if (g_fA[m * N + s]) g_f1[m * N + dd] = 1;
}

__global__ void k_compact1() {
  int n = blockIdx.x * blockDim.x + threadIdx.x;
  if (n >= N) return;
#pragma unroll
  for (int m = 0; m < M; ++m) {
    if (g_f1[m * N + n]) {
      int p = atomicAdd(&g_cnt[m], 1);
      g_list1[m * N + p] = n;
    }
  }
}

__global__ void k_mark_edges2(const int* __restrict__ es, const int* __restrict__ ed) {
  int e = blockIdx.x * blockDim.x + threadIdx.x;
  if (e >= E) return;
  int s = es[e], dd = ed[e];
#pragma unroll
  for (int m = 0; m < M; ++m)
    if (g_f1[m * N + s]) g_f2[m * N + dd] = 1;
}

__global__ void k_compact2() {
  int n = blockIdx.x * blockDim.x + threadIdx.x;
  if (n >= N) return;
#pragma unroll
  for (int m = 0; m < M; ++m) {
    if (g_f1[m * N + n] || g_f2[m * N + n]) {
      int p = atomicAdd(&g_cnt[4 + m], 1);
      g_list2[m * N + p] = n;
    }
  }
}

__global__ void __launch_bounds__(256) k_delta1() {
  int m = blockIdx.y;
  int cnt = g_cnt[m];
  int w = (blockIdx.x * 256 + threadIdx.x) >> 5;
  int lane = threadIdx.x & 31;
  int nw = gridDim.x * 8;
  const unsigned char* fA = g_fA + m * N;
  const float* dA = g_dA + (size_t)m * N * D;
  float* dh1 = g_dh1 + (size_t)m * N * D;
  for (int i = w; i < cnt; i += nw) {
    int n = g_list1[m * N + i];
    float4 acc = make_float4(0.f, 0.f, 0.f, 0.f);
    if (fA[n]) acc = *reinterpret_cast<const float4*>(dA + (size_t)n * D + lane * 4);
    int beg = g_rowoff[n], end = g_rowoff[n + 1];
    for (int k = beg; k < end; ++k) {
      int s = g_csrsrc[k];
      if (fA[s]) {
        float4 v = *reinterpret_cast<const float4*>(dA + (size_t)s * D + lane * 4);
        acc.x += v.x; acc.y += v.y; acc.z += v.z; acc.w += v.w;
      }
    }
    float4 zp = *reinterpret_cast<const float4*>(g_zp1 + (size_t)n * D + lane * 4);
    float4 hv = *reinterpret_cast<const float4*>(g_h1 + (size_t)n * D + lane * 4);
    float4 o;
    o.x = fmaxf(zp.x + acc.x, 0.f) - hv.x;
    o.y = fmaxf(zp.y + acc.y, 0.f) - hv.y;
    o.z = fmaxf(zp.z + acc.z, 0.f) - hv.z;
    o.w = fmaxf(zp.w + acc.w, 0.f) - hv.w;
    *reinterpret_cast<float4*>(dh1 + (size_t)n * D + lane * 4) = o;
  }
}

__global__ void __launch_bounds__(256) k_delta2() {
  int m = blockIdx.y;
  int cnt = g_cnt[4 + m];
  int w = (blockIdx.x * 256 + threadIdx.x) >> 5;
  int lane = threadIdx.x & 31;
  int nw = gridDim.x * 8;
  const unsigned char* f1 = g_f1 + m * N;
  const float* dA = g_dA + (size_t)m * N * D;
  float* dh2 = g_dh2 + (size_t)m * N * D;
  for (int i = w; i < cnt; i += nw) {
    int n = g_list2[m * N + i];
    float4 acc = make_float4(0.f, 0.f, 0.f, 0.f);
    if (f1[n]) acc = *reinterpret_cast<const float4*>(dA + (size_t)n * D + lane * 4);
    int beg = g_rowoff[n], end = g_rowoff[n + 1];
    for (int k = beg; k < end; ++k) {
      int s = g_csrsrc[k];
      if (f1[s]) {
        float4 v = *reinterpret_cast<const float4*>(dA + (size_t)s * D + lane * 4);
        acc.x += v.x; acc.y += v.y; acc.z += v.z; acc.w += v.w;
      }
    }
    float4 zp = *reinterpret_cast<const float4*>(g_zp2 + (size_t)n * D + lane * 4);
    float4 hv = *reinterpret_cast<const float4*>(g_h2 + (size_t)n * D + lane * 4);
    float4 o;
    o.x = fmaxf(zp.x + acc.x, 0.f) - hv.x;
    o.y = fmaxf(zp.y + acc.y, 0.f) - hv.y;
    o.z = fmaxf(zp.z + acc.z, 0.f) - hv.z;
    o.w = fmaxf(zp.w + acc.w, 0.f) - hv.w;
    *reinterpret_cast<float4*>(dh2 + (size_t)n * D + lane * 4) = o;
  }
}

__global__ void k_poolb() {
  int g = blockIdx.x;
  int tid = threadIdx.x;
  int d = tid & 127;
  int half = tid >> 7;
  int beg = g_gstart[g], end = g_gstart[g + 1];
  float acc = 0.f;
  for (int n = beg + half; n < end; n += 2) acc += g_hn[(size_t)n * D + d];
  __shared__ float s[128];
  if (half == 1) s[d] = acc;
  __syncthreads();
  if (half == 0) {
    float tot = acc + s[d];
    int c = end - beg;
    float v = tot / (float)max(c, 1);
    g_hg[(0 * NG + g) * D + d] = v;
    g_hg[(1 * NG + g) * D + d] = v;
  }
}

__global__ void k_pool_delta(const int* __restrict__ batch) {
  int m = blockIdx.y;
  int cnt = g_cnt[4 + m];
  int d = threadIdx.x;
  const float* dhn = g_dhn + (size_t)m * N * D;
  for (int i = blockIdx.x; i < cnt; i += gridDim.x) {
    int n = g_list2[m * N + i];
    int g = batch[n];
    int c = g_gstart[g + 1] - g_gstart[g];
    float inv = 1.0f / (float)max(c, 1);
    atomicAdd(&g_hg[(m * NG + g) * D + d], dhn[(size_t)n * D + d] * inv);
  }
}

__global__ void k_out(const float* __restrict__ Wp, const float* __restrict__ bp,
                      float* __restrict__ out) {
  int g = blockIdx.x;
  int t = threadIdx.x;
  if (t >= NT) return;
  float acc = 0.f;
  for (int m = 0; m < M; ++m) {
    const float* hg = &g_hg[(m * NG + g) * D];
    float s = 0.f;
#pragma unroll 16
    for (int k = 0; k < D; ++k) s += hg[k] * Wp[k * NT + t];
    acc += s;
  }
  out[g * NT + t] = acc * (1.0f / M) + bp[t];
}

// ---------------- launch ----------------
extern "C" void kernel_launch(void* const* d_in, const int* in_sizes, int n_in,
                              void* d_out, int out_size) {
  const int*   x_idx    = (const int*)d_in[0];
  const int*   edge_src = (const int*)d_in[1];
  const int*   edge_dst = (const int*)d_in[2];
  const int*   batch    = (const int*)d_in[3];
  const float* x_table  = (const float*)d_in[4];
  const float* anchor_t = (const float*)d_in[5];
  const float* Wg       = (const float*)d_in[6];
  const float* bg       = (const float*)d_in[7];
  const float* Wn       = (const float*)d_in[8];
  const float* bn       = (const float*)d_in[9];
  const float* Wd       = (const float*)d_in[10];
  const float* bd       = (const float*)d_in[11];
  const float* Wp       = (const float*)d_in[12];
  const float* bp       = (const float*)d_in[13];
  float* out = (float*)d_out;

  float *txp, *y1, *zp1, *h1, *y2, *zp2, *h2, *hn, *dA, *dh1, *dh2, *dhn;
  float *predp, *wmod;
  int *list1, *list2, *cnt, *anch;
  cudaGetSymbolAddress((void**)&txp, g_tx);
  cudaGetSymbolAddress((void**)&y1, g_y1);
  cudaGetSymbolAddress((void**)&zp1, g_zp1);
  cudaGetSymbolAddress((void**)&h1, g_h1);
  cudaGetSymbolAddress((void**)&y2, g_y2);
  cudaGetSymbolAddress((void**)&zp2, g_zp2);
  cudaGetSymbolAddress((void**)&h2, g_h2);
  cudaGetSymbolAddress((void**)&hn, g_hn);
  cudaGetSymbolAddress((void**)&dA, g_dA);
  cudaGetSymbolAddress((void**)&dh1, g_dh1);
  cudaGetSymbolAddress((void**)&dh2, g_dh2);
  cudaGetSymbolAddress((void**)&dhn, g_dhn);
  cudaGetSymbolAddress((void**)&predp, g_pred);
  cudaGetSymbolAddress((void**)&wmod, g_wmod);
  cudaGetSymbolAddress((void**)&list1, g_list1);
  cudaGetSymbolAddress((void**)&list2, g_list2);
  cudaGetSymbolAddress((void**)&cnt, g_cnt);
  cudaGetSymbolAddress((void**)&anch, g_anchor);

  static cudaStream_t s1 = nullptr;
  static cudaEvent_t evFork = nullptr, evY1 = nullptr, evH2 = nullptr;
  static cudaEvent_t evPool = nullptr, evC1 = nullptr, evC2 = nullptr;
  if (!s1) {
    cudaStreamCreateWithFlags(&s1, cudaStreamNonBlocking);
    cudaEventCreateWithFlags(&evFork, cudaEventDisableTiming);
    cudaEventCreateWithFlags(&evY1, cudaEventDisableTiming);
    cudaEventCreateWithFlags(&evH2, cudaEventDisableTiming);
    cudaEventCreateWithFlags(&evPool, cudaEventDisableTiming);
    cudaEventCreateWithFlags(&evC1, cudaEventDisableTiming);
    cudaEventCreateWithFlags(&evC2, cudaEventDisableTiming);
    cudaFuncSetAttribute(k_hmm, cudaFuncAttributeMaxDynamicSharedMemorySize,
                         WB_SMEM);
  }
  cudaStream_t s0 = 0;

  const int AGG_GRID = (N * 32 + 255) / 256;
  const int MMG = (N + 127) / 128;       // 391
  const dim3 MM2(MMG, 2);

  // ---- fork: s1 does embed + clears + weight prep + y1 GEMM; s0 builds CSR ----
  cudaEventRecord(evFork, s0);
  cudaStreamWaitEvent(s1, evFork, 0);
  k_embed<<<N, D, 0, s1>>>(x_idx, batch, x_table);
  k_mclear<<<(N + 255) / 256, 256, 0, s1>>>();
  k_wmod<<<D, D, 0, s1>>>(anchor_t, Wg);
  k_wsplit3<<<D, D, 0, s1>>>(Wg, 0);
  k_wsplit3<<<D, D, 0, s1>>>(Wg + D * D, 1);
  k_wsplit3<<<D, D, 0, s1>>>(Wn, 2);
  k_hmm<<<MMG, 256, WB_SMEM, s1>>>(N, txp, 0, nullptr, y1);
  cudaEventRecord(evY1, s1);

  k_zerodeg<<<(N + 255) / 256, 256, 0, s0>>>();
  k_hist<<<(E + 255) / 256, 256, 0, s0>>>(edge_dst);
  k_scan<<<1, 1024, 0, s0>>>();
  k_scatter<<<(E + 255) / 256, 256, 0, s0>>>(edge_src, edge_dst);
  cudaStreamWaitEvent(s0, evY1, 0);

  // ---- layer 1 + layer 2 (agg-after-GEMM) on s0 ----
  k_aggf<<<AGG_GRID, 256, 0, s0>>>(y1, zp1, h1, bg, nullptr, nullptr, nullptr);
  k_hmm<<<MMG, 256, WB_SMEM, s0>>>(N, h1, 1, nullptr, y2);
  k_aggf<<<AGG_GRID, 256, 0, s0>>>(y2, zp2, h2, bg + D, Wd, bd, predp);
  cudaEventRecord(evH2, s0);

  // ---- s1: base node MLP (bf16 mma, bias+relu) + base pool ----
  cudaStreamWaitEvent(s1, evH2, 0);
  k_hmm<<<MMG, 256, WB_SMEM, s1>>>(N, h2, 2, bn, hn);
  k_poolb<<<NG, 256, 0, s1>>>();
  cudaEventRecord(evPool, s1);

  // ---- s0: sampling + layer-1 deltas ----
  k_gstats<<<NG, 256, 0, s0>>>();
  k_sample<<<M * NG, 128, 0, s0>>>();
  k_mark_edges1<<<(E + 255) / 256, 256, 0, s0>>>(edge_src, edge_dst);
  k_compact1<<<(N + 255) / 256, 256, 0, s0>>>();
  cudaEventRecord(evC1, s0);
  k_mm<<<dim3(1, 2), 256, 0, s0>>>(NG, anch, NG, nullptr, 0, txp, nullptr, wmod,
                                   nullptr, nullptr, dA);
  k_delta1<<<dim3(64, 2), 256, 0, s0>>>();

  // ---- s1 (concurrent): layer-2 frontier discovery ----
  cudaStreamWaitEvent(s1, evC1, 0);
  k_mark_edges2<<<(E + 255) / 256, 256, 0, s1>>>(edge_src, edge_dst);
  k_compact2<<<(N + 255) / 256, 256, 0, s1>>>();
  cudaEventRecord(evC2, s1);

  // ---- s0: dy2 (list1 GEMM), layer-2 delta, node-MLP delta GEMM ----
  k_mm<<<MM2, 256, 0, s0>>>(0, list1, N, cnt, 0, nullptr, dh1, Wg + D * D,
                            nullptr, nullptr, dA);
  cudaStreamWaitEvent(s0, evC2, 0);
  k_delta2<<<dim3(256, 2), 256, 0, s0>>>();
  cudaStreamWaitEvent(s0, evPool, 0);
  k_mm<<<MM2, 256, 0, s0>>>(0, list2, N, cnt, 4, h2, dh2, Wn, bn, hn, dhn);
  k_pool_delta<<<dim3(256, 2), 128, 0, s0>>>(batch);
  k_out<<<NG, 32, 0, s0>>>(Wp, bp, out);
}